// round 1
// baseline (speedup 1.0000x reference)
#include <cuda_runtime.h>
#include <math.h>

#define NN 50000
#define NE 800000
#define ET (NE + NN)
#define C1 256      // layer1 total out channels (2 heads x 128)
#define CH 128
#define FCH 64
#define NEG_SLOPE 0.2f
#define EPS 1e-16f

// ---------------- scratch (device globals; allocation-free) ----------------
__device__ int   g_is64;
__device__ int   g_edge[2 * NE];        // [0,NE): src   [NE,2NE): dst
__device__ int   g_deg[NN];
__device__ int   g_rowstart[NN + 1];
__device__ int   g_cursor[NN];
__device__ int   g_srcs[ET];
__device__ float g_h1[(size_t)NN * C1];
__device__ float g_out1[(size_t)NN * C1];
__device__ float g_h2[(size_t)NN * CH];
__device__ float g_out2[(size_t)NN * CH];
__device__ float g_a1s[NN * 2], g_a1d[NN * 2];
__device__ float g_a2s[NN],     g_a2d[NN];

// ---------------- helpers ----------------
__device__ __forceinline__ float warpMax(float v) {
    #pragma unroll
    for (int o = 16; o; o >>= 1) v = fmaxf(v, __shfl_xor_sync(0xffffffffu, v, o));
    return v;
}
__device__ __forceinline__ float warpSum(float v) {
    #pragma unroll
    for (int o = 16; o; o >>= 1) v += __shfl_xor_sync(0xffffffffu, v, o);
    return v;
}
__device__ __forceinline__ float lrelu(float x) { return x > 0.f ? x : NEG_SLOPE * x; }
__device__ __forceinline__ float elu1(float x)  { return x > 0.f ? x : (__expf(x) - 1.0f); }

// ---------------- edge-index width detect + normalize ----------------
__global__ void k_detect(const int* __restrict__ raw) {
    if (threadIdx.x == 0) {
        int ok = 1;
        #pragma unroll
        for (int i = 0; i < 64; i++) ok &= (raw[2 * i + 1] == 0);
        g_is64 = ok;   // 1 => data is int64 (values < 50000 -> high word 0)
    }
}
__global__ void k_cvt(const int* __restrict__ raw) {
    int t = blockIdx.x * blockDim.x + threadIdx.x;
    if (t < 2 * NE) g_edge[t] = g_is64 ? raw[2 * t] : raw[t];
}

// ---------------- CSR build ----------------
__global__ void k_zero_deg() {
    int t = blockIdx.x * blockDim.x + threadIdx.x;
    if (t < NN) g_deg[t] = 0;
}
__global__ void k_count() {
    int t = blockIdx.x * blockDim.x + threadIdx.x;
    if (t < ET) {
        int d = (t < NE) ? g_edge[NE + t] : (t - NE);
        atomicAdd(&g_deg[d], 1);
    }
}
__global__ void k_scan() {   // single block, 1024 threads
    __shared__ int sh[1024];
    __shared__ int carry;
    int t = threadIdx.x;
    if (t == 0) { carry = 0; g_rowstart[0] = 0; }
    __syncthreads();
    for (int base = 0; base < NN; base += 1024) {
        int v = (base + t < NN) ? g_deg[base + t] : 0;
        sh[t] = v;
        __syncthreads();
        for (int off = 1; off < 1024; off <<= 1) {
            int x = (t >= off) ? sh[t - off] : 0;
            __syncthreads();
            sh[t] += x;
            __syncthreads();
        }
        int c = carry;
        if (base + t < NN) {
            g_rowstart[base + t + 1] = c + sh[t];
            g_cursor[base + t]       = c + sh[t] - v;
        }
        __syncthreads();
        if (t == 1023) carry = c + sh[1023];
        __syncthreads();
    }
}
__global__ void k_fill() {
    int t = blockIdx.x * blockDim.x + threadIdx.x;
    if (t < ET) {
        int s, d;
        if (t < NE) { s = g_edge[t]; d = g_edge[NE + t]; }
        else        { s = d = t - NE; }
        int p = atomicAdd(&g_cursor[d], 1);
        g_srcs[p] = s;
    }
}

// ---------------- SGEMM (64x64x16 tile, 256 thr, 4x4 microtile) ----------------
__device__ __forceinline__ void sgemm_body(const float* __restrict__ A,
                                           const float* __restrict__ B,
                                           float* __restrict__ C,
                                           int M, int Nc, int K) {
    __shared__ float As[16][64 + 4];
    __shared__ float Bs[16][64];
    int row0 = blockIdx.y * 64, col0 = blockIdx.x * 64;
    int tid = threadIdx.x;
    int tx = tid & 15, ty = tid >> 4;
    float acc[4][4] = {};
    for (int k0 = 0; k0 < K; k0 += 16) {
        #pragma unroll
        for (int i = tid; i < 64 * 16; i += 256) {
            int r = i >> 4, c = i & 15;
            As[c][r] = (row0 + r < M) ? A[(size_t)(row0 + r) * K + k0 + c] : 0.f;
        }
        #pragma unroll
        for (int i = tid; i < 16 * 64; i += 256) {
            int r = i >> 6, c = i & 63;
            Bs[r][c] = B[(size_t)(k0 + r) * Nc + col0 + c];
        }
        __syncthreads();
        #pragma unroll
        for (int kk = 0; kk < 16; kk++) {
            float4 a = *(const float4*)&As[kk][ty * 4];
            float4 b = *(const float4*)&Bs[kk][tx * 4];
            float av[4] = {a.x, a.y, a.z, a.w};
            float bv[4] = {b.x, b.y, b.z, b.w};
            #pragma unroll
            for (int i = 0; i < 4; i++)
                #pragma unroll
                for (int j = 0; j < 4; j++)
                    acc[i][j] += av[i] * bv[j];
        }
        __syncthreads();
    }
    #pragma unroll
    for (int i = 0; i < 4; i++) {
        int r = row0 + ty * 4 + i;
        if (r < M) {
            float4 v = {acc[i][0], acc[i][1], acc[i][2], acc[i][3]};
            *(float4*)&C[(size_t)r * Nc + col0 + tx * 4] = v;
        }
    }
}
__global__ void k_gemm1(const float* __restrict__ x, const float* __restrict__ W1) {
    sgemm_body(x, W1, g_h1, NN, C1, CH);
}
__global__ void k_gemm2(const float* __restrict__ W2) {
    sgemm_body(g_out1, W2, g_h2, NN, CH, C1);
}

// ---------------- attention coefficient dots ----------------
__global__ void k_att1(const float* __restrict__ as1, const float* __restrict__ ad1) {
    int w = (blockIdx.x * blockDim.x + threadIdx.x) >> 5;
    int lane = threadIdx.x & 31;
    if (w >= NN) return;
    const float4* h = (const float4*)(g_h1 + (size_t)w * C1);
    float4 v0 = h[lane], v1 = h[32 + lane];
    float4 s0 = ((const float4*)as1)[lane];
    float4 s1 = ((const float4*)as1)[32 + lane];
    float4 d0 = ((const float4*)ad1)[lane];
    float4 d1 = ((const float4*)ad1)[32 + lane];
    float rs0 = v0.x * s0.x + v0.y * s0.y + v0.z * s0.z + v0.w * s0.w;
    float rd0 = v0.x * d0.x + v0.y * d0.y + v0.z * d0.z + v0.w * d0.w;
    float rs1 = v1.x * s1.x + v1.y * s1.y + v1.z * s1.z + v1.w * s1.w;
    float rd1 = v1.x * d1.x + v1.y * d1.y + v1.z * d1.z + v1.w * d1.w;
    rs0 = warpSum(rs0); rd0 = warpSum(rd0);
    rs1 = warpSum(rs1); rd1 = warpSum(rd1);
    if (lane == 0) {
        g_a1s[2 * w] = rs0; g_a1s[2 * w + 1] = rs1;
        g_a1d[2 * w] = rd0; g_a1d[2 * w + 1] = rd1;
    }
}
__global__ void k_att2(const float* __restrict__ as2, const float* __restrict__ ad2) {
    int w = (blockIdx.x * blockDim.x + threadIdx.x) >> 5;
    int lane = threadIdx.x & 31;
    if (w >= NN) return;
    float4 v = ((const float4*)(g_h2 + (size_t)w * CH))[lane];
    float4 s = ((const float4*)as2)[lane];
    float4 d = ((const float4*)ad2)[lane];
    float rs = v.x * s.x + v.y * s.y + v.z * s.z + v.w * s.w;
    float rd = v.x * d.x + v.y * d.y + v.z * d.z + v.w * d.w;
    rs = warpSum(rs); rd = warpSum(rd);
    if (lane == 0) { g_a2s[w] = rs; g_a2d[w] = rd; }
}

// ---------------- node-centric GAT aggregation (atomic-free) ----------------
__global__ void k_agg1(const float* __restrict__ b1) {
    int w = (blockIdx.x * blockDim.x + threadIdx.x) >> 5;
    int lane = threadIdx.x & 31;
    if (w >= NN) return;
    int beg = g_rowstart[w], end = g_rowstart[w + 1];
    float ad0 = g_a1d[2 * w], ad1v = g_a1d[2 * w + 1];

    float m0 = -1e30f, m1 = -1e30f;
    for (int j = beg + lane; j < end; j += 32) {
        int s = g_srcs[j];
        m0 = fmaxf(m0, lrelu(g_a1s[2 * s] + ad0));
        m1 = fmaxf(m1, lrelu(g_a1s[2 * s + 1] + ad1v));
    }
    m0 = warpMax(m0); m1 = warpMax(m1);

    float z0 = 0.f, z1 = 0.f;
    for (int j = beg + lane; j < end; j += 32) {
        int s = g_srcs[j];
        z0 += __expf(lrelu(g_a1s[2 * s] + ad0) - m0);
        z1 += __expf(lrelu(g_a1s[2 * s + 1] + ad1v) - m1);
    }
    z0 = warpSum(z0); z1 = warpSum(z1);
    float i0 = 1.0f / (z0 + EPS), i1 = 1.0f / (z1 + EPS);

    float4 a0 = {0, 0, 0, 0}, a1 = {0, 0, 0, 0};
    for (int j = beg; j < end; j++) {
        int s = g_srcs[j];
        float w0 = __expf(lrelu(g_a1s[2 * s] + ad0) - m0) * i0;
        float w1 = __expf(lrelu(g_a1s[2 * s + 1] + ad1v) - m1) * i1;
        const float4* hv = (const float4*)(g_h1 + (size_t)s * C1);
        float4 v0 = hv[lane], v1 = hv[32 + lane];
        a0.x += v0.x * w0; a0.y += v0.y * w0; a0.z += v0.z * w0; a0.w += v0.w * w0;
        a1.x += v1.x * w1; a1.y += v1.y * w1; a1.z += v1.z * w1; a1.w += v1.w * w1;
    }
    float4 b0 = ((const float4*)b1)[lane];
    float4 bb = ((const float4*)b1)[32 + lane];
    float4 o0 = {elu1(a0.x + b0.x), elu1(a0.y + b0.y), elu1(a0.z + b0.z), elu1(a0.w + b0.w)};
    float4 o1 = {elu1(a1.x + bb.x), elu1(a1.y + bb.y), elu1(a1.z + bb.z), elu1(a1.w + bb.w)};
    float4* o = (float4*)(g_out1 + (size_t)w * C1);
    o[lane] = o0; o[32 + lane] = o1;
}

__global__ void k_agg2(const float* __restrict__ b2) {
    int w = (blockIdx.x * blockDim.x + threadIdx.x) >> 5;
    int lane = threadIdx.x & 31;
    if (w >= NN) return;
    int beg = g_rowstart[w], end = g_rowstart[w + 1];
    float ad = g_a2d[w];

    float m = -1e30f;
    for (int j = beg + lane; j < end; j += 32)
        m = fmaxf(m, lrelu(g_a2s[g_srcs[j]] + ad));
    m = warpMax(m);

    float z = 0.f;
    for (int j = beg + lane; j < end; j += 32)
        z += __expf(lrelu(g_a2s[g_srcs[j]] + ad) - m);
    z = warpSum(z);
    float iz = 1.0f / (z + EPS);

    float4 a = {0, 0, 0, 0};
    for (int j = beg; j < end; j++) {
        int s = g_srcs[j];
        float wt = __expf(lrelu(g_a2s[s] + ad) - m) * iz;
        float4 v = ((const float4*)(g_h2 + (size_t)s * CH))[lane];
        a.x += v.x * wt; a.y += v.y * wt; a.z += v.z * wt; a.w += v.w * wt;
    }
    float4 b = ((const float4*)b2)[lane];
    float4 o = {elu1(a.x + b.x), elu1(a.y + b.y), elu1(a.z + b.z), elu1(a.w + b.w)};
    ((float4*)(g_out2 + (size_t)w * CH))[lane] = o;
}

// ---------------- fused MLP head ----------------
__global__ void k_mlp(const float* __restrict__ fc1w, const float* __restrict__ fc1b,
                      const float* __restrict__ fc2w, const float* __restrict__ fc2b,
                      float* __restrict__ out) {
    __shared__ float w1s[CH * FCH];
    __shared__ float w2s[FCH], b1s[FCH];
    int tid = threadIdx.x;
    for (int i = tid; i < CH * FCH; i += blockDim.x) w1s[i] = fc1w[i];
    if (tid < FCH) { w2s[tid] = fc2w[tid]; b1s[tid] = fc1b[tid]; }
    __syncthreads();

    int w = (blockIdx.x * blockDim.x + tid) >> 5;
    int lane = tid & 31;
    if (w >= NN) return;
    float4 hv = ((const float4*)(g_out2 + (size_t)w * CH))[lane];
    float hvv[4] = {hv.x, hv.y, hv.z, hv.w};
    float acc0 = 0.f, acc1 = 0.f;
    #pragma unroll
    for (int k0 = 0; k0 < CH; k0 += 4) {
        int srcl = k0 >> 2;
        #pragma unroll
        for (int kk = 0; kk < 4; kk++) {
            float hk = __shfl_sync(0xffffffffu, hvv[kk], srcl);
            acc0 += hk * w1s[(k0 + kk) * FCH + lane];
            acc1 += hk * w1s[(k0 + kk) * FCH + lane + 32];
        }
    }
    float h0 = fmaxf(acc0 + b1s[lane], 0.f);
    float h1 = fmaxf(acc1 + b1s[lane + 32], 0.f);
    float p = h0 * w2s[lane] + h1 * w2s[lane + 32];
    p = warpSum(p);
    if (lane == 0) out[w] = p + fc2b[0];
}

// ---------------- launch ----------------
extern "C" void kernel_launch(void* const* d_in, const int* in_sizes, int n_in,
                              void* d_out, int out_size) {
    const float* x    = (const float*)d_in[0];
    const int*   eraw = (const int*)d_in[1];
    const float* W1   = (const float*)d_in[2];
    const float* as1  = (const float*)d_in[3];
    const float* ad1  = (const float*)d_in[4];
    const float* b1   = (const float*)d_in[5];
    const float* W2   = (const float*)d_in[6];
    const float* as2  = (const float*)d_in[7];
    const float* ad2  = (const float*)d_in[8];
    const float* b2   = (const float*)d_in[9];
    const float* fc1w = (const float*)d_in[10];
    const float* fc1b = (const float*)d_in[11];
    const float* fc2w = (const float*)d_in[12];
    const float* fc2b = (const float*)d_in[13];
    float* out = (float*)d_out;

    k_detect<<<1, 32>>>(eraw);
    k_cvt<<<(2 * NE + 255) / 256, 256>>>(eraw);
    k_zero_deg<<<(NN + 255) / 256, 256>>>();
    k_count<<<(ET + 255) / 256, 256>>>();
    k_scan<<<1, 1024>>>();
    k_fill<<<(ET + 255) / 256, 256>>>();

    k_gemm1<<<dim3(C1 / 64, (NN + 63) / 64), 256>>>(x, W1);
    k_att1<<<(NN + 7) / 8, 256>>>(as1, ad1);
    k_agg1<<<(NN + 7) / 8, 256>>>(b1);

    k_gemm2<<<dim3(CH / 64, (NN + 63) / 64), 256>>>(W2);
    k_att2<<<(NN + 7) / 8, 256>>>(as2, ad2);
    k_agg2<<<(NN + 7) / 8, 256>>>(b2);

    k_mlp<<<(NN + 7) / 8, 256>>>(fc1w, fc1b, fc2w, fc2b, out);
}

// round 3
// speedup vs baseline: 1.5930x; 1.5930x over previous
#include <cuda_runtime.h>
#include <cuda_bf16.h>
#include <mma.h>
#include <math.h>
#include <cstdint>

using namespace nvcuda;

#define NN 50000
#define NE 800000
#define ET (NE + NN)
#define C1 256
#define CH 128
#define FCH 64
#define NEG_SLOPE 0.2f
#define EPS 1e-16f

// ---------------- device scratch ----------------
__device__ int   g_is64;
__device__ int   g_deg[NN];
__device__ int   g_dinc[NN];
__device__ int   g_bsum[64];
__device__ int   g_boff[64];
__device__ int   g_rowstart[NN + 1];
__device__ int   g_cursor[NN];
__device__ int   g_srcs[ET];
__device__ float g_h1[(size_t)NN * C1];
__device__ float g_out1[(size_t)NN * C1];
__device__ float g_h2[(size_t)NN * CH];
__device__ float g_out2[(size_t)NN * CH];
__device__ float g_a1s[NN * 2], g_a1d[NN * 2];
__device__ float g_a2s[NN],     g_a2d[NN];

// ---------------- helpers ----------------
__device__ __forceinline__ float warpMax(float v) {
    #pragma unroll
    for (int o = 16; o; o >>= 1) v = fmaxf(v, __shfl_xor_sync(0xffffffffu, v, o));
    return v;
}
__device__ __forceinline__ float warpSum(float v) {
    #pragma unroll
    for (int o = 16; o; o >>= 1) v += __shfl_xor_sync(0xffffffffu, v, o);
    return v;
}
__device__ __forceinline__ float lrelu(float x) { return x > 0.f ? x : NEG_SLOPE * x; }
__device__ __forceinline__ float elu1(float x)  { return x > 0.f ? x : (__expf(x) - 1.0f); }

// ---------------- edge width detect ----------------
__global__ void k_detect(const int* __restrict__ raw) {
    if (threadIdx.x == 0) {
        int ok = 1;
        #pragma unroll
        for (int i = 0; i < 64; i++) ok &= (raw[2 * i + 1] == 0);
        g_is64 = ok;
    }
}

// ---------------- CSR build ----------------
__global__ void k_zero_deg() {
    int t = blockIdx.x * blockDim.x + threadIdx.x;
    if (t < NN) g_deg[t] = 0;
}
__global__ void k_count(const int* __restrict__ raw) {
    int t = blockIdx.x * blockDim.x + threadIdx.x;
    if (t < ET) {
        int d;
        if (t < NE) d = g_is64 ? raw[2 * (NE + t)] : raw[NE + t];
        else        d = t - NE;
        atomicAdd(&g_deg[d], 1);
    }
}
__global__ void k_scanA() {
    __shared__ int sh[1024];
    int t = threadIdx.x;
    int i = blockIdx.x * 1024 + t;
    int v = (i < NN) ? g_deg[i] : 0;
    sh[t] = v;
    __syncthreads();
    for (int off = 1; off < 1024; off <<= 1) {
        int x = (t >= off) ? sh[t - off] : 0;
        __syncthreads();
        sh[t] += x;
        __syncthreads();
    }
    if (i < NN) g_dinc[i] = sh[t];
    if (t == 1023) g_bsum[blockIdx.x] = sh[1023];
}
__global__ void k_scanB() {
    __shared__ int s[64];
    int t = threadIdx.x;
    int v = (t < 49) ? g_bsum[t] : 0;
    s[t] = v;
    __syncthreads();
    for (int off = 1; off < 64; off <<= 1) {
        int x = (t >= off) ? s[t - off] : 0;
        __syncthreads();
        s[t] += x;
        __syncthreads();
    }
    if (t < 49) g_boff[t] = s[t] - v;
}
__global__ void k_scanC() {
    int i = blockIdx.x * 1024 + threadIdx.x;
    if (i < NN) {
        int inc = g_dinc[i] + g_boff[blockIdx.x];
        g_rowstart[i + 1] = inc;
        g_cursor[i] = inc - g_deg[i];
    }
    if (i == 0) g_rowstart[0] = 0;
}
__global__ void k_fill(const int* __restrict__ raw) {
    int t = blockIdx.x * blockDim.x + threadIdx.x;
    if (t < ET) {
        int s, d;
        if (t < NE) {
            if (g_is64) { s = raw[2 * t]; d = raw[2 * (NE + t)]; }
            else        { s = raw[t];     d = raw[NE + t]; }
        } else { s = d = t - NE; }
        int p = atomicAdd(&g_cursor[d], 1);
        g_srcs[p] = s;
    }
}

// ---------------- WMMA bf16 3-term GEMM with fused attention-dot epilogue ----------------
// MODE 1: h1 = x @ W1   (K=128, N=256 as 2 head-tiles of 128)
// MODE 2: h2 = out1 @ W2 (K=256, N=128)
#define PA 136   // bf16 pitch (conflict-free, 16B-aligned rows)
#define PC 132   // fp32 pitch for C staging
#define OFF_AHI 0
#define OFF_ALO 34816
#define OFF_BHI 69632
#define OFF_BLO 104448
#define SMEM_TOT 139264

__device__ __forceinline__ void f2hl(float v, __nv_bfloat16& h, __nv_bfloat16& l) {
    h = __float2bfloat16_rn(v);
    l = __float2bfloat16_rn(v - __bfloat162float(h));
}

template <int MODE>
__global__ __launch_bounds__(256)
void k_gemm_wmma(const float* __restrict__ x, const float* __restrict__ W,
                 const float* __restrict__ attS, const float* __restrict__ attD) {
    extern __shared__ char dyn[];
    __shared__ float s_as[128], s_ad[128];

    constexpr int K      = (MODE == 1) ? 128 : 256;
    constexpr int NCHUNK = K / 128;
    constexpr int NCOLS  = (MODE == 1) ? 256 : 128;   // B width
    constexpr int Hstr   = (MODE == 1) ? C1 : CH;
    constexpr int aStr   = (MODE == 1) ? 2 : 1;
    const float* A  = (MODE == 1) ? x : g_out1;
    float* Hout     = (MODE == 1) ? g_h1 : g_h2;
    float* outS     = (MODE == 1) ? g_a1s : g_a2s;
    float* outD     = (MODE == 1) ? g_a1d : g_a2d;

    const int tid = threadIdx.x, wid = tid >> 5, lane = tid & 31;
    const int head = blockIdx.x;
    const int row0 = blockIdx.y * 128;
    const int warp_m = wid >> 1, warp_n = wid & 1;

    __nv_bfloat16* AHI = (__nv_bfloat16*)(dyn + OFF_AHI);
    __nv_bfloat16* ALO = (__nv_bfloat16*)(dyn + OFF_ALO);
    __nv_bfloat16* BHI = (__nv_bfloat16*)(dyn + OFF_BHI);
    __nv_bfloat16* BLO = (__nv_bfloat16*)(dyn + OFF_BLO);

    if (tid < 128) {
        s_as[tid] = attS[head * 128 + tid];
        s_ad[tid] = attD[head * 128 + tid];
    }

    wmma::fragment<wmma::accumulator, 16, 16, 16, float> acc[2][4];
    #pragma unroll
    for (int i = 0; i < 2; i++)
        #pragma unroll
        for (int j = 0; j < 4; j++) wmma::fill_fragment(acc[i][j], 0.f);

    const int lr = tid >> 1, lh = tid & 1;      // loader: row / 64-col half
    const bool rok = (row0 + lr) < NN;

    #pragma unroll
    for (int c = 0; c < NCHUNK; c++) {
        if (c) __syncthreads();
        // --- stage A (fp32 -> bf16 hi/lo) ---
        {
            const float* src = A + (size_t)(row0 + lr) * K + c * 128 + lh * 64;
            __nv_bfloat16* ah = AHI + lr * PA + lh * 64;
            __nv_bfloat16* al = ALO + lr * PA + lh * 64;
            #pragma unroll
            for (int i = 0; i < 16; i++) {
                float4 v = rok ? ((const float4*)src)[i] : make_float4(0, 0, 0, 0);
                __nv_bfloat16 h0, l0, h1, l1, h2, l2, h3, l3;
                f2hl(v.x, h0, l0); f2hl(v.y, h1, l1);
                f2hl(v.z, h2, l2); f2hl(v.w, h3, l3);
                ((__nv_bfloat162*)(ah + i * 4))[0] = __nv_bfloat162(h0, h1);
                ((__nv_bfloat162*)(ah + i * 4))[1] = __nv_bfloat162(h2, h3);
                ((__nv_bfloat162*)(al + i * 4))[0] = __nv_bfloat162(l0, l1);
                ((__nv_bfloat162*)(al + i * 4))[1] = __nv_bfloat162(l2, l3);
            }
        }
        // --- stage B (W fp32 -> bf16 hi/lo); row k = c*128 + lr ---
        {
            const float* src = W + (size_t)(c * 128 + lr) * NCOLS + head * 128 + lh * 64;
            __nv_bfloat16* bh = BHI + lr * PA + lh * 64;
            __nv_bfloat16* bl = BLO + lr * PA + lh * 64;
            #pragma unroll
            for (int i = 0; i < 16; i++) {
                float4 v = ((const float4*)src)[i];
                __nv_bfloat16 h0, l0, h1, l1, h2, l2, h3, l3;
                f2hl(v.x, h0, l0); f2hl(v.y, h1, l1);
                f2hl(v.z, h2, l2); f2hl(v.w, h3, l3);
                ((__nv_bfloat162*)(bh + i * 4))[0] = __nv_bfloat162(h0, h1);
                ((__nv_bfloat162*)(bh + i * 4))[1] = __nv_bfloat162(h2, h3);
                ((__nv_bfloat162*)(bl + i * 4))[0] = __nv_bfloat162(l0, l1);
                ((__nv_bfloat162*)(bl + i * 4))[1] = __nv_bfloat162(l2, l3);
            }
        }
        __syncthreads();

        // --- MMA: 3-term hi/lo ---
        #pragma unroll
        for (int kk = 0; kk < 8; kk++) {
            wmma::fragment<wmma::matrix_a, 16, 16, 16, __nv_bfloat16, wmma::row_major> ah[2], al[2];
            wmma::fragment<wmma::matrix_b, 16, 16, 16, __nv_bfloat16, wmma::row_major> bh[4], bl[4];
            #pragma unroll
            for (int i = 0; i < 2; i++) {
                wmma::load_matrix_sync(ah[i], AHI + (warp_m * 32 + i * 16) * PA + kk * 16, PA);
                wmma::load_matrix_sync(al[i], ALO + (warp_m * 32 + i * 16) * PA + kk * 16, PA);
            }
            #pragma unroll
            for (int j = 0; j < 4; j++) {
                wmma::load_matrix_sync(bh[j], BHI + (kk * 16) * PA + warp_n * 64 + j * 16, PA);
                wmma::load_matrix_sync(bl[j], BLO + (kk * 16) * PA + warp_n * 64 + j * 16, PA);
            }
            #pragma unroll
            for (int i = 0; i < 2; i++)
                #pragma unroll
                for (int j = 0; j < 4; j++) {
                    wmma::mma_sync(acc[i][j], ah[i], bh[j], acc[i][j]);
                    wmma::mma_sync(acc[i][j], ah[i], bl[j], acc[i][j]);
                    wmma::mma_sync(acc[i][j], al[i], bh[j], acc[i][j]);
                }
        }
    }

    // --- epilogue: stage C in SMEM, write h + fused attention dots ---
    __syncthreads();
    float* Cs = (float*)dyn;
    #pragma unroll
    for (int i = 0; i < 2; i++)
        #pragma unroll
        for (int j = 0; j < 4; j++)
            wmma::store_matrix_sync(Cs + (warp_m * 32 + i * 16) * PC + warp_n * 64 + j * 16,
                                    acc[i][j], PC, wmma::mem_row_major);
    __syncthreads();

    #pragma unroll 4
    for (int rr = 0; rr < 16; rr++) {
        int row = wid * 16 + rr;
        int r = row0 + row;
        float4 v = *(float4*)&Cs[row * PC + lane * 4];
        float sacc = v.x * s_as[lane * 4]     + v.y * s_as[lane * 4 + 1]
                   + v.z * s_as[lane * 4 + 2] + v.w * s_as[lane * 4 + 3];
        float dacc = v.x * s_ad[lane * 4]     + v.y * s_ad[lane * 4 + 1]
                   + v.z * s_ad[lane * 4 + 2] + v.w * s_ad[lane * 4 + 3];
        sacc = warpSum(sacc); dacc = warpSum(dacc);
        if (r < NN) {
            *(float4*)(Hout + (size_t)r * Hstr + head * 128 + lane * 4) = v;
            if (lane == 0) {
                outS[(size_t)r * aStr + head] = sacc;
                outD[(size_t)r * aStr + head] = dacc;
            }
        }
    }
}

// ---------------- node-centric GAT aggregation ----------------
__global__ void k_agg1(const float* __restrict__ b1) {
    int w = (blockIdx.x * blockDim.x + threadIdx.x) >> 5;
    int lane = threadIdx.x & 31;
    if (w >= NN) return;
    int beg = g_rowstart[w], end = g_rowstart[w + 1];
    float ad0 = g_a1d[2 * w], ad1v = g_a1d[2 * w + 1];

    float m0 = -1e30f, m1 = -1e30f;
    for (int j = beg + lane; j < end; j += 32) {
        int s = g_srcs[j];
        m0 = fmaxf(m0, lrelu(g_a1s[2 * s] + ad0));
        m1 = fmaxf(m1, lrelu(g_a1s[2 * s + 1] + ad1v));
    }
    m0 = warpMax(m0); m1 = warpMax(m1);

    float z0 = 0.f, z1 = 0.f;
    for (int j = beg + lane; j < end; j += 32) {
        int s = g_srcs[j];
        z0 += __expf(lrelu(g_a1s[2 * s] + ad0) - m0);
        z1 += __expf(lrelu(g_a1s[2 * s + 1] + ad1v) - m1);
    }
    z0 = warpSum(z0); z1 = warpSum(z1);
    float i0 = 1.0f / (z0 + EPS), i1 = 1.0f / (z1 + EPS);

    float4 a0 = {0, 0, 0, 0}, a1 = {0, 0, 0, 0};
    #pragma unroll 2
    for (int j = beg; j < end; j++) {
        int s = g_srcs[j];
        float w0 = __expf(lrelu(g_a1s[2 * s] + ad0) - m0) * i0;
        float w1 = __expf(lrelu(g_a1s[2 * s + 1] + ad1v) - m1) * i1;
        const float4* hv = (const float4*)(g_h1 + (size_t)s * C1);
        float4 v0 = hv[lane], v1 = hv[32 + lane];
        a0.x += v0.x * w0; a0.y += v0.y * w0; a0.z += v0.z * w0; a0.w += v0.w * w0;
        a1.x += v1.x * w1; a1.y += v1.y * w1; a1.z += v1.z * w1; a1.w += v1.w * w1;
    }
    float4 b0 = ((const float4*)b1)[lane];
    float4 bb = ((const float4*)b1)[32 + lane];
    float4 o0 = {elu1(a0.x + b0.x), elu1(a0.y + b0.y), elu1(a0.z + b0.z), elu1(a0.w + b0.w)};
    float4 o1 = {elu1(a1.x + bb.x), elu1(a1.y + bb.y), elu1(a1.z + bb.z), elu1(a1.w + bb.w)};
    float4* o = (float4*)(g_out1 + (size_t)w * C1);
    o[lane] = o0; o[32 + lane] = o1;
}

__global__ void k_agg2(const float* __restrict__ b2) {
    int w = (blockIdx.x * blockDim.x + threadIdx.x) >> 5;
    int lane = threadIdx.x & 31;
    if (w >= NN) return;
    int beg = g_rowstart[w], end = g_rowstart[w + 1];
    float ad = g_a2d[w];

    float m = -1e30f;
    for (int j = beg + lane; j < end; j += 32)
        m = fmaxf(m, lrelu(g_a2s[g_srcs[j]] + ad));
    m = warpMax(m);

    float z = 0.f;
    for (int j = beg + lane; j < end; j += 32)
        z += __expf(lrelu(g_a2s[g_srcs[j]] + ad) - m);
    z = warpSum(z);
    float iz = 1.0f / (z + EPS);

    float4 a = {0, 0, 0, 0};
    #pragma unroll 2
    for (int j = beg; j < end; j++) {
        int s = g_srcs[j];
        float wt = __expf(lrelu(g_a2s[s] + ad) - m) * iz;
        float4 v = ((const float4*)(g_h2 + (size_t)s * CH))[lane];
        a.x += v.x * wt; a.y += v.y * wt; a.z += v.z * wt; a.w += v.w * wt;
    }
    float4 b = ((const float4*)b2)[lane];
    float4 o = {elu1(a.x + b.x), elu1(a.y + b.y), elu1(a.z + b.z), elu1(a.w + b.w)};
    ((float4*)(g_out2 + (size_t)w * CH))[lane] = o;
}

// ---------------- fused MLP head ----------------
__global__ void k_mlp(const float* __restrict__ fc1w, const float* __restrict__ fc1b,
                      const float* __restrict__ fc2w, const float* __restrict__ fc2b,
                      float* __restrict__ out) {
    __shared__ float w1s[CH * FCH];
    __shared__ float w2s[FCH], b1s[FCH];
    int tid = threadIdx.x;
    for (int i = tid; i < CH * FCH; i += blockDim.x) w1s[i] = fc1w[i];
    if (tid < FCH) { w2s[tid] = fc2w[tid]; b1s[tid] = fc1b[tid]; }
    __syncthreads();

    int w = (blockIdx.x * blockDim.x + tid) >> 5;
    int lane = tid & 31;
    if (w >= NN) return;
    float4 hv = ((const float4*)(g_out2 + (size_t)w * CH))[lane];
    float hvv[4] = {hv.x, hv.y, hv.z, hv.w};
    float acc0 = 0.f, acc1 = 0.f;
    #pragma unroll
    for (int k0 = 0; k0 < CH; k0 += 4) {
        int srcl = k0 >> 2;
        #pragma unroll
        for (int kk = 0; kk < 4; kk++) {
            float hk = __shfl_sync(0xffffffffu, hvv[kk], srcl);
            acc0 += hk * w1s[(k0 + kk) * FCH + lane];
            acc1 += hk * w1s[(k0 + kk) * FCH + lane + 32];
        }
    }
    float h0 = fmaxf(acc0 + b1s[lane], 0.f);
    float h1 = fmaxf(acc1 + b1s[lane + 32], 0.f);
    float p = h0 * w2s[lane] + h1 * w2s[lane + 32];
    p = warpSum(p);
    if (lane == 0) out[w] = p + fc2b[0];
}

// ---------------- launch ----------------
extern "C" void kernel_launch(void* const* d_in, const int* in_sizes, int n_in,
                              void* d_out, int out_size) {
    const float* x    = (const float*)d_in[0];
    const int*   eraw = (const int*)d_in[1];
    const float* W1   = (const float*)d_in[2];
    const float* as1  = (const float*)d_in[3];
    const float* ad1  = (const float*)d_in[4];
    const float* b1   = (const float*)d_in[5];
    const float* W2   = (const float*)d_in[6];
    const float* as2  = (const float*)d_in[7];
    const float* ad2  = (const float*)d_in[8];
    const float* b2   = (const float*)d_in[9];
    const float* fc1w = (const float*)d_in[10];
    const float* fc1b = (const float*)d_in[11];
    const float* fc2w = (const float*)d_in[12];
    const float* fc2b = (const float*)d_in[13];
    float* out = (float*)d_out;

    static int attr_done = 0;
    cudaFuncSetAttribute(k_gemm_wmma<1>, cudaFuncAttributeMaxDynamicSharedMemorySize, SMEM_TOT);
    cudaFuncSetAttribute(k_gemm_wmma<2>, cudaFuncAttributeMaxDynamicSharedMemorySize, SMEM_TOT);
    (void)attr_done;

    k_detect<<<1, 32>>>(eraw);
    k_zero_deg<<<(NN + 255) / 256, 256>>>();
    k_count<<<(ET + 255) / 256, 256>>>(eraw);
    k_scanA<<<49, 1024>>>();
    k_scanB<<<1, 64>>>();
    k_scanC<<<49, 1024>>>();
    k_fill<<<(ET + 255) / 256, 256>>>(eraw);

    k_gemm_wmma<1><<<dim3(2, 391), 256, SMEM_TOT>>>(x, W1, as1, ad1);
    k_agg1<<<(NN + 7) / 8, 256>>>(b1);

    k_gemm_wmma<2><<<dim3(1, 391), 256, SMEM_TOT>>>(x, W2, as2, ad2);
    k_agg2<<<(NN + 7) / 8, 256>>>(b2);

    k_mlp<<<(NN + 7) / 8, 256>>>(fc1w, fc1b, fc2w, fc2b, out);
}

// round 5
// speedup vs baseline: 1.6444x; 1.0322x over previous
#include <cuda_runtime.h>
#include <cuda_bf16.h>
#include <cuda_fp16.h>
#include <mma.h>
#include <math.h>
#include <cstdint>

using namespace nvcuda;

#define NN 50000
#define NE 800000
#define ET (NE + NN)
#define C1 256
#define CH 128
#define FCH 64
#define NEG_SLOPE 0.2f
#define EPS 1e-16f

// ---------------- device scratch ----------------
__device__ int   g_is64;
__device__ int   g_deg[NN];
__device__ int   g_dinc[NN];
__device__ int   g_bsum[64];
__device__ int   g_boff[64];
__device__ int   g_rowstart[NN + 1];
__device__ int   g_cursor[NN];
__device__ int   g_srcs[ET];
__device__ __half g_h1h[(size_t)NN * C1];   // fp16 h1 (gather-only)
__device__ __half g_h2h[(size_t)NN * CH];   // fp16 h2 (gather-only)
__device__ float g_out1[(size_t)NN * C1];
__device__ float g_out2[(size_t)NN * CH];
__device__ float g_a1s[NN * 2], g_a1d[NN * 2];
__device__ float g_a2s[NN],     g_a2d[NN];

// ---------------- helpers ----------------
__device__ __forceinline__ float warpMax(float v) {
    #pragma unroll
    for (int o = 16; o; o >>= 1) v = fmaxf(v, __shfl_xor_sync(0xffffffffu, v, o));
    return v;
}
__device__ __forceinline__ float warpSum(float v) {
    #pragma unroll
    for (int o = 16; o; o >>= 1) v += __shfl_xor_sync(0xffffffffu, v, o);
    return v;
}
__device__ __forceinline__ float lrelu(float x) { return x > 0.f ? x : NEG_SLOPE * x; }
__device__ __forceinline__ float elu1(float x)  { return x > 0.f ? x : (__expf(x) - 1.0f); }

// ---------------- edge width detect ----------------
__global__ void k_detect(const int* __restrict__ raw) {
    if (threadIdx.x == 0) {
        int ok = 1;
        #pragma unroll
        for (int i = 0; i < 64; i++) ok &= (raw[2 * i + 1] == 0);
        g_is64 = ok;
    }
}

// ---------------- CSR build ----------------
__global__ void k_zero_deg() {
    int t = blockIdx.x * blockDim.x + threadIdx.x;
    if (t < NN) g_deg[t] = 0;
}
__global__ void k_count(const int* __restrict__ raw) {
    int t = blockIdx.x * blockDim.x + threadIdx.x;
    if (t < ET) {
        int d;
        if (t < NE) d = g_is64 ? raw[2 * (NE + t)] : raw[NE + t];
        else        d = t - NE;
        atomicAdd(&g_deg[d], 1);
    }
}
__global__ void k_scanA() {
    __shared__ int sh[1024];
    int t = threadIdx.x;
    int i = blockIdx.x * 1024 + t;
    int v = (i < NN) ? g_deg[i] : 0;
    sh[t] = v;
    __syncthreads();
    for (int off = 1; off < 1024; off <<= 1) {
        int x = (t >= off) ? sh[t - off] : 0;
        __syncthreads();
        sh[t] += x;
        __syncthreads();
    }
    if (i < NN) g_dinc[i] = sh[t];
    if (t == 1023) g_bsum[blockIdx.x] = sh[1023];
}
__global__ void k_scanB() {
    __shared__ int s[64];
    int t = threadIdx.x;
    int v = (t < 49) ? g_bsum[t] : 0;
    s[t] = v;
    __syncthreads();
    for (int off = 1; off < 64; off <<= 1) {
        int x = (t >= off) ? s[t - off] : 0;
        __syncthreads();
        s[t] += x;
        __syncthreads();
    }
    if (t < 49) g_boff[t] = s[t] - v;
}
__global__ void k_scanC() {
    int i = blockIdx.x * 1024 + threadIdx.x;
    if (i < NN) {
        int inc = g_dinc[i] + g_boff[blockIdx.x];
        g_rowstart[i + 1] = inc;
        g_cursor[i] = inc - g_deg[i];
    }
    if (i == 0) g_rowstart[0] = 0;
}
__global__ void k_fill(const int* __restrict__ raw) {
    int t = blockIdx.x * blockDim.x + threadIdx.x;
    if (t < ET) {
        int s, d;
        if (t < NE) {
            if (g_is64) { s = raw[2 * t]; d = raw[2 * (NE + t)]; }
            else        { s = raw[t];     d = raw[NE + t]; }
        } else { s = d = t - NE; }
        int p = atomicAdd(&g_cursor[d], 1);
        g_srcs[p] = s;
    }
}

// ---------------- WMMA bf16 3-term GEMM with fused attention-dot epilogue ----------------
// MODE 1: h1 = x @ W1   (K=128, N=256 as 2 head-tiles of 128)
// MODE 2: h2 = out1 @ W2 (K=256, N=128)
#define PA 136   // bf16 pitch (conflict-free, 16B-aligned rows)
#define PC 132   // fp32 pitch for C staging
#define OFF_AHI 0
#define OFF_ALO 34816
#define OFF_BHI 69632
#define OFF_BLO 104448
#define SMEM_TOT 139264

__device__ __forceinline__ void f2hl(float v, __nv_bfloat16& h, __nv_bfloat16& l) {
    h = __float2bfloat16_rn(v);
    l = __float2bfloat16_rn(v - __bfloat162float(h));
}

template <int MODE>
__global__ __launch_bounds__(256)
void k_gemm_wmma(const float* __restrict__ x, const float* __restrict__ W,
                 const float* __restrict__ attS, const float* __restrict__ attD) {
    extern __shared__ char dyn[];
    __shared__ float s_as[128], s_ad[128];

    constexpr int K      = (MODE == 1) ? 128 : 256;
    constexpr int NCHUNK = K / 128;
    constexpr int NCOLS  = (MODE == 1) ? 256 : 128;   // B width
    constexpr int Hstr   = (MODE == 1) ? C1 : CH;
    constexpr int aStr   = (MODE == 1) ? 2 : 1;
    const float* A  = (MODE == 1) ? x : g_out1;
    __half* Hout    = (MODE == 1) ? g_h1h : g_h2h;
    float* outS     = (MODE == 1) ? g_a1s : g_a2s;
    float* outD     = (MODE == 1) ? g_a1d : g_a2d;

    const int tid = threadIdx.x, wid = tid >> 5, lane = tid & 31;
    const int head = blockIdx.x;
    const int row0 = blockIdx.y * 128;
    const int warp_m = wid >> 1, warp_n = wid & 1;

    __nv_bfloat16* AHI = (__nv_bfloat16*)(dyn + OFF_AHI);
    __nv_bfloat16* ALO = (__nv_bfloat16*)(dyn + OFF_ALO);
    __nv_bfloat16* BHI = (__nv_bfloat16*)(dyn + OFF_BHI);
    __nv_bfloat16* BLO = (__nv_bfloat16*)(dyn + OFF_BLO);

    if (tid < 128) {
        s_as[tid] = attS[head * 128 + tid];
        s_ad[tid] = attD[head * 128 + tid];
    }

    wmma::fragment<wmma::accumulator, 16, 16, 16, float> acc[2][4];
    #pragma unroll
    for (int i = 0; i < 2; i++)
        #pragma unroll
        for (int j = 0; j < 4; j++) wmma::fill_fragment(acc[i][j], 0.f);

    const int lr = tid >> 1, lh = tid & 1;      // loader: row / 64-col half
    const bool rok = (row0 + lr) < NN;

    #pragma unroll
    for (int c = 0; c < NCHUNK; c++) {
        if (c) __syncthreads();
        // --- stage A (fp32 -> bf16 hi/lo) ---
        {
            const float* src = A + (size_t)(row0 + lr) * K + c * 128 + lh * 64;
            __nv_bfloat16* ah = AHI + lr * PA + lh * 64;
            __nv_bfloat16* al = ALO + lr * PA + lh * 64;
            #pragma unroll
            for (int i = 0; i < 16; i++) {
                float4 v = rok ? ((const float4*)src)[i] : make_float4(0, 0, 0, 0);
                __nv_bfloat16 h0, l0, h1, l1, h2, l2, h3, l3;
                f2hl(v.x, h0, l0); f2hl(v.y, h1, l1);
                f2hl(v.z, h2, l2); f2hl(v.w, h3, l3);
                ((__nv_bfloat162*)(ah + i * 4))[0] = __nv_bfloat162(h0, h1);
                ((__nv_bfloat162*)(ah + i * 4))[1] = __nv_bfloat162(h2, h3);
                ((__nv_bfloat162*)(al + i * 4))[0] = __nv_bfloat162(l0, l1);
                ((__nv_bfloat162*)(al + i * 4))[1] = __nv_bfloat162(l2, l3);
            }
        }
        // --- stage B (W fp32 -> bf16 hi/lo); row k = c*128 + lr ---
        {
            const float* src = W + (size_t)(c * 128 + lr) * NCOLS + head * 128 + lh * 64;
            __nv_bfloat16* bh = BHI + lr * PA + lh * 64;
            __nv_bfloat16* bl = BLO + lr * PA + lh * 64;
            #pragma unroll
            for (int i = 0; i < 16; i++) {
                float4 v = ((const float4*)src)[i];
                __nv_bfloat16 h0, l0, h1, l1, h2, l2, h3, l3;
                f2hl(v.x, h0, l0); f2hl(v.y, h1, l1);
                f2hl(v.z, h2, l2); f2hl(v.w, h3, l3);
                ((__nv_bfloat162*)(bh + i * 4))[0] = __nv_bfloat162(h0, h1);
                ((__nv_bfloat162*)(bh + i * 4))[1] = __nv_bfloat162(h2, h3);
                ((__nv_bfloat162*)(bl + i * 4))[0] = __nv_bfloat162(l0, l1);
                ((__nv_bfloat162*)(bl + i * 4))[1] = __nv_bfloat162(l2, l3);
            }
        }
        __syncthreads();

        // --- MMA: 3-term hi/lo ---
        #pragma unroll
        for (int kk = 0; kk < 8; kk++) {
            wmma::fragment<wmma::matrix_a, 16, 16, 16, __nv_bfloat16, wmma::row_major> ah[2], al[2];
            wmma::fragment<wmma::matrix_b, 16, 16, 16, __nv_bfloat16, wmma::row_major> bh[4], bl[4];
            #pragma unroll
            for (int i = 0; i < 2; i++) {
                wmma::load_matrix_sync(ah[i], AHI + (warp_m * 32 + i * 16) * PA + kk * 16, PA);
                wmma::load_matrix_sync(al[i], ALO + (warp_m * 32 + i * 16) * PA + kk * 16, PA);
            }
            #pragma unroll
            for (int j = 0; j < 4; j++) {
                wmma::load_matrix_sync(bh[j], BHI + (kk * 16) * PA + warp_n * 64 + j * 16, PA);
                wmma::load_matrix_sync(bl[j], BLO + (kk * 16) * PA + warp_n * 64 + j * 16, PA);
            }
            #pragma unroll
            for (int i = 0; i < 2; i++)
                #pragma unroll
                for (int j = 0; j < 4; j++) {
                    wmma::mma_sync(acc[i][j], ah[i], bh[j], acc[i][j]);
                    wmma::mma_sync(acc[i][j], ah[i], bl[j], acc[i][j]);
                    wmma::mma_sync(acc[i][j], al[i], bh[j], acc[i][j]);
                }
        }
    }

    // --- epilogue: stage C in SMEM, write fp16 h + fused attention dots ---
    __syncthreads();
    float* Cs = (float*)dyn;
    #pragma unroll
    for (int i = 0; i < 2; i++)
        #pragma unroll
        for (int j = 0; j < 4; j++)
            wmma::store_matrix_sync(Cs + (warp_m * 32 + i * 16) * PC + warp_n * 64 + j * 16,
                                    acc[i][j], PC, wmma::mem_row_major);
    __syncthreads();

    #pragma unroll 4
    for (int rr = 0; rr < 16; rr++) {
        int row = wid * 16 + rr;
        int r = row0 + row;
        float4 v = *(float4*)&Cs[row * PC + lane * 4];
        float sacc = v.x * s_as[lane * 4]     + v.y * s_as[lane * 4 + 1]
                   + v.z * s_as[lane * 4 + 2] + v.w * s_as[lane * 4 + 3];
        float dacc = v.x * s_ad[lane * 4]     + v.y * s_ad[lane * 4 + 1]
                   + v.z * s_ad[lane * 4 + 2] + v.w * s_ad[lane * 4 + 3];
        sacc = warpSum(sacc); dacc = warpSum(dacc);
        if (r < NN) {
            __half2 p0 = __floats2half2_rn(v.x, v.y);
            __half2 p1 = __floats2half2_rn(v.z, v.w);
            uint2 pk = make_uint2(*(uint32_t*)&p0, *(uint32_t*)&p1);
            *(uint2*)(Hout + (size_t)r * Hstr + head * 128 + lane * 4) = pk;
            if (lane == 0) {
                outS[(size_t)r * aStr + head] = sacc;
                outD[(size_t)r * aStr + head] = dacc;
            }
        }
    }
}

// ---------------- node-centric GAT aggregation (fp16 gather, fp32 accum) ----------------
__global__ void k_agg1(const float* __restrict__ b1) {
    int w = (blockIdx.x * blockDim.x + threadIdx.x) >> 5;
    int lane = threadIdx.x & 31;
    if (w >= NN) return;
    int beg = g_rowstart[w], end = g_rowstart[w + 1];
    float ad0 = g_a1d[2 * w], ad1v = g_a1d[2 * w + 1];

    float m0 = -1e30f, m1 = -1e30f;
    for (int j = beg + lane; j < end; j += 32) {
        int s = g_srcs[j];
        m0 = fmaxf(m0, lrelu(g_a1s[2 * s] + ad0));
        m1 = fmaxf(m1, lrelu(g_a1s[2 * s + 1] + ad1v));
    }
    m0 = warpMax(m0); m1 = warpMax(m1);

    float z0 = 0.f, z1 = 0.f;
    for (int j = beg + lane; j < end; j += 32) {
        int s = g_srcs[j];
        z0 += __expf(lrelu(g_a1s[2 * s] + ad0) - m0);
        z1 += __expf(lrelu(g_a1s[2 * s + 1] + ad1v) - m1);
    }
    z0 = warpSum(z0); z1 = warpSum(z1);

    // lanes 0-15 -> head 0 channels [8l,8l+8); lanes 16-31 -> head 1
    const int hd = lane >> 4;
    const float m  = hd ? m1 : m0;
    const float iz = hd ? (1.0f / (z1 + EPS)) : (1.0f / (z0 + EPS));
    const float ad = hd ? ad1v : ad0;

    float acc[8] = {0, 0, 0, 0, 0, 0, 0, 0};
    #pragma unroll 2
    for (int j = beg; j < end; j++) {
        int s = g_srcs[j];
        float wt = __expf(lrelu(g_a1s[2 * s + hd] + ad) - m) * iz;
        uint4 pk = *(const uint4*)(g_h1h + (size_t)s * C1 + lane * 8);
        const uint32_t u[4] = {pk.x, pk.y, pk.z, pk.w};
        #pragma unroll
        for (int q = 0; q < 4; q++) {
            float2 f = __half22float2(*(const __half2*)&u[q]);
            acc[2 * q]     += wt * f.x;
            acc[2 * q + 1] += wt * f.y;
        }
    }
    float* o = g_out1 + (size_t)w * C1 + lane * 8;
    const float* bb = b1 + lane * 8;
    float4 o0 = {elu1(acc[0] + bb[0]), elu1(acc[1] + bb[1]),
                 elu1(acc[2] + bb[2]), elu1(acc[3] + bb[3])};
    float4 o1 = {elu1(acc[4] + bb[4]), elu1(acc[5] + bb[5]),
                 elu1(acc[6] + bb[6]), elu1(acc[7] + bb[7])};
    ((float4*)o)[0] = o0; ((float4*)o)[1] = o1;
}

__global__ void k_agg2(const float* __restrict__ b2) {
    int w = (blockIdx.x * blockDim.x + threadIdx.x) >> 5;
    int lane = threadIdx.x & 31;
    if (w >= NN) return;
    int beg = g_rowstart[w], end = g_rowstart[w + 1];
    float ad = g_a2d[w];

    float m = -1e30f;
    for (int j = beg + lane; j < end; j += 32)
        m = fmaxf(m, lrelu(g_a2s[g_srcs[j]] + ad));
    m = warpMax(m);

    float z = 0.f;
    for (int j = beg + lane; j < end; j += 32)
        z += __expf(lrelu(g_a2s[g_srcs[j]] + ad) - m);
    z = warpSum(z);
    float iz = 1.0f / (z + EPS);

    float acc[4] = {0, 0, 0, 0};
    #pragma unroll 2
    for (int j = beg; j < end; j++) {
        int s = g_srcs[j];
        float wt = __expf(lrelu(g_a2s[s] + ad) - m) * iz;
        uint2 pk = *(const uint2*)(g_h2h + (size_t)s * CH + lane * 4);
        float2 f0 = __half22float2(*(const __half2*)&pk.x);
        float2 f1 = __half22float2(*(const __half2*)&pk.y);
        acc[0] += wt * f0.x; acc[1] += wt * f0.y;
        acc[2] += wt * f1.x; acc[3] += wt * f1.y;
    }
    const float* bb = b2 + lane * 4;
    float4 o = {elu1(acc[0] + bb[0]), elu1(acc[1] + bb[1]),
                elu1(acc[2] + bb[2]), elu1(acc[3] + bb[3])};
    ((float4*)(g_out2 + (size_t)w * CH))[lane] = o;
}

// ---------------- fused MLP head ----------------
__global__ void k_mlp(const float* __restrict__ fc1w, const float* __restrict__ fc1b,
                      const float* __restrict__ fc2w, const float* __restrict__ fc2b,
                      float* __restrict__ out) {
    __shared__ float w1s[CH * FCH];
    __shared__ float w2s[FCH], b1s[FCH];
    int tid = threadIdx.x;
    for (int i = tid; i < CH * FCH; i += blockDim.x) w1s[i] = fc1w[i];
    if (tid < FCH) { w2s[tid] = fc2w[tid]; b1s[tid] = fc1b[tid]; }
    __syncthreads();

    int w = (blockIdx.x * blockDim.x + tid) >> 5;
    int lane = tid & 31;
    if (w >= NN) return;
    float4 hv = ((const float4*)(g_out2 + (size_t)w * CH))[lane];
    float hvv[4] = {hv.x, hv.y, hv.z, hv.w};
    float acc0 = 0.f, acc1 = 0.f;
    #pragma unroll
    for (int k0 = 0; k0 < CH; k0 += 4) {
        int srcl = k0 >> 2;
        #pragma unroll
        for (int kk = 0; kk < 4; kk++) {
            float hk = __shfl_sync(0xffffffffu, hvv[kk], srcl);
            acc0 += hk * w1s[(k0 + kk) * FCH + lane];
            acc1 += hk * w1s[(k0 + kk) * FCH + lane + 32];
        }
    }
    float h0 = fmaxf(acc0 + b1s[lane], 0.f);
    float h1 = fmaxf(acc1 + b1s[lane + 32], 0.f);
    float p = h0 * w2s[lane] + h1 * w2s[lane + 32];
    p = warpSum(p);
    if (lane == 0) out[w] = p + fc2b[0];
}

// ---------------- launch ----------------
extern "C" void kernel_launch(void* const* d_in, const int* in_sizes, int n_in,
                              void* d_out, int out_size) {
    const float* x    = (const float*)d_in[0];
    const int*   eraw = (const int*)d_in[1];
    const float* W1   = (const float*)d_in[2];
    const float* as1  = (const float*)d_in[3];
    const float* ad1  = (const float*)d_in[4];
    const float* b1   = (const float*)d_in[5];
    const float* W2   = (const float*)d_in[6];
    const float* as2  = (const float*)d_in[7];
    const float* ad2  = (const float*)d_in[8];
    const float* b2   = (const float*)d_in[9];
    const float* fc1w = (const float*)d_in[10];
    const float* fc1b = (const float*)d_in[11];
    const float* fc2w = (const float*)d_in[12];
    const float* fc2b = (const float*)d_in[13];
    float* out = (float*)d_out;

    cudaFuncSetAttribute(k_gemm_wmma<1>, cudaFuncAttributeMaxDynamicSharedMemorySize, SMEM_TOT);
    cudaFuncSetAttribute(k_gemm_wmma<2>, cudaFuncAttributeMaxDynamicSharedMemorySize, SMEM_TOT);

    k_detect<<<1, 32>>>(eraw);
    k_zero_deg<<<(NN + 255) / 256, 256>>>();
    k_count<<<(ET + 255) / 256, 256>>>(eraw);
    k_scanA<<<49, 1024>>>();
    k_scanB<<<1, 64>>>();
    k_scanC<<<49, 1024>>>();
    k_fill<<<(ET + 255) / 256, 256>>>(eraw);

    k_gemm_wmma<1><<<dim3(2, 391), 256, SMEM_TOT>>>(x, W1, as1, ad1);
    k_agg1<<<(NN + 7) / 8, 256>>>(b1);

    k_gemm_wmma<2><<<dim3(1, 391), 256, SMEM_TOT>>>(x, W2, as2, ad2);
    k_agg2<<<(NN + 7) / 8, 256>>>(b2);

    k_mlp<<<(NN + 7) / 8, 256>>>(fc1w, fc1b, fc2w, fc2b, out);
}

// round 6
// speedup vs baseline: 1.6734x; 1.0176x over previous
#include <cuda_runtime.h>
#include <cuda_bf16.h>
#include <cuda_fp16.h>
#include <mma.h>
#include <math.h>
#include <cstdint>

using namespace nvcuda;

#define NN 50000
#define NE 800000
#define ET (NE + NN)
#define C1 256
#define CH 128
#define FCH 64
#define NEG_SLOPE 0.2f
#define EPS 1e-16f

// ---------------- device scratch ----------------
__device__ int   g_is64;
__device__ int   g_deg[NN];
__device__ int   g_dinc[NN];
__device__ int   g_bsum[64];
__device__ int   g_rowstart[NN + 1];
__device__ int   g_cursor[NN];
__device__ int   g_srcs[ET];
__device__ __half g_h1h[(size_t)NN * C1];   // fp16 h1 (gather-only)
__device__ __half g_h2h[(size_t)NN * CH];   // fp16 h2 (gather-only)
__device__ float g_out1[(size_t)NN * C1];
__device__ float g_a1s[NN * 2], g_a1d[NN * 2];
__device__ float g_a2s[NN],     g_a2d[NN];

// ---------------- helpers ----------------
__device__ __forceinline__ float warpMax(float v) {
    #pragma unroll
    for (int o = 16; o; o >>= 1) v = fmaxf(v, __shfl_xor_sync(0xffffffffu, v, o));
    return v;
}
__device__ __forceinline__ float warpSum(float v) {
    #pragma unroll
    for (int o = 16; o; o >>= 1) v += __shfl_xor_sync(0xffffffffu, v, o);
    return v;
}
__device__ __forceinline__ float lrelu(float x) { return x > 0.f ? x : NEG_SLOPE * x; }
__device__ __forceinline__ float elu1(float x)  { return x > 0.f ? x : (__expf(x) - 1.0f); }

// ---------------- init: zero degrees + edge width detect ----------------
__global__ void k_init(const int* __restrict__ raw) {
    int t = blockIdx.x * blockDim.x + threadIdx.x;
    if (t < NN) g_deg[t] = 0;
    if (t == 0) {
        int ok = 1;
        #pragma unroll
        for (int i = 0; i < 64; i++) ok &= (raw[2 * i + 1] == 0);
        g_is64 = ok;
    }
}

// ---------------- CSR build ----------------
__global__ void k_count(const int* __restrict__ raw) {
    int t = blockIdx.x * blockDim.x + threadIdx.x;
    if (t < ET) {
        int d;
        if (t < NE) d = g_is64 ? raw[2 * (NE + t)] : raw[NE + t];
        else        d = t - NE;
        atomicAdd(&g_deg[d], 1);
    }
}
__global__ void k_scanA() {
    __shared__ int sh[1024];
    int t = threadIdx.x;
    int i = blockIdx.x * 1024 + t;
    int v = (i < NN) ? g_deg[i] : 0;
    sh[t] = v;
    __syncthreads();
    for (int off = 1; off < 1024; off <<= 1) {
        int x = (t >= off) ? sh[t - off] : 0;
        __syncthreads();
        sh[t] += x;
        __syncthreads();
    }
    if (i < NN) g_dinc[i] = sh[t];
    if (t == 1023) g_bsum[blockIdx.x] = sh[1023];
}
__global__ void k_scanC() {   // each block redundantly scans the 49 block sums
    __shared__ int s[64];
    int t = threadIdx.x;
    if (t < 64) s[t] = (t < 49) ? g_bsum[t] : 0;
    __syncthreads();
    for (int off = 1; off < 64; off <<= 1) {
        int x = (t >= off && t < 64) ? s[t - off] : 0;
        __syncthreads();
        if (t < 64) s[t] += x;
        __syncthreads();
    }
    int boff = (blockIdx.x == 0) ? 0 : s[blockIdx.x - 1];
    int i = blockIdx.x * 1024 + t;
    if (i < NN) {
        int inc = g_dinc[i] + boff;
        g_rowstart[i + 1] = inc;
        g_cursor[i] = inc - g_deg[i];
    }
    if (i == 0) g_rowstart[0] = 0;
}
__global__ void k_fill(const int* __restrict__ raw) {
    int t = blockIdx.x * blockDim.x + threadIdx.x;
    if (t < ET) {
        int s, d;
        if (t < NE) {
            if (g_is64) { s = raw[2 * t]; d = raw[2 * (NE + t)]; }
            else        { s = raw[t];     d = raw[NE + t]; }
        } else { s = d = t - NE; }
        int p = atomicAdd(&g_cursor[d], 1);
        g_srcs[p] = s;
    }
}

// ---------------- WMMA bf16 3-term GEMM with fused attention-dot epilogue ----------------
// MODE 1: h1 = x @ W1    (K=128, N=256: both head tiles in one CTA, A staged once)
// MODE 2: h2 = out1 @ W2 (K=256, N=128)
#define PA 136   // bf16 pitch (conflict-free, 16B-aligned rows)
#define PC 132   // fp32 pitch for C staging
#define OFF_AHI 0
#define OFF_ALO 34816
#define OFF_BHI 69632
#define OFF_BLO 104448
#define SMEM_TOT 139264

__device__ __forceinline__ void f2hl(float v, __nv_bfloat16& h, __nv_bfloat16& l) {
    h = __float2bfloat16_rn(v);
    l = __float2bfloat16_rn(v - __bfloat162float(h));
}

template <int MODE>
__global__ __launch_bounds__(256)
void k_gemm_wmma(const float* __restrict__ x, const float* __restrict__ W,
                 const float* __restrict__ attS, const float* __restrict__ attD) {
    extern __shared__ char dyn[];
    __shared__ float s_as[256], s_ad[256];

    constexpr int K      = (MODE == 1) ? 128 : 256;
    constexpr int NCHUNK = K / 128;
    constexpr int NHEADS = (MODE == 1) ? 2 : 1;
    constexpr int NCOLS  = (MODE == 1) ? 256 : 128;   // B width
    constexpr int Hstr   = (MODE == 1) ? C1 : CH;
    constexpr int aStr   = (MODE == 1) ? 2 : 1;
    const float* A  = (MODE == 1) ? x : g_out1;
    __half* Hout    = (MODE == 1) ? g_h1h : g_h2h;
    float* outS     = (MODE == 1) ? g_a1s : g_a2s;
    float* outD     = (MODE == 1) ? g_a1d : g_a2d;

    const int tid = threadIdx.x, wid = tid >> 5, lane = tid & 31;
    const int row0 = blockIdx.x * 128;
    const int warp_m = wid >> 1, warp_n = wid & 1;

    __nv_bfloat16* AHI = (__nv_bfloat16*)(dyn + OFF_AHI);
    __nv_bfloat16* ALO = (__nv_bfloat16*)(dyn + OFF_ALO);
    __nv_bfloat16* BHI = (__nv_bfloat16*)(dyn + OFF_BHI);
    __nv_bfloat16* BLO = (__nv_bfloat16*)(dyn + OFF_BLO);

    if (tid < NHEADS * 128) {
        s_as[tid] = attS[tid];
        s_ad[tid] = attD[tid];
    }

    const int lr = tid >> 1, lh = tid & 1;      // loader: row / 64-col half
    const bool rok = (row0 + lr) < NN;

    for (int head = 0; head < NHEADS; head++) {
        wmma::fragment<wmma::accumulator, 16, 16, 16, float> acc[2][4];
        #pragma unroll
        for (int i = 0; i < 2; i++)
            #pragma unroll
            for (int j = 0; j < 4; j++) wmma::fill_fragment(acc[i][j], 0.f);

        #pragma unroll
        for (int c = 0; c < NCHUNK; c++) {
            if (head || c) __syncthreads();   // protect SMEM being re-staged
            if (head == 0) {
                // --- stage A chunk (fp32 -> bf16 hi/lo); persists across heads ---
                const float* src = A + (size_t)(row0 + lr) * K + c * 128 + lh * 64;
                __nv_bfloat16* ah = AHI + lr * PA + lh * 64;
                __nv_bfloat16* al = ALO + lr * PA + lh * 64;
                #pragma unroll
                for (int i = 0; i < 16; i++) {
                    float4 v = rok ? ((const float4*)src)[i] : make_float4(0, 0, 0, 0);
                    __nv_bfloat16 h0, l0, h1, l1, h2, l2, h3, l3;
                    f2hl(v.x, h0, l0); f2hl(v.y, h1, l1);
                    f2hl(v.z, h2, l2); f2hl(v.w, h3, l3);
                    ((__nv_bfloat162*)(ah + i * 4))[0] = __nv_bfloat162(h0, h1);
                    ((__nv_bfloat162*)(ah + i * 4))[1] = __nv_bfloat162(h2, h3);
                    ((__nv_bfloat162*)(al + i * 4))[0] = __nv_bfloat162(l0, l1);
                    ((__nv_bfloat162*)(al + i * 4))[1] = __nv_bfloat162(l2, l3);
                }
            }
            {
                // --- stage B chunk for this head ---
                const float* src = W + (size_t)(c * 128 + lr) * NCOLS + head * 128 + lh * 64;
                __nv_bfloat16* bh = BHI + lr * PA + lh * 64;
                __nv_bfloat16* bl = BLO + lr * PA + lh * 64;
                #pragma unroll
                for (int i = 0; i < 16; i++) {
                    float4 v = ((const float4*)src)[i];
                    __nv_bfloat16 h0, l0, h1, l1, h2, l2, h3, l3;
                    f2hl(v.x, h0, l0); f2hl(v.y, h1, l1);
                    f2hl(v.z, h2, l2); f2hl(v.w, h3, l3);
                    ((__nv_bfloat162*)(bh + i * 4))[0] = __nv_bfloat162(h0, h1);
                    ((__nv_bfloat162*)(bh + i * 4))[1] = __nv_bfloat162(h2, h3);
                    ((__nv_bfloat162*)(bl + i * 4))[0] = __nv_bfloat162(l0, l1);
                    ((__nv_bfloat162*)(bl + i * 4))[1] = __nv_bfloat162(l2, l3);
                }
            }
            __syncthreads();

            // --- MMA: 3-term hi/lo ---
            #pragma unroll
            for (int kk = 0; kk < 8; kk++) {
                wmma::fragment<wmma::matrix_a, 16, 16, 16, __nv_bfloat16, wmma::row_major> ah[2], al[2];
                wmma::fragment<wmma::matrix_b, 16, 16, 16, __nv_bfloat16, wmma::row_major> bh[4], bl[4];
                #pragma unroll
                for (int i = 0; i < 2; i++) {
                    wmma::load_matrix_sync(ah[i], AHI + (warp_m * 32 + i * 16) * PA + kk * 16, PA);
                    wmma::load_matrix_sync(al[i], ALO + (warp_m * 32 + i * 16) * PA + kk * 16, PA);
                }
                #pragma unroll
                for (int j = 0; j < 4; j++) {
                    wmma::load_matrix_sync(bh[j], BHI + (kk * 16) * PA + warp_n * 64 + j * 16, PA);
                    wmma::load_matrix_sync(bl[j], BLO + (kk * 16) * PA + warp_n * 64 + j * 16, PA);
                }
                #pragma unroll
                for (int i = 0; i < 2; i++)
                    #pragma unroll
                    for (int j = 0; j < 4; j++) {
                        wmma::mma_sync(acc[i][j], ah[i], bh[j], acc[i][j]);
                        wmma::mma_sync(acc[i][j], ah[i], bl[j], acc[i][j]);
                        wmma::mma_sync(acc[i][j], al[i], bh[j], acc[i][j]);
                    }
            }
        }

        // --- epilogue: stage C in the (dead) B region, write fp16 h + attention dots ---
        __syncthreads();
        float* Cs = (float*)(dyn + OFF_BHI);
        #pragma unroll
        for (int i = 0; i < 2; i++)
            #pragma unroll
            for (int j = 0; j < 4; j++)
                wmma::store_matrix_sync(Cs + (warp_m * 32 + i * 16) * PC + warp_n * 64 + j * 16,
                                        acc[i][j], PC, wmma::mem_row_major);
        __syncthreads();

        #pragma unroll 4
        for (int rr = 0; rr < 16; rr++) {
            int row = wid * 16 + rr;
            int r = row0 + row;
            float4 v = *(float4*)&Cs[row * PC + lane * 4];
            int ab = head * 128 + lane * 4;
            float sacc = v.x * s_as[ab]     + v.y * s_as[ab + 1]
                       + v.z * s_as[ab + 2] + v.w * s_as[ab + 3];
            float dacc = v.x * s_ad[ab]     + v.y * s_ad[ab + 1]
                       + v.z * s_ad[ab + 2] + v.w * s_ad[ab + 3];
            sacc = warpSum(sacc); dacc = warpSum(dacc);
            if (r < NN) {
                __half2 p0 = __floats2half2_rn(v.x, v.y);
                __half2 p1 = __floats2half2_rn(v.z, v.w);
                uint2 pk = make_uint2(*(uint32_t*)&p0, *(uint32_t*)&p1);
                *(uint2*)(Hout + (size_t)r * Hstr + head * 128 + lane * 4) = pk;
                if (lane == 0) {
                    outS[(size_t)r * aStr + head] = sacc;
                    outD[(size_t)r * aStr + head] = dacc;
                }
            }
        }
    }
}

// ---------------- node-centric GAT aggregation (fp16 gather, fp32 accum) ----------------
__global__ void k_agg1(const float* __restrict__ b1) {
    int w = (blockIdx.x * blockDim.x + threadIdx.x) >> 5;
    int lane = threadIdx.x & 31;
    if (w >= NN) return;
    int beg = g_rowstart[w], end = g_rowstart[w + 1];
    float ad0 = g_a1d[2 * w], ad1v = g_a1d[2 * w + 1];

    float m0 = -1e30f, m1 = -1e30f;
    for (int j = beg + lane; j < end; j += 32) {
        int s = g_srcs[j];
        m0 = fmaxf(m0, lrelu(g_a1s[2 * s] + ad0));
        m1 = fmaxf(m1, lrelu(g_a1s[2 * s + 1] + ad1v));
    }
    m0 = warpMax(m0); m1 = warpMax(m1);

    float z0 = 0.f, z1 = 0.f;
    for (int j = beg + lane; j < end; j += 32) {
        int s = g_srcs[j];
        z0 += __expf(lrelu(g_a1s[2 * s] + ad0) - m0);
        z1 += __expf(lrelu(g_a1s[2 * s + 1] + ad1v) - m1);
    }
    z0 = warpSum(z0); z1 = warpSum(z1);

    // lanes 0-15 -> head 0 channels [8l,8l+8); lanes 16-31 -> head 1
    const int hd = lane >> 4;
    const float m  = hd ? m1 : m0;
    const float iz = hd ? (1.0f / (z1 + EPS)) : (1.0f / (z0 + EPS));
    const float ad = hd ? ad1v : ad0;

    float acc[8] = {0, 0, 0, 0, 0, 0, 0, 0};
    #pragma unroll 2
    for (int j = beg; j < end; j++) {
        int s = g_srcs[j];
        float wt = __expf(lrelu(g_a1s[2 * s + hd] + ad) - m) * iz;
        uint4 pk = *(const uint4*)(g_h1h + (size_t)s * C1 + lane * 8);
        const uint32_t u[4] = {pk.x, pk.y, pk.z, pk.w};
        #pragma unroll
        for (int q = 0; q < 4; q++) {
            float2 f = __half22float2(*(const __half2*)&u[q]);
            acc[2 * q]     += wt * f.x;
            acc[2 * q + 1] += wt * f.y;
        }
    }
    float* o = g_out1 + (size_t)w * C1 + lane * 8;
    const float* bb = b1 + lane * 8;
    float4 o0 = {elu1(acc[0] + bb[0]), elu1(acc[1] + bb[1]),
                 elu1(acc[2] + bb[2]), elu1(acc[3] + bb[3])};
    float4 o1 = {elu1(acc[4] + bb[4]), elu1(acc[5] + bb[5]),
                 elu1(acc[6] + bb[6]), elu1(acc[7] + bb[7])};
    ((float4*)o)[0] = o0; ((float4*)o)[1] = o1;
}

// ---------------- layer-2 aggregation fused with MLP head ----------------
__global__ void k_agg2mlp(const float* __restrict__ b2,
                          const float* __restrict__ fc1w, const float* __restrict__ fc1b,
                          const float* __restrict__ fc2w, const float* __restrict__ fc2b,
                          float* __restrict__ out) {
    __shared__ float w1s[CH * FCH];
    __shared__ float w2s[FCH], b1s[FCH], b2s[CH];
    int tid = threadIdx.x;
    for (int i = tid; i < CH * FCH; i += blockDim.x) w1s[i] = fc1w[i];
    if (tid < FCH) { w2s[tid] = fc2w[tid]; b1s[tid] = fc1b[tid]; }
    if (tid < CH)  b2s[tid] = b2[tid];
    __syncthreads();

    int w = (blockIdx.x * blockDim.x + tid) >> 5;
    int lane = tid & 31;
    if (w >= NN) return;
    int beg = g_rowstart[w], end = g_rowstart[w + 1];
    float ad = g_a2d[w];

    float m = -1e30f;
    for (int j = beg + lane; j < end; j += 32)
        m = fmaxf(m, lrelu(g_a2s[g_srcs[j]] + ad));
    m = warpMax(m);

    float z = 0.f;
    for (int j = beg + lane; j < end; j += 32)
        z += __expf(lrelu(g_a2s[g_srcs[j]] + ad) - m);
    z = warpSum(z);
    float iz = 1.0f / (z + EPS);

    float acc[4] = {0, 0, 0, 0};
    #pragma unroll 2
    for (int j = beg; j < end; j++) {
        int s = g_srcs[j];
        float wt = __expf(lrelu(g_a2s[s] + ad) - m) * iz;
        uint2 pk = *(const uint2*)(g_h2h + (size_t)s * CH + lane * 4);
        float2 f0 = __half22float2(*(const __half2*)&pk.x);
        float2 f1 = __half22float2(*(const __half2*)&pk.y);
        acc[0] += wt * f0.x; acc[1] += wt * f0.y;
        acc[2] += wt * f1.x; acc[3] += wt * f1.y;
    }
    // out2 row stays in registers: lane holds channels [4*lane, 4*lane+4)
    float hvv[4];
    #pragma unroll
    for (int q = 0; q < 4; q++) hvv[q] = elu1(acc[q] + b2s[lane * 4 + q]);

    // MLP: 128 -> 64 (relu) -> 1
    float acc0 = 0.f, acc1 = 0.f;
    #pragma unroll
    for (int k0 = 0; k0 < CH; k0 += 4) {
        int srcl = k0 >> 2;
        #pragma unroll
        for (int kk = 0; kk < 4; kk++) {
            float hk = __shfl_sync(0xffffffffu, hvv[kk], srcl);
            acc0 += hk * w1s[(k0 + kk) * FCH + lane];
            acc1 += hk * w1s[(k0 + kk) * FCH + lane + 32];
        }
    }
    float h0 = fmaxf(acc0 + b1s[lane], 0.f);
    float h1 = fmaxf(acc1 + b1s[lane + 32], 0.f);
    float p = h0 * w2s[lane] + h1 * w2s[lane + 32];
    p = warpSum(p);
    if (lane == 0) out[w] = p + fc2b[0];
}

// ---------------- launch ----------------
extern "C" void kernel_launch(void* const* d_in, const int* in_sizes, int n_in,
                              void* d_out, int out_size) {
    const float* x    = (const float*)d_in[0];
    const int*   eraw = (const int*)d_in[1];
    const float* W1   = (const float*)d_in[2];
    const float* as1  = (const float*)d_in[3];
    const float* ad1  = (const float*)d_in[4];
    const float* b1   = (const float*)d_in[5];
    const float* W2   = (const float*)d_in[6];
    const float* as2  = (const float*)d_in[7];
    const float* ad2  = (const float*)d_in[8];
    const float* b2   = (const float*)d_in[9];
    const float* fc1w = (const float*)d_in[10];
    const float* fc1b = (const float*)d_in[11];
    const float* fc2w = (const float*)d_in[12];
    const float* fc2b = (const float*)d_in[13];
    float* out = (float*)d_out;

    cudaFuncSetAttribute(k_gemm_wmma<1>, cudaFuncAttributeMaxDynamicSharedMemorySize, SMEM_TOT);
    cudaFuncSetAttribute(k_gemm_wmma<2>, cudaFuncAttributeMaxDynamicSharedMemorySize, SMEM_TOT);

    k_init<<<(NN + 255) / 256, 256>>>(eraw);
    k_count<<<(ET + 255) / 256, 256>>>(eraw);
    k_scanA<<<49, 1024>>>();
    k_scanC<<<49, 1024>>>();
    k_fill<<<(ET + 255) / 256, 256>>>(eraw);

    k_gemm_wmma<1><<<391, 256, SMEM_TOT>>>(x, W1, as1, ad1);   // launch #6 -> ncu window
    k_agg1<<<(NN + 7) / 8, 256>>>(b1);

    k_gemm_wmma<2><<<391, 256, SMEM_TOT>>>(x, W2, as2, ad2);
    k_agg2mlp<<<(NN + 7) / 8, 256>>>(b2, fc1w, fc1b, fc2w, fc2b, out);
}

// round 7
// speedup vs baseline: 1.8380x; 1.0984x over previous
#include <cuda_runtime.h>
#include <cuda_bf16.h>
#include <cuda_fp16.h>
#include <mma.h>
#include <math.h>
#include <cstdint>

using namespace nvcuda;

#define NN 50000
#define NE 800000
#define ET (NE + NN)
#define C1 256
#define CH 128
#define FCH 64
#define NEG_SLOPE 0.2f
#define EPS 1e-16f

// ---------------- device scratch ----------------
__device__ int   g_is64;
__device__ int   g_deg[NN];
__device__ int   g_dinc[NN];
__device__ int   g_bsum[64];
__device__ int   g_rowstart[NN + 1];
__device__ int   g_cursor[NN];
__device__ int   g_srcs[ET];
__device__ __half g_h1h[(size_t)NN * C1];   // fp16 h1 (gather-only)
__device__ __half g_h2h[(size_t)NN * CH];   // fp16 h2 (gather-only)
__device__ float g_out1[(size_t)NN * C1];
__device__ float g_a1s[NN * 2], g_a1d[NN * 2];
__device__ float g_a2s[NN],     g_a2d[NN];

// ---------------- helpers ----------------
__device__ __forceinline__ float warpSum(float v) {
    #pragma unroll
    for (int o = 16; o; o >>= 1) v += __shfl_xor_sync(0xffffffffu, v, o);
    return v;
}
__device__ __forceinline__ float lrelu(float x) { return x > 0.f ? x : NEG_SLOPE * x; }
__device__ __forceinline__ float elu1(float x)  { return x > 0.f ? x : (__expf(x) - 1.0f); }

// ---------------- init: zero degrees + edge width detect ----------------
__global__ void k_init(const int* __restrict__ raw) {
    int t = blockIdx.x * blockDim.x + threadIdx.x;
    if (t < NN) g_deg[t] = 0;
    if (t == 0) {
        int ok = 1;
        #pragma unroll
        for (int i = 0; i < 64; i++) ok &= (raw[2 * i + 1] == 0);
        g_is64 = ok;
    }
}

// ---------------- CSR build ----------------
__global__ void k_count(const int* __restrict__ raw) {
    int t = blockIdx.x * blockDim.x + threadIdx.x;
    if (t < ET) {
        int d;
        if (t < NE) d = g_is64 ? raw[2 * (NE + t)] : raw[NE + t];
        else        d = t - NE;
        atomicAdd(&g_deg[d], 1);
    }
}
__global__ void k_scanA() {
    __shared__ int sh[1024];
    int t = threadIdx.x;
    int i = blockIdx.x * 1024 + t;
    int v = (i < NN) ? g_deg[i] : 0;
    sh[t] = v;
    __syncthreads();
    for (int off = 1; off < 1024; off <<= 1) {
        int x = (t >= off) ? sh[t - off] : 0;
        __syncthreads();
        sh[t] += x;
        __syncthreads();
    }
    if (i < NN) g_dinc[i] = sh[t];
    if (t == 1023) g_bsum[blockIdx.x] = sh[1023];
}
__global__ void k_scanC() {   // each block redundantly scans the 49 block sums
    __shared__ int s[64];
    int t = threadIdx.x;
    if (t < 64) s[t] = (t < 49) ? g_bsum[t] : 0;
    __syncthreads();
    for (int off = 1; off < 64; off <<= 1) {
        int x = (t >= off && t < 64) ? s[t - off] : 0;
        __syncthreads();
        if (t < 64) s[t] += x;
        __syncthreads();
    }
    int boff = (blockIdx.x == 0) ? 0 : s[blockIdx.x - 1];
    int i = blockIdx.x * 1024 + t;
    if (i < NN) {
        int inc = g_dinc[i] + boff;
        g_rowstart[i + 1] = inc;
        g_cursor[i] = inc - g_deg[i];
    }
    if (i == 0) g_rowstart[0] = 0;
}
__global__ void k_fill(const int* __restrict__ raw) {
    int t = blockIdx.x * blockDim.x + threadIdx.x;
    if (t < ET) {
        int s, d;
        if (t < NE) {
            if (g_is64) { s = raw[2 * t]; d = raw[2 * (NE + t)]; }
            else        { s = raw[t];     d = raw[NE + t]; }
        } else { s = d = t - NE; }
        int p = atomicAdd(&g_cursor[d], 1);
        g_srcs[p] = s;
    }
}

// ---------------- WMMA bf16 3-term GEMM with fused attention-dot epilogue ----------------
// MODE 1: h1 = x @ W1    (K=128, N=256: both head tiles in one CTA, A staged once)
// MODE 2: h2 = out1 @ W2 (K=256, N=128)
#define PA 136   // bf16 pitch (conflict-free, 16B-aligned rows)
#define PC 132   // fp32 pitch for C staging
#define OFF_AHI 0
#define OFF_ALO 34816
#define OFF_BHI 69632
#define OFF_BLO 104448
#define SMEM_TOT 139264

__device__ __forceinline__ void f2hl(float v, __nv_bfloat16& h, __nv_bfloat16& l) {
    h = __float2bfloat16_rn(v);
    l = __float2bfloat16_rn(v - __bfloat162float(h));
}

template <int MODE>
__global__ __launch_bounds__(256)
void k_gemm_wmma(const float* __restrict__ x, const float* __restrict__ W,
                 const float* __restrict__ attS, const float* __restrict__ attD) {
    extern __shared__ char dyn[];
    __shared__ float s_as[256], s_ad[256];

    constexpr int K      = (MODE == 1) ? 128 : 256;
    constexpr int NCHUNK = K / 128;
    constexpr int NHEADS = (MODE == 1) ? 2 : 1;
    constexpr int NCOLS  = (MODE == 1) ? 256 : 128;   // B width
    constexpr int Hstr   = (MODE == 1) ? C1 : CH;
    constexpr int aStr   = (MODE == 1) ? 2 : 1;
    const float* A  = (MODE == 1) ? x : g_out1;
    __half* Hout    = (MODE == 1) ? g_h1h : g_h2h;
    float* outS     = (MODE == 1) ? g_a1s : g_a2s;
    float* outD     = (MODE == 1) ? g_a1d : g_a2d;

    const int tid = threadIdx.x, wid = tid >> 5, lane = tid & 31;
    const int row0 = blockIdx.x * 128;
    const int warp_m = wid >> 1, warp_n = wid & 1;

    __nv_bfloat16* AHI = (__nv_bfloat16*)(dyn + OFF_AHI);
    __nv_bfloat16* ALO = (__nv_bfloat16*)(dyn + OFF_ALO);
    __nv_bfloat16* BHI = (__nv_bfloat16*)(dyn + OFF_BHI);
    __nv_bfloat16* BLO = (__nv_bfloat16*)(dyn + OFF_BLO);

    if (tid < NHEADS * 128) {
        s_as[tid] = attS[tid];
        s_ad[tid] = attD[tid];
    }

    const int lr = tid >> 1, lh = tid & 1;      // loader: row / 64-col half
    const bool rok = (row0 + lr) < NN;

    for (int head = 0; head < NHEADS; head++) {
        wmma::fragment<wmma::accumulator, 16, 16, 16, float> acc[2][4];
        #pragma unroll
        for (int i = 0; i < 2; i++)
            #pragma unroll
            for (int j = 0; j < 4; j++) wmma::fill_fragment(acc[i][j], 0.f);

        #pragma unroll
        for (int c = 0; c < NCHUNK; c++) {
            if (head || c) __syncthreads();   // protect SMEM being re-staged
            if (head == 0) {
                // --- stage A chunk (fp32 -> bf16 hi/lo); persists across heads ---
                const float* src = A + (size_t)(row0 + lr) * K + c * 128 + lh * 64;
                __nv_bfloat16* ah = AHI + lr * PA + lh * 64;
                __nv_bfloat16* al = ALO + lr * PA + lh * 64;
                #pragma unroll
                for (int i = 0; i < 16; i++) {
                    float4 v = rok ? ((const float4*)src)[i] : make_float4(0, 0, 0, 0);
                    __nv_bfloat16 h0, l0, h1, l1, h2, l2, h3, l3;
                    f2hl(v.x, h0, l0); f2hl(v.y, h1, l1);
                    f2hl(v.z, h2, l2); f2hl(v.w, h3, l3);
                    ((__nv_bfloat162*)(ah + i * 4))[0] = __nv_bfloat162(h0, h1);
                    ((__nv_bfloat162*)(ah + i * 4))[1] = __nv_bfloat162(h2, h3);
                    ((__nv_bfloat162*)(al + i * 4))[0] = __nv_bfloat162(l0, l1);
                    ((__nv_bfloat162*)(al + i * 4))[1] = __nv_bfloat162(l2, l3);
                }
            }
            {
                // --- stage B chunk for this head ---
                const float* src = W + (size_t)(c * 128 + lr) * NCOLS + head * 128 + lh * 64;
                __nv_bfloat16* bh = BHI + lr * PA + lh * 64;
                __nv_bfloat16* bl = BLO + lr * PA + lh * 64;
                #pragma unroll
                for (int i = 0; i < 16; i++) {
                    float4 v = ((const float4*)src)[i];
                    __nv_bfloat16 h0, l0, h1, l1, h2, l2, h3, l3;
                    f2hl(v.x, h0, l0); f2hl(v.y, h1, l1);
                    f2hl(v.z, h2, l2); f2hl(v.w, h3, l3);
                    ((__nv_bfloat162*)(bh + i * 4))[0] = __nv_bfloat162(h0, h1);
                    ((__nv_bfloat162*)(bh + i * 4))[1] = __nv_bfloat162(h2, h3);
                    ((__nv_bfloat162*)(bl + i * 4))[0] = __nv_bfloat162(l0, l1);
                    ((__nv_bfloat162*)(bl + i * 4))[1] = __nv_bfloat162(l2, l3);
                }
            }
            __syncthreads();

            // --- MMA: 3-term hi/lo ---
            #pragma unroll
            for (int kk = 0; kk < 8; kk++) {
                wmma::fragment<wmma::matrix_a, 16, 16, 16, __nv_bfloat16, wmma::row_major> ah[2], al[2];
                wmma::fragment<wmma::matrix_b, 16, 16, 16, __nv_bfloat16, wmma::row_major> bh[4], bl[4];
                #pragma unroll
                for (int i = 0; i < 2; i++) {
                    wmma::load_matrix_sync(ah[i], AHI + (warp_m * 32 + i * 16) * PA + kk * 16, PA);
                    wmma::load_matrix_sync(al[i], ALO + (warp_m * 32 + i * 16) * PA + kk * 16, PA);
                }
                #pragma unroll
                for (int j = 0; j < 4; j++) {
                    wmma::load_matrix_sync(bh[j], BHI + (kk * 16) * PA + warp_n * 64 + j * 16, PA);
                    wmma::load_matrix_sync(bl[j], BLO + (kk * 16) * PA + warp_n * 64 + j * 16, PA);
                }
                #pragma unroll
                for (int i = 0; i < 2; i++)
                    #pragma unroll
                    for (int j = 0; j < 4; j++) {
                        wmma::mma_sync(acc[i][j], ah[i], bh[j], acc[i][j]);
                        wmma::mma_sync(acc[i][j], ah[i], bl[j], acc[i][j]);
                        wmma::mma_sync(acc[i][j], al[i], bh[j], acc[i][j]);
                    }
            }
        }

        // --- epilogue: stage C in the (dead) B region, write fp16 h + attention dots ---
        __syncthreads();
        float* Cs = (float*)(dyn + OFF_BHI);
        #pragma unroll
        for (int i = 0; i < 2; i++)
            #pragma unroll
            for (int j = 0; j < 4; j++)
                wmma::store_matrix_sync(Cs + (warp_m * 32 + i * 16) * PC + warp_n * 64 + j * 16,
                                        acc[i][j], PC, wmma::mem_row_major);
        __syncthreads();

        #pragma unroll 4
        for (int rr = 0; rr < 16; rr++) {
            int row = wid * 16 + rr;
            int r = row0 + row;
            float4 v = *(float4*)&Cs[row * PC + lane * 4];
            int ab = head * 128 + lane * 4;
            float sacc = v.x * s_as[ab]     + v.y * s_as[ab + 1]
                       + v.z * s_as[ab + 2] + v.w * s_as[ab + 3];
            float dacc = v.x * s_ad[ab]     + v.y * s_ad[ab + 1]
                       + v.z * s_ad[ab + 2] + v.w * s_ad[ab + 3];
            sacc = warpSum(sacc); dacc = warpSum(dacc);
            if (r < NN) {
                __half2 p0 = __floats2half2_rn(v.x, v.y);
                __half2 p1 = __floats2half2_rn(v.z, v.w);
                uint2 pk = make_uint2(*(uint32_t*)&p0, *(uint32_t*)&p1);
                *(uint2*)(Hout + (size_t)r * Hstr + head * 128 + lane * 4) = pk;
                if (lane == 0) {
                    outS[(size_t)r * aStr + head] = sacc;
                    outD[(size_t)r * aStr + head] = dacc;
                }
            }
        }
    }
}

// ---------------- single-pass GAT aggregation (no max-shift; softmax invariant) ----------------
__global__ void k_agg1(const float* __restrict__ b1) {
    int w = (blockIdx.x * blockDim.x + threadIdx.x) >> 5;
    int lane = threadIdx.x & 31;
    if (w >= NN) return;
    int beg = g_rowstart[w], end = g_rowstart[w + 1];

    // lanes 0-15 -> head 0 channels [8l,8l+8); lanes 16-31 -> head 1
    const int hd = lane >> 4;
    const float ad = g_a1d[2 * w + hd];

    float z = 0.f;
    float acc[8] = {0, 0, 0, 0, 0, 0, 0, 0};
    #pragma unroll 2
    for (int j = beg; j < end; j++) {
        int s = g_srcs[j];
        float e = __expf(lrelu(g_a1s[2 * s + hd] + ad));
        z += e;
        uint4 pk = *(const uint4*)(g_h1h + (size_t)s * C1 + lane * 8);
        const uint32_t u[4] = {pk.x, pk.y, pk.z, pk.w};
        #pragma unroll
        for (int q = 0; q < 4; q++) {
            float2 f = __half22float2(*(const __half2*)&u[q]);
            acc[2 * q]     += e * f.x;
            acc[2 * q + 1] += e * f.y;
        }
    }
    float iz = 1.0f / (z + EPS);
    float* o = g_out1 + (size_t)w * C1 + lane * 8;
    const float* bb = b1 + lane * 8;
    float4 o0 = {elu1(acc[0] * iz + bb[0]), elu1(acc[1] * iz + bb[1]),
                 elu1(acc[2] * iz + bb[2]), elu1(acc[3] * iz + bb[3])};
    float4 o1 = {elu1(acc[4] * iz + bb[4]), elu1(acc[5] * iz + bb[5]),
                 elu1(acc[6] * iz + bb[6]), elu1(acc[7] * iz + bb[7])};
    ((float4*)o)[0] = o0; ((float4*)o)[1] = o1;
}

// ---------------- layer-2 single-pass aggregation fused with MLP head ----------------
__global__ void k_agg2mlp(const float* __restrict__ b2,
                          const float* __restrict__ fc1w, const float* __restrict__ fc1b,
                          const float* __restrict__ fc2w, const float* __restrict__ fc2b,
                          float* __restrict__ out) {
    __shared__ float w1s[CH * FCH];
    __shared__ float w2s[FCH], b1s[FCH], b2s[CH];
    int tid = threadIdx.x;
    for (int i = tid; i < CH * FCH; i += blockDim.x) w1s[i] = fc1w[i];
    if (tid < FCH) { w2s[tid] = fc2w[tid]; b1s[tid] = fc1b[tid]; }
    if (tid < CH)  b2s[tid] = b2[tid];
    __syncthreads();

    int w = (blockIdx.x * blockDim.x + tid) >> 5;
    int lane = tid & 31;
    if (w >= NN) return;
    int beg = g_rowstart[w], end = g_rowstart[w + 1];
    float ad = g_a2d[w];

    float z = 0.f;
    float acc[4] = {0, 0, 0, 0};
    #pragma unroll 2
    for (int j = beg; j < end; j++) {
        int s = g_srcs[j];
        float e = __expf(lrelu(g_a2s[s] + ad));
        z += e;
        uint2 pk = *(const uint2*)(g_h2h + (size_t)s * CH + lane * 4);
        float2 f0 = __half22float2(*(const __half2*)&pk.x);
        float2 f1 = __half22float2(*(const __half2*)&pk.y);
        acc[0] += e * f0.x; acc[1] += e * f0.y;
        acc[2] += e * f1.x; acc[3] += e * f1.y;
    }
    float iz = 1.0f / (z + EPS);

    // out2 row stays in registers: lane holds channels [4*lane, 4*lane+4)
    float hvv[4];
    #pragma unroll
    for (int q = 0; q < 4; q++) hvv[q] = elu1(acc[q] * iz + b2s[lane * 4 + q]);

    // MLP: 128 -> 64 (relu) -> 1
    float acc0 = 0.f, acc1 = 0.f;
    #pragma unroll
    for (int k0 = 0; k0 < CH; k0 += 4) {
        int srcl = k0 >> 2;
        #pragma unroll
        for (int kk = 0; kk < 4; kk++) {
            float hk = __shfl_sync(0xffffffffu, hvv[kk], srcl);
            acc0 += hk * w1s[(k0 + kk) * FCH + lane];
            acc1 += hk * w1s[(k0 + kk) * FCH + lane + 32];
        }
    }
    float h0 = fmaxf(acc0 + b1s[lane], 0.f);
    float h1 = fmaxf(acc1 + b1s[lane + 32], 0.f);
    float p = h0 * w2s[lane] + h1 * w2s[lane + 32];
    p = warpSum(p);
    if (lane == 0) out[w] = p + fc2b[0];
}

// ---------------- launch ----------------
extern "C" void kernel_launch(void* const* d_in, const int* in_sizes, int n_in,
                              void* d_out, int out_size) {
    const float* x    = (const float*)d_in[0];
    const int*   eraw = (const int*)d_in[1];
    const float* W1   = (const float*)d_in[2];
    const float* as1  = (const float*)d_in[3];
    const float* ad1  = (const float*)d_in[4];
    const float* b1   = (const float*)d_in[5];
    const float* W2   = (const float*)d_in[6];
    const float* as2  = (const float*)d_in[7];
    const float* ad2  = (const float*)d_in[8];
    const float* b2   = (const float*)d_in[9];
    const float* fc1w = (const float*)d_in[10];
    const float* fc1b = (const float*)d_in[11];
    const float* fc2w = (const float*)d_in[12];
    const float* fc2b = (const float*)d_in[13];
    float* out = (float*)d_out;

    cudaFuncSetAttribute(k_gemm_wmma<1>, cudaFuncAttributeMaxDynamicSharedMemorySize, SMEM_TOT);
    cudaFuncSetAttribute(k_gemm_wmma<2>, cudaFuncAttributeMaxDynamicSharedMemorySize, SMEM_TOT);

    k_init<<<(NN + 255) / 256, 256>>>(eraw);                   // #1
    k_count<<<(ET + 255) / 256, 256>>>(eraw);                  // #2
    k_scanA<<<49, 1024>>>();                                   // #3
    k_gemm_wmma<1><<<391, 256, SMEM_TOT>>>(x, W1, as1, ad1);   // #4 -> ncu window
    k_scanC<<<49, 1024>>>();                                   // #5
    k_fill<<<(ET + 255) / 256, 256>>>(eraw);                   // #6
    k_agg1<<<(NN + 7) / 8, 256>>>(b1);                         // #7

    k_gemm_wmma<2><<<391, 256, SMEM_TOT>>>(x, W2, as2, ad2);   // #8
    k_agg2mlp<<<(NN + 7) / 8, 256>>>(b2, fc1w, fc1b, fc2w, fc2b, out);  // #9
}

// round 8
// speedup vs baseline: 2.0689x; 1.1257x over previous
#include <cuda_runtime.h>
#include <cuda_fp16.h>
#include <mma.h>
#include <math.h>
#include <cstdint>

using namespace nvcuda;

#define NN 50000
#define NE 800000
#define ET (NE + NN)
#define C1 256
#define CH 128
#define FCH 64
#define NEG_SLOPE 0.2f
#define EPS 1e-16f

// ---------------- device scratch ----------------
__device__ int   g_is64;
__device__ int   g_deg[NN];
__device__ int   g_dinc[NN];
__device__ int   g_bsum[64];
__device__ int   g_rowstart[NN + 1];
__device__ int   g_cursor[NN];
__device__ int   g_srcs[ET];
__device__ __half g_h1h[(size_t)NN * C1];   // fp16 h1 (gather-only)
__device__ __half g_h2h[(size_t)NN * CH];   // fp16 h2 (gather-only)
__device__ float g_out1[(size_t)NN * C1];
__device__ float g_a1s[NN * 2], g_a1d[NN * 2];
__device__ float g_a2s[NN],     g_a2d[NN];

// ---------------- helpers ----------------
__device__ __forceinline__ float warpSum(float v) {
    #pragma unroll
    for (int o = 16; o; o >>= 1) v += __shfl_xor_sync(0xffffffffu, v, o);
    return v;
}
__device__ __forceinline__ float lrelu(float x) { return x > 0.f ? x : NEG_SLOPE * x; }
__device__ __forceinline__ float elu1(float x)  { return x > 0.f ? x : (__expf(x) - 1.0f); }

// ---------------- init: zero degrees + edge width detect ----------------
__global__ void k_init(const int* __restrict__ raw) {
    int t = blockIdx.x * blockDim.x + threadIdx.x;
    if (t < NN) g_deg[t] = 0;
    if (t == 0) {
        int ok = 1;
        #pragma unroll
        for (int i = 0; i < 64; i++) ok &= (raw[2 * i + 1] == 0);
        g_is64 = ok;
    }
}

// ---------------- CSR build ----------------
__global__ void k_count(const int* __restrict__ raw) {
    int t = blockIdx.x * blockDim.x + threadIdx.x;
    if (t < ET) {
        int d;
        if (t < NE) d = g_is64 ? raw[2 * (NE + t)] : raw[NE + t];
        else        d = t - NE;
        atomicAdd(&g_deg[d], 1);
    }
}
__global__ void k_scanA() {
    __shared__ int sh[1024];
    int t = threadIdx.x;
    int i = blockIdx.x * 1024 + t;
    int v = (i < NN) ? g_deg[i] : 0;
    sh[t] = v;
    __syncthreads();
    for (int off = 1; off < 1024; off <<= 1) {
        int x = (t >= off) ? sh[t - off] : 0;
        __syncthreads();
        sh[t] += x;
        __syncthreads();
    }
    if (i < NN) g_dinc[i] = sh[t];
    if (t == 1023) g_bsum[blockIdx.x] = sh[1023];
}
__global__ void k_scanC() {   // each block redundantly scans the 49 block sums
    __shared__ int s[64];
    int t = threadIdx.x;
    if (t < 64) s[t] = (t < 49) ? g_bsum[t] : 0;
    __syncthreads();
    for (int off = 1; off < 64; off <<= 1) {
        int x = (t >= off && t < 64) ? s[t - off] : 0;
        __syncthreads();
        if (t < 64) s[t] += x;
        __syncthreads();
    }
    int boff = (blockIdx.x == 0) ? 0 : s[blockIdx.x - 1];
    int i = blockIdx.x * 1024 + t;
    if (i < NN) {
        int inc = g_dinc[i] + boff;
        g_rowstart[i + 1] = inc;
        g_cursor[i] = inc - g_deg[i];
    }
    if (i == 0) g_rowstart[0] = 0;
}
__global__ void k_fill(const int* __restrict__ raw) {
    int t = blockIdx.x * blockDim.x + threadIdx.x;
    if (t < ET) {
        int s, d;
        if (t < NE) {
            if (g_is64) { s = raw[2 * t]; d = raw[2 * (NE + t)]; }
            else        { s = raw[t];     d = raw[NE + t]; }
        } else { s = d = t - NE; }
        int p = atomicAdd(&g_cursor[d], 1);
        g_srcs[p] = s;
    }
}

// ---------------- WMMA fp16 single-term GEMM with fused attention-dot epilogue ----------------
// MODE 1: h1 = x @ W1    (K=128, N=256: both head tiles in one CTA, A staged once)
// MODE 2: h2 = out1 @ W2 (K=256, N=128)
#define PA 136   // fp16 pitch (conflict-free, 16B-aligned rows)
#define PC 132   // fp32 pitch for C staging
#define OFF_A 0
#define OFF_B 34816
#define SMEM_TOT 102400   // A (34816) + max(B 34816, C 67584)

template <int MODE>
__global__ __launch_bounds__(256, 2)
void k_gemm_wmma(const float* __restrict__ x, const float* __restrict__ W,
                 const float* __restrict__ attS, const float* __restrict__ attD) {
    extern __shared__ char dyn[];
    __shared__ float s_as[256], s_ad[256];

    constexpr int K      = (MODE == 1) ? 128 : 256;
    constexpr int NCHUNK = K / 128;
    constexpr int NHEADS = (MODE == 1) ? 2 : 1;
    constexpr int NCOLS  = (MODE == 1) ? 256 : 128;   // B width
    constexpr int Hstr   = (MODE == 1) ? C1 : CH;
    constexpr int aStr   = (MODE == 1) ? 2 : 1;
    const float* A  = (MODE == 1) ? x : g_out1;
    __half* Hout    = (MODE == 1) ? g_h1h : g_h2h;
    float* outS     = (MODE == 1) ? g_a1s : g_a2s;
    float* outD     = (MODE == 1) ? g_a1d : g_a2d;

    const int tid = threadIdx.x, wid = tid >> 5, lane = tid & 31;
    const int row0 = blockIdx.x * 128;
    const int warp_m = wid >> 1, warp_n = wid & 1;

    __half* AH = (__half*)(dyn + OFF_A);
    __half* BH = (__half*)(dyn + OFF_B);

    if (tid < NHEADS * 128) {
        s_as[tid] = attS[tid];
        s_ad[tid] = attD[tid];
    }

    const int lr = tid >> 1, lh = tid & 1;      // loader: row / 64-col half
    const bool rok = (row0 + lr) < NN;

    for (int head = 0; head < NHEADS; head++) {
        wmma::fragment<wmma::accumulator, 16, 16, 16, float> acc[2][4];
        #pragma unroll
        for (int i = 0; i < 2; i++)
            #pragma unroll
            for (int j = 0; j < 4; j++) wmma::fill_fragment(acc[i][j], 0.f);

        #pragma unroll
        for (int c = 0; c < NCHUNK; c++) {
            if (head || c) __syncthreads();   // protect SMEM being re-staged
            if (head == 0) {
                // --- stage A chunk (fp32 -> fp16); persists across heads ---
                const float* src = A + (size_t)(row0 + lr) * K + c * 128 + lh * 64;
                __half* ah = AH + lr * PA + lh * 64;
                #pragma unroll
                for (int i = 0; i < 16; i++) {
                    float4 v = rok ? ((const float4*)src)[i] : make_float4(0, 0, 0, 0);
                    ((__half2*)(ah + i * 4))[0] = __floats2half2_rn(v.x, v.y);
                    ((__half2*)(ah + i * 4))[1] = __floats2half2_rn(v.z, v.w);
                }
            }
            {
                // --- stage B chunk for this head ---
                const float* src = W + (size_t)(c * 128 + lr) * NCOLS + head * 128 + lh * 64;
                __half* bh = BH + lr * PA + lh * 64;
                #pragma unroll
                for (int i = 0; i < 16; i++) {
                    float4 v = ((const float4*)src)[i];
                    ((__half2*)(bh + i * 4))[0] = __floats2half2_rn(v.x, v.y);
                    ((__half2*)(bh + i * 4))[1] = __floats2half2_rn(v.z, v.w);
                }
            }
            __syncthreads();

            // --- MMA: single-term fp16 ---
            #pragma unroll
            for (int kk = 0; kk < 8; kk++) {
                wmma::fragment<wmma::matrix_a, 16, 16, 16, __half, wmma::row_major> af[2];
                wmma::fragment<wmma::matrix_b, 16, 16, 16, __half, wmma::row_major> bf[4];
                #pragma unroll
                for (int i = 0; i < 2; i++)
                    wmma::load_matrix_sync(af[i], AH + (warp_m * 32 + i * 16) * PA + kk * 16, PA);
                #pragma unroll
                for (int j = 0; j < 4; j++)
                    wmma::load_matrix_sync(bf[j], BH + (kk * 16) * PA + warp_n * 64 + j * 16, PA);
                #pragma unroll
                for (int i = 0; i < 2; i++)
                    #pragma unroll
                    for (int j = 0; j < 4; j++)
                        wmma::mma_sync(acc[i][j], af[i], bf[j], acc[i][j]);
            }
        }

        // --- epilogue: stage C in the (dead) B region, write fp16 h + attention dots ---
        __syncthreads();
        float* Cs = (float*)(dyn + OFF_B);
        #pragma unroll
        for (int i = 0; i < 2; i++)
            #pragma unroll
            for (int j = 0; j < 4; j++)
                wmma::store_matrix_sync(Cs + (warp_m * 32 + i * 16) * PC + warp_n * 64 + j * 16,
                                        acc[i][j], PC, wmma::mem_row_major);
        __syncthreads();

        #pragma unroll 4
        for (int rr = 0; rr < 16; rr++) {
            int row = wid * 16 + rr;
            int r = row0 + row;
            float4 v = *(float4*)&Cs[row * PC + lane * 4];
            int ab = head * 128 + lane * 4;
            float sacc = v.x * s_as[ab]     + v.y * s_as[ab + 1]
                       + v.z * s_as[ab + 2] + v.w * s_as[ab + 3];
            float dacc = v.x * s_ad[ab]     + v.y * s_ad[ab + 1]
                       + v.z * s_ad[ab + 2] + v.w * s_ad[ab + 3];
            sacc = warpSum(sacc); dacc = warpSum(dacc);
            if (r < NN) {
                __half2 p0 = __floats2half2_rn(v.x, v.y);
                __half2 p1 = __floats2half2_rn(v.z, v.w);
                uint2 pk = make_uint2(*(uint32_t*)&p0, *(uint32_t*)&p1);
                *(uint2*)(Hout + (size_t)r * Hstr + head * 128 + lane * 4) = pk;
                if (lane == 0) {
                    outS[(size_t)r * aStr + head] = sacc;
                    outD[(size_t)r * aStr + head] = dacc;
                }
            }
        }
    }
}

// ---------------- single-pass GAT aggregation (no max-shift; softmax invariant) ----------------
__global__ void k_agg1(const float* __restrict__ b1) {
    int w = (blockIdx.x * blockDim.x + threadIdx.x) >> 5;
    int lane = threadIdx.x & 31;
    if (w >= NN) return;
    int beg = g_rowstart[w], end = g_rowstart[w + 1];

    // lanes 0-15 -> head 0 channels [8l,8l+8); lanes 16-31 -> head 1
    const int hd = lane >> 4;
    const float ad = g_a1d[2 * w + hd];

    float z = 0.f;
    float acc[8] = {0, 0, 0, 0, 0, 0, 0, 0};
    #pragma unroll 2
    for (int j = beg; j < end; j++) {
        int s = g_srcs[j];
        float e = __expf(lrelu(g_a1s[2 * s + hd] + ad));
        z += e;
        uint4 pk = *(const uint4*)(g_h1h + (size_t)s * C1 + lane * 8);
        const uint32_t u[4] = {pk.x, pk.y, pk.z, pk.w};
        #pragma unroll
        for (int q = 0; q < 4; q++) {
            float2 f = __half22float2(*(const __half2*)&u[q]);
            acc[2 * q]     += e * f.x;
            acc[2 * q + 1] += e * f.y;
        }
    }
    float iz = 1.0f / (z + EPS);
    float* o = g_out1 + (size_t)w * C1 + lane * 8;
    const float* bb = b1 + lane * 8;
    float4 o0 = {elu1(acc[0] * iz + bb[0]), elu1(acc[1] * iz + bb[1]),
                 elu1(acc[2] * iz + bb[2]), elu1(acc[3] * iz + bb[3])};
    float4 o1 = {elu1(acc[4] * iz + bb[4]), elu1(acc[5] * iz + bb[5]),
                 elu1(acc[6] * iz + bb[6]), elu1(acc[7] * iz + bb[7])};
    ((float4*)o)[0] = o0; ((float4*)o)[1] = o1;
}

// ---------------- layer-2 single-pass aggregation fused with MLP head ----------------
__global__ void k_agg2mlp(const float* __restrict__ b2,
                          const float* __restrict__ fc1w, const float* __restrict__ fc1b,
                          const float* __restrict__ fc2w, const float* __restrict__ fc2b,
                          float* __restrict__ out) {
    __shared__ float w1s[CH * FCH];
    __shared__ float w2s[FCH], b1s[FCH], b2s[CH];
    int tid = threadIdx.x;
    for (int i = tid; i < CH * FCH; i += blockDim.x) w1s[i] = fc1w[i];
    if (tid < FCH) { w2s[tid] = fc2w[tid]; b1s[tid] = fc1b[tid]; }
    if (tid < CH)  b2s[tid] = b2[tid];
    __syncthreads();

    int w = (blockIdx.x * blockDim.x + tid) >> 5;
    int lane = tid & 31;
    if (w >= NN) return;
    int beg = g_rowstart[w], end = g_rowstart[w + 1];
    float ad = g_a2d[w];

    float z = 0.f;
    float acc[4] = {0, 0, 0, 0};
    #pragma unroll 2
    for (int j = beg; j < end; j++) {
        int s = g_srcs[j];
        float e = __expf(lrelu(g_a2s[s] + ad));
        z += e;
        uint2 pk = *(const uint2*)(g_h2h + (size_t)s * CH + lane * 4);
        float2 f0 = __half22float2(*(const __half2*)&pk.x);
        float2 f1 = __half22float2(*(const __half2*)&pk.y);
        acc[0] += e * f0.x; acc[1] += e * f0.y;
        acc[2] += e * f1.x; acc[3] += e * f1.y;
    }
    float iz = 1.0f / (z + EPS);

    // out2 row stays in registers: lane holds channels [4*lane, 4*lane+4)
    float hvv[4];
    #pragma unroll
    for (int q = 0; q < 4; q++) hvv[q] = elu1(acc[q] * iz + b2s[lane * 4 + q]);

    // MLP: 128 -> 64 (relu) -> 1
    float acc0 = 0.f, acc1 = 0.f;
    #pragma unroll
    for (int k0 = 0; k0 < CH; k0 += 4) {
        int srcl = k0 >> 2;
        #pragma unroll
        for (int kk = 0; kk < 4; kk++) {
            float hk = __shfl_sync(0xffffffffu, hvv[kk], srcl);
            acc0 += hk * w1s[(k0 + kk) * FCH + lane];
            acc1 += hk * w1s[(k0 + kk) * FCH + lane + 32];
        }
    }
    float h0 = fmaxf(acc0 + b1s[lane], 0.f);
    float h1 = fmaxf(acc1 + b1s[lane + 32], 0.f);
    float p = h0 * w2s[lane] + h1 * w2s[lane + 32];
    p = warpSum(p);
    if (lane == 0) out[w] = p + fc2b[0];
}

// ---------------- launch ----------------
extern "C" void kernel_launch(void* const* d_in, const int* in_sizes, int n_in,
                              void* d_out, int out_size) {
    const float* x    = (const float*)d_in[0];
    const int*   eraw = (const int*)d_in[1];
    const float* W1   = (const float*)d_in[2];
    const float* as1  = (const float*)d_in[3];
    const float* ad1  = (const float*)d_in[4];
    const float* b1   = (const float*)d_in[5];
    const float* W2   = (const float*)d_in[6];
    const float* as2  = (const float*)d_in[7];
    const float* ad2  = (const float*)d_in[8];
    const float* b2   = (const float*)d_in[9];
    const float* fc1w = (const float*)d_in[10];
    const float* fc1b = (const float*)d_in[11];
    const float* fc2w = (const float*)d_in[12];
    const float* fc2b = (const float*)d_in[13];
    float* out = (float*)d_out;

    cudaFuncSetAttribute(k_gemm_wmma<1>, cudaFuncAttributeMaxDynamicSharedMemorySize, SMEM_TOT);
    cudaFuncSetAttribute(k_gemm_wmma<2>, cudaFuncAttributeMaxDynamicSharedMemorySize, SMEM_TOT);

    k_init<<<(NN + 255) / 256, 256>>>(eraw);                   // #1
    k_count<<<(ET + 255) / 256, 256>>>(eraw);                  // #2
    k_scanA<<<49, 1024>>>();                                   // #3
    k_gemm_wmma<1><<<391, 256, SMEM_TOT>>>(x, W1, as1, ad1);   // #4 -> ncu window
    k_scanC<<<49, 1024>>>();                                   // #5
    k_fill<<<(ET + 255) / 256, 256>>>(eraw);                   // #6
    k_agg1<<<(NN + 7) / 8, 256>>>(b1);                         // #7

    k_gemm_wmma<2><<<391, 256, SMEM_TOT>>>(x, W2, as2, ad2);   // #8
    k_agg2mlp<<<(NN + 7) / 8, 256>>>(b2, fc1w, fc1b, fc2w, fc2b, out);  // #9
}

// round 9
// speedup vs baseline: 2.1782x; 1.0528x over previous
#include <cuda_runtime.h>
#include <cuda_fp16.h>
#include <mma.h>
#include <math.h>
#include <cstdint>

using namespace nvcuda;

#define NN 50000
#define NE 800000
#define ET (NE + NN)
#define C1 256
#define CH 128
#define FCH 64
#define NEG_SLOPE 0.2f
#define EPS 1e-16f

// ---------------- device scratch ----------------
__device__ int   g_is64;
__device__ int   g_deg[NN];
__device__ int   g_dinc[NN];
__device__ int   g_bsum[64];
__device__ int   g_rowstart[NN + 1];
__device__ int   g_cursor[NN];
__device__ int   g_srcs[ET];
__device__ __half g_h1h[(size_t)NN * C1];   // fp16 h1 (gather-only)
__device__ __half g_h2h[(size_t)NN * CH];   // fp16 h2 (gather-only)
__device__ __half g_o1h[(size_t)NN * C1];   // fp16 out1 (feeds GEMM2 only)
__device__ float g_a1s[NN * 2], g_a1d[NN * 2];
__device__ float g_a2s[NN],     g_a2d[NN];

// ---------------- helpers ----------------
__device__ __forceinline__ float warpSum(float v) {
    #pragma unroll
    for (int o = 16; o; o >>= 1) v += __shfl_xor_sync(0xffffffffu, v, o);
    return v;
}
__device__ __forceinline__ float lrelu(float x) { return x > 0.f ? x : NEG_SLOPE * x; }
__device__ __forceinline__ float elu1(float x)  { return x > 0.f ? x : (__expf(x) - 1.0f); }
__device__ __forceinline__ uint32_t pk2(float a, float b) {
    __half2 h = __floats2half2_rn(a, b);
    return *(uint32_t*)&h;
}

// ---------------- init: zero degrees + edge width detect ----------------
__global__ void k_init(const int* __restrict__ raw) {
    int t = blockIdx.x * blockDim.x + threadIdx.x;
    if (t < NN) g_deg[t] = 0;
    if (t == 0) {
        int ok = 1;
        #pragma unroll
        for (int i = 0; i < 64; i++) ok &= (raw[2 * i + 1] == 0);
        g_is64 = ok;
    }
}

// ---------------- CSR build ----------------
__global__ void k_count(const int* __restrict__ raw) {
    int t = blockIdx.x * blockDim.x + threadIdx.x;
    if (t < ET) {
        int d;
        if (t < NE) d = g_is64 ? raw[2 * (NE + t)] : raw[NE + t];
        else        d = t - NE;
        atomicAdd(&g_deg[d], 1);
    }
}
__global__ void k_scanA() {
    __shared__ int sh[1024];
    int t = threadIdx.x;
    int i = blockIdx.x * 1024 + t;
    int v = (i < NN) ? g_deg[i] : 0;
    sh[t] = v;
    __syncthreads();
    for (int off = 1; off < 1024; off <<= 1) {
        int x = (t >= off) ? sh[t - off] : 0;
        __syncthreads();
        sh[t] += x;
        __syncthreads();
    }
    if (i < NN) g_dinc[i] = sh[t];
    if (t == 1023) g_bsum[blockIdx.x] = sh[1023];
}
__global__ void k_scanC() {   // each block redundantly scans the 49 block sums
    __shared__ int s[64];
    int t = threadIdx.x;
    if (t < 64) s[t] = (t < 49) ? g_bsum[t] : 0;
    __syncthreads();
    for (int off = 1; off < 64; off <<= 1) {
        int x = (t >= off && t < 64) ? s[t - off] : 0;
        __syncthreads();
        if (t < 64) s[t] += x;
        __syncthreads();
    }
    int boff = (blockIdx.x == 0) ? 0 : s[blockIdx.x - 1];
    int i = blockIdx.x * 1024 + t;
    if (i < NN) {
        int inc = g_dinc[i] + boff;
        g_rowstart[i + 1] = inc;
        g_cursor[i] = inc - g_deg[i];
    }
    if (i == 0) g_rowstart[0] = 0;
}
__global__ void k_fill(const int* __restrict__ raw) {
    int t = blockIdx.x * blockDim.x + threadIdx.x;
    if (t < ET) {
        int s, d;
        if (t < NE) {
            if (g_is64) { s = raw[2 * t]; d = raw[2 * (NE + t)]; }
            else        { s = raw[t];     d = raw[NE + t]; }
        } else { s = d = t - NE; }
        int p = atomicAdd(&g_cursor[d], 1);
        g_srcs[p] = s;
    }
}

// ---------------- WMMA fp16 single-term GEMM with fused attention-dot epilogue ----------------
// MODE 1: h1 = x @ W1    (K=128, N=256: both head tiles in one CTA, A staged once)
// MODE 2: h2 = o1h @ W2  (K=256, N=128; A already fp16 -> copy staging)
#define PA 136   // fp16 pitch (conflict-free, 16B-aligned rows)
#define PC 132   // fp32 pitch for C staging
#define OFF_A 0
#define OFF_B 34816
#define SMEM_TOT 102400   // A (34816) + max(B 34816, C 67584)

template <int MODE>
__global__ __launch_bounds__(256, 2)
void k_gemm_wmma(const float* __restrict__ x, const float* __restrict__ W,
                 const float* __restrict__ attS, const float* __restrict__ attD) {
    extern __shared__ char dyn[];
    __shared__ float s_as[256], s_ad[256];

    constexpr int K      = (MODE == 1) ? 128 : 256;
    constexpr int NCHUNK = K / 128;
    constexpr int NHEADS = (MODE == 1) ? 2 : 1;
    constexpr int NCOLS  = (MODE == 1) ? 256 : 128;   // B width
    constexpr int Hstr   = (MODE == 1) ? C1 : CH;
    constexpr int aStr   = (MODE == 1) ? 2 : 1;
    __half* Hout    = (MODE == 1) ? g_h1h : g_h2h;
    float* outS     = (MODE == 1) ? g_a1s : g_a2s;
    float* outD     = (MODE == 1) ? g_a1d : g_a2d;

    const int tid = threadIdx.x, wid = tid >> 5, lane = tid & 31;
    const int row0 = blockIdx.x * 128;
    const int warp_m = wid >> 1, warp_n = wid & 1;

    __half* AH = (__half*)(dyn + OFF_A);
    __half* BH = (__half*)(dyn + OFF_B);

    if (tid < NHEADS * 128) {
        s_as[tid] = attS[tid];
        s_ad[tid] = attD[tid];
    }

    const int lr = tid >> 1, lh = tid & 1;      // loader: row / 64-col half
    const bool rok = (row0 + lr) < NN;

    for (int head = 0; head < NHEADS; head++) {
        wmma::fragment<wmma::accumulator, 16, 16, 16, float> acc[2][4];
        #pragma unroll
        for (int i = 0; i < 2; i++)
            #pragma unroll
            for (int j = 0; j < 4; j++) wmma::fill_fragment(acc[i][j], 0.f);

        #pragma unroll
        for (int c = 0; c < NCHUNK; c++) {
            if (head || c) __syncthreads();   // protect SMEM being re-staged
            if (head == 0) {
                uint4* dst = (uint4*)(AH + lr * PA + lh * 64);
                if (MODE == 1) {
                    // --- stage A chunk (fp32 -> fp16, 128-bit stores) ---
                    const float4* src = (const float4*)(x + (size_t)(row0 + lr) * K + c * 128 + lh * 64);
                    #pragma unroll
                    for (int i = 0; i < 8; i++) {
                        float4 a = rok ? src[2 * i]     : make_float4(0, 0, 0, 0);
                        float4 b = rok ? src[2 * i + 1] : make_float4(0, 0, 0, 0);
                        dst[i] = make_uint4(pk2(a.x, a.y), pk2(a.z, a.w),
                                            pk2(b.x, b.y), pk2(b.z, b.w));
                    }
                } else {
                    // --- stage A chunk (fp16 copy, 128-bit) ---
                    const uint4* src = (const uint4*)(g_o1h + (size_t)(row0 + lr) * K + c * 128 + lh * 64);
                    #pragma unroll
                    for (int i = 0; i < 8; i++)
                        dst[i] = rok ? src[i] : make_uint4(0, 0, 0, 0);
                }
            }
            {
                // --- stage B chunk for this head (fp32 -> fp16, 128-bit stores) ---
                const float4* src = (const float4*)(W + (size_t)(c * 128 + lr) * NCOLS + head * 128 + lh * 64);
                uint4* dst = (uint4*)(BH + lr * PA + lh * 64);
                #pragma unroll
                for (int i = 0; i < 8; i++) {
                    float4 a = src[2 * i];
                    float4 b = src[2 * i + 1];
                    dst[i] = make_uint4(pk2(a.x, a.y), pk2(a.z, a.w),
                                        pk2(b.x, b.y), pk2(b.z, b.w));
                }
            }
            __syncthreads();

            // --- MMA: single-term fp16 ---
            #pragma unroll
            for (int kk = 0; kk < 8; kk++) {
                wmma::fragment<wmma::matrix_a, 16, 16, 16, __half, wmma::row_major> af[2];
                wmma::fragment<wmma::matrix_b, 16, 16, 16, __half, wmma::row_major> bf[4];
                #pragma unroll
                for (int i = 0; i < 2; i++)
                    wmma::load_matrix_sync(af[i], AH + (warp_m * 32 + i * 16) * PA + kk * 16, PA);
                #pragma unroll
                for (int j = 0; j < 4; j++)
                    wmma::load_matrix_sync(bf[j], BH + (kk * 16) * PA + warp_n * 64 + j * 16, PA);
                #pragma unroll
                for (int i = 0; i < 2; i++)
                    #pragma unroll
                    for (int j = 0; j < 4; j++)
                        wmma::mma_sync(acc[i][j], af[i], bf[j], acc[i][j]);
            }
        }

        // --- epilogue: stage C in the (dead) B region, write fp16 h + attention dots ---
        __syncthreads();
        float* Cs = (float*)(dyn + OFF_B);
        #pragma unroll
        for (int i = 0; i < 2; i++)
            #pragma unroll
            for (int j = 0; j < 4; j++)
                wmma::store_matrix_sync(Cs + (warp_m * 32 + i * 16) * PC + warp_n * 64 + j * 16,
                                        acc[i][j], PC, wmma::mem_row_major);
        __syncthreads();

        #pragma unroll 4
        for (int rr = 0; rr < 16; rr++) {
            int row = wid * 16 + rr;
            int r = row0 + row;
            float4 v = *(float4*)&Cs[row * PC + lane * 4];
            int ab = head * 128 + lane * 4;
            float sacc = v.x * s_as[ab]     + v.y * s_as[ab + 1]
                       + v.z * s_as[ab + 2] + v.w * s_as[ab + 3];
            float dacc = v.x * s_ad[ab]     + v.y * s_ad[ab + 1]
                       + v.z * s_ad[ab + 2] + v.w * s_ad[ab + 3];
            sacc = warpSum(sacc); dacc = warpSum(dacc);
            if (r < NN) {
                uint2 pk = make_uint2(pk2(v.x, v.y), pk2(v.z, v.w));
                *(uint2*)(Hout + (size_t)r * Hstr + head * 128 + lane * 4) = pk;
                if (lane == 0) {
                    outS[(size_t)r * aStr + head] = sacc;
                    outD[(size_t)r * aStr + head] = dacc;
                }
            }
        }
    }
}

// ---------------- single-pass GAT aggregation (no max-shift; softmax invariant) ----------------
__global__ void k_agg1(const float* __restrict__ b1) {
    int w = (blockIdx.x * blockDim.x + threadIdx.x) >> 5;
    int lane = threadIdx.x & 31;
    if (w >= NN) return;
    int beg = g_rowstart[w], end = g_rowstart[w + 1];

    // lanes 0-15 -> head 0 channels [8l,8l+8); lanes 16-31 -> head 1
    const int hd = lane >> 4;
    const float ad = g_a1d[2 * w + hd];

    float z = 0.f;
    float acc[8] = {0, 0, 0, 0, 0, 0, 0, 0};
    #pragma unroll 2
    for (int j = beg; j < end; j++) {
        int s = g_srcs[j];
        float e = __expf(lrelu(g_a1s[2 * s + hd] + ad));
        z += e;
        uint4 pk = *(const uint4*)(g_h1h + (size_t)s * C1 + lane * 8);
        const uint32_t u[4] = {pk.x, pk.y, pk.z, pk.w};
        #pragma unroll
        for (int q = 0; q < 4; q++) {
            float2 f = __half22float2(*(const __half2*)&u[q]);
            acc[2 * q]     += e * f.x;
            acc[2 * q + 1] += e * f.y;
        }
    }
    float iz = 1.0f / (z + EPS);
    const float* bb = b1 + lane * 8;
    uint4 o;
    o.x = pk2(elu1(acc[0] * iz + bb[0]), elu1(acc[1] * iz + bb[1]));
    o.y = pk2(elu1(acc[2] * iz + bb[2]), elu1(acc[3] * iz + bb[3]));
    o.z = pk2(elu1(acc[4] * iz + bb[4]), elu1(acc[5] * iz + bb[5]));
    o.w = pk2(elu1(acc[6] * iz + bb[6]), elu1(acc[7] * iz + bb[7]));
    *(uint4*)(g_o1h + (size_t)w * C1 + lane * 8) = o;
}

// ---------------- layer-2 single-pass aggregation fused with MLP head ----------------
__global__ void k_agg2mlp(const float* __restrict__ b2,
                          const float* __restrict__ fc1w, const float* __restrict__ fc1b,
                          const float* __restrict__ fc2w, const float* __restrict__ fc2b,
                          float* __restrict__ out) {
    __shared__ float w1s[CH * FCH];
    __shared__ float w2s[FCH], b1s[FCH], b2s[CH];
    int tid = threadIdx.x;
    for (int i = tid; i < CH * FCH; i += blockDim.x) w1s[i] = fc1w[i];
    if (tid < FCH) { w2s[tid] = fc2w[tid]; b1s[tid] = fc1b[tid]; }
    if (tid < CH)  b2s[tid] = b2[tid];
    __syncthreads();

    int w = (blockIdx.x * blockDim.x + tid) >> 5;
    int lane = tid & 31;
    if (w >= NN) return;
    int beg = g_rowstart[w], end = g_rowstart[w + 1];
    float ad = g_a2d[w];

    float z = 0.f;
    float acc[4] = {0, 0, 0, 0};
    #pragma unroll 2
    for (int j = beg; j < end; j++) {
        int s = g_srcs[j];
        float e = __expf(lrelu(g_a2s[s] + ad));
        z += e;
        uint2 pk = *(const uint2*)(g_h2h + (size_t)s * CH + lane * 4);
        float2 f0 = __half22float2(*(const __half2*)&pk.x);
        float2 f1 = __half22float2(*(const __half2*)&pk.y);
        acc[0] += e * f0.x; acc[1] += e * f0.y;
        acc[2] += e * f1.x; acc[3] += e * f1.y;
    }
    float iz = 1.0f / (z + EPS);

    // out2 row stays in registers: lane holds channels [4*lane, 4*lane+4)
    float hvv[4];
    #pragma unroll
    for (int q = 0; q < 4; q++) hvv[q] = elu1(acc[q] * iz + b2s[lane * 4 + q]);

    // MLP: 128 -> 64 (relu) -> 1
    float acc0 = 0.f, acc1 = 0.f;
    #pragma unroll
    for (int k0 = 0; k0 < CH; k0 += 4) {
        int srcl = k0 >> 2;
        #pragma unroll
        for (int kk = 0; kk < 4; kk++) {
            float hk = __shfl_sync(0xffffffffu, hvv[kk], srcl);
            acc0 += hk * w1s[(k0 + kk) * FCH + lane];
            acc1 += hk * w1s[(k0 + kk) * FCH + lane + 32];
        }
    }
    float h0 = fmaxf(acc0 + b1s[lane], 0.f);
    float h1 = fmaxf(acc1 + b1s[lane + 32], 0.f);
    float p = h0 * w2s[lane] + h1 * w2s[lane + 32];
    p = warpSum(p);
    if (lane == 0) out[w] = p + fc2b[0];
}

// ---------------- launch ----------------
extern "C" void kernel_launch(void* const* d_in, const int* in_sizes, int n_in,
                              void* d_out, int out_size) {
    const float* x    = (const float*)d_in[0];
    const int*   eraw = (const int*)d_in[1];
    const float* W1   = (const float*)d_in[2];
    const float* as1  = (const float*)d_in[3];
    const float* ad1  = (const float*)d_in[4];
    const float* b1   = (const float*)d_in[5];
    const float* W2   = (const float*)d_in[6];
    const float* as2  = (const float*)d_in[7];
    const float* ad2  = (const float*)d_in[8];
    const float* b2   = (const float*)d_in[9];
    const float* fc1w = (const float*)d_in[10];
    const float* fc1b = (const float*)d_in[11];
    const float* fc2w = (const float*)d_in[12];
    const float* fc2b = (const float*)d_in[13];
    float* out = (float*)d_out;

    cudaFuncSetAttribute(k_gemm_wmma<1>, cudaFuncAttributeMaxDynamicSharedMemorySize, SMEM_TOT);
    cudaFuncSetAttribute(k_gemm_wmma<2>, cudaFuncAttributeMaxDynamicSharedMemorySize, SMEM_TOT);

    k_init<<<(NN + 255) / 256, 256>>>(eraw);                   // #1
    k_count<<<(ET + 255) / 256, 256>>>(eraw);                  // #2
    k_scanA<<<49, 1024>>>();                                   // #3
    k_gemm_wmma<1><<<391, 256, SMEM_TOT>>>(x, W1, as1, ad1);   // #4 -> ncu window
    k_scanC<<<49, 1024>>>();                                   // #5
    k_fill<<<(ET + 255) / 256, 256>>>(eraw);                   // #6
    k_agg1<<<(NN + 7) / 8, 256>>>(b1);                         // #7

    k_gemm_wmma<2><<<391, 256, SMEM_TOT>>>(x, W2, as2, ad2);   // #8
    k_agg2mlp<<<(NN + 7) / 8, 256>>>(b2, fc1w, fc1b, fc2w, fc2b, out);  // #9
}

// round 10
// speedup vs baseline: 2.2997x; 1.0558x over previous
#include <cuda_runtime.h>
#include <cuda_fp16.h>
#include <mma.h>
#include <math.h>
#include <cstdint>

using namespace nvcuda;

#define NN 50000
#define NE 800000
#define ET (NE + NN)
#define C1 256
#define CH 128
#define FCH 64
#define NEG_SLOPE 0.2f
#define EPS 1e-16f

// ---------------- device scratch ----------------
__device__ int   g_is64;
__device__ int   g_deg[NN];
__device__ int   g_dinc[NN];
__device__ int   g_bsum[64];
__device__ int   g_rowstart[NN + 1];
__device__ int   g_cursor[NN];
__device__ int   g_srcs[ET];
__device__ __half g_h1h[(size_t)NN * C1];   // fp16 h1 (gather-only)
__device__ __half g_h2h[(size_t)NN * CH];   // fp16 h2 (gather-only)
__device__ __half g_o1h[(size_t)NN * C1];   // fp16 out1 (feeds GEMM2 only)
__device__ float g_a1s[NN * 2], g_a1d[NN * 2];
__device__ float g_a2s[NN],     g_a2d[NN];
__device__ float g_u1s[256], g_u1d[256];    // W1 @ as1 / ad1 (head-major)
__device__ float g_u2s[256], g_u2d[256];    // W2 @ as2 / ad2

// ---------------- helpers ----------------
__device__ __forceinline__ float warpSum(float v) {
    #pragma unroll
    for (int o = 16; o; o >>= 1) v += __shfl_xor_sync(0xffffffffu, v, o);
    return v;
}
__device__ __forceinline__ float lrelu(float x) { return x > 0.f ? x : NEG_SLOPE * x; }
__device__ __forceinline__ float elu1(float x)  { return x > 0.f ? x : (__expf(x) - 1.0f); }
__device__ __forceinline__ uint32_t pk2(float a, float b) {
    __half2 h = __floats2half2_rn(a, b);
    return *(uint32_t*)&h;
}

// ---------------- init: zero degrees + edge width detect ----------------
__global__ void k_init(const int* __restrict__ raw) {
    int t = blockIdx.x * blockDim.x + threadIdx.x;
    if (t < NN) g_deg[t] = 0;
    if (t == 0) {
        int ok = 1;
        #pragma unroll
        for (int i = 0; i < 64; i++) ok &= (raw[2 * i + 1] == 0);
        g_is64 = ok;
    }
}

// ---------------- attention u-vectors: u = W @ att (warp per output) ----------------
__global__ void k_uvec(const float* __restrict__ W1, const float* __restrict__ as1,
                       const float* __restrict__ ad1,
                       const float* __restrict__ W2, const float* __restrict__ as2,
                       const float* __restrict__ ad2) {
    int gw = (blockIdx.x * blockDim.x + threadIdx.x) >> 5;   // 0..511
    int lane = threadIdx.x & 31;
    if (gw < 256) {
        int h = gw >> 7, k = gw & 127;
        float4 w = ((const float4*)(W1 + k * 256 + h * 128))[lane];
        float4 s = ((const float4*)(as1 + h * 128))[lane];
        float4 d = ((const float4*)(ad1 + h * 128))[lane];
        float ps = w.x * s.x + w.y * s.y + w.z * s.z + w.w * s.w;
        float pd = w.x * d.x + w.y * d.y + w.z * d.z + w.w * d.w;
        ps = warpSum(ps); pd = warpSum(pd);
        if (lane == 0) { g_u1s[gw] = ps; g_u1d[gw] = pd; }
    } else {
        int k = gw - 256;
        float4 w = ((const float4*)(W2 + k * 128))[lane];
        float4 s = ((const float4*)as2)[lane];
        float4 d = ((const float4*)ad2)[lane];
        float ps = w.x * s.x + w.y * s.y + w.z * s.z + w.w * s.w;
        float pd = w.x * d.x + w.y * d.y + w.z * d.z + w.w * d.w;
        ps = warpSum(ps); pd = warpSum(pd);
        if (lane == 0) { g_u2s[k] = ps; g_u2d[k] = pd; }
    }
}

// ---------------- CSR build ----------------
__global__ void k_count(const int* __restrict__ raw) {
    int t = blockIdx.x * blockDim.x + threadIdx.x;
    if (t < ET) {
        int d;
        if (t < NE) d = g_is64 ? raw[2 * (NE + t)] : raw[NE + t];
        else        d = t - NE;
        atomicAdd(&g_deg[d], 1);
    }
}
__global__ void k_scanA() {
    __shared__ int sh[1024];
    int t = threadIdx.x;
    int i = blockIdx.x * 1024 + t;
    int v = (i < NN) ? g_deg[i] : 0;
    sh[t] = v;
    __syncthreads();
    for (int off = 1; off < 1024; off <<= 1) {
        int x = (t >= off) ? sh[t - off] : 0;
        __syncthreads();
        sh[t] += x;
        __syncthreads();
    }
    if (i < NN) g_dinc[i] = sh[t];
    if (t == 1023) g_bsum[blockIdx.x] = sh[1023];
}
__global__ void k_scanC() {   // each block redundantly scans the 49 block sums
    __shared__ int s[64];
    int t = threadIdx.x;
    if (t < 64) s[t] = (t < 49) ? g_bsum[t] : 0;
    __syncthreads();
    for (int off = 1; off < 64; off <<= 1) {
        int x = (t >= off && t < 64) ? s[t - off] : 0;
        __syncthreads();
        if (t < 64) s[t] += x;
        __syncthreads();
    }
    int boff = (blockIdx.x == 0) ? 0 : s[blockIdx.x - 1];
    int i = blockIdx.x * 1024 + t;
    if (i < NN) {
        int inc = g_dinc[i] + boff;
        g_rowstart[i + 1] = inc;
        g_cursor[i] = inc - g_deg[i];
    }
    if (i == 0) g_rowstart[0] = 0;
}
__global__ void k_fill(const int* __restrict__ raw) {
    int t = blockIdx.x * blockDim.x + threadIdx.x;
    if (t < ET) {
        int s, d;
        if (t < NE) {
            if (g_is64) { s = raw[2 * t]; d = raw[2 * (NE + t)]; }
            else        { s = raw[t];     d = raw[NE + t]; }
        } else { s = d = t - NE; }
        int p = atomicAdd(&g_cursor[d], 1);
        g_srcs[p] = s;
    }
}

// ---------------- WMMA fp16 GEMM, fp16 C staging, dots via u-vectors ----------------
// MODE 1: h1 = x @ W1    (K=128, N=256: both head tiles, A staged once; a1s/a1d from A tile)
// MODE 2: h2 = o1h @ W2  (K=256, N=128; A already fp16 -> copy staging; no dots)
#define PA 136   // fp16 pitch (conflict-free, 16B-aligned rows)
#define OFF_A 0
#define OFF_B 34816
#define SMEM_TOT 69632    // A (34816) + max(B fp16 34816, C fp16 34816)

template <int MODE>
__global__ __launch_bounds__(256, 2)
void k_gemm_wmma(const float* __restrict__ x, const float* __restrict__ W) {
    extern __shared__ char dyn[];
    __shared__ float s_u[4][128];   // MODE1: u1s h0, u1d h0, u1s h1, u1d h1

    constexpr int K      = (MODE == 1) ? 128 : 256;
    constexpr int NCHUNK = K / 128;
    constexpr int NHEADS = (MODE == 1) ? 2 : 1;
    constexpr int NCOLS  = (MODE == 1) ? 256 : 128;   // B width
    constexpr int Hstr   = (MODE == 1) ? C1 : CH;
    __half* Hout    = (MODE == 1) ? g_h1h : g_h2h;

    const int tid = threadIdx.x, wid = tid >> 5, lane = tid & 31;
    const int row0 = blockIdx.x * 128;
    const int warp_m = wid >> 1, warp_n = wid & 1;

    __half* AH = (__half*)(dyn + OFF_A);
    __half* BH = (__half*)(dyn + OFF_B);

    if (MODE == 1 && tid < 128) {
        s_u[0][tid] = g_u1s[tid];
        s_u[1][tid] = g_u1d[tid];
        s_u[2][tid] = g_u1s[128 + tid];
        s_u[3][tid] = g_u1d[128 + tid];
    }

    const int lr = tid >> 1, lh = tid & 1;      // loader: row / 64-col half
    const bool rok = (row0 + lr) < NN;

    for (int head = 0; head < NHEADS; head++) {
        wmma::fragment<wmma::accumulator, 16, 16, 16, float> acc[2][4];
        #pragma unroll
        for (int i = 0; i < 2; i++)
            #pragma unroll
            for (int j = 0; j < 4; j++) wmma::fill_fragment(acc[i][j], 0.f);

        #pragma unroll
        for (int c = 0; c < NCHUNK; c++) {
            if (head || c) __syncthreads();   // protect SMEM being re-staged
            if (head == 0) {
                uint4* dst = (uint4*)(AH + lr * PA + lh * 64);
                if (MODE == 1) {
                    // --- stage A chunk (fp32 -> fp16, 128-bit stores) ---
                    const float4* src = (const float4*)(x + (size_t)(row0 + lr) * K + c * 128 + lh * 64);
                    #pragma unroll
                    for (int i = 0; i < 8; i++) {
                        float4 a = rok ? src[2 * i]     : make_float4(0, 0, 0, 0);
                        float4 b = rok ? src[2 * i + 1] : make_float4(0, 0, 0, 0);
                        dst[i] = make_uint4(pk2(a.x, a.y), pk2(a.z, a.w),
                                            pk2(b.x, b.y), pk2(b.z, b.w));
                    }
                } else {
                    // --- stage A chunk (fp16 copy, 128-bit) ---
                    const uint4* src = (const uint4*)(g_o1h + (size_t)(row0 + lr) * K + c * 128 + lh * 64);
                    #pragma unroll
                    for (int i = 0; i < 8; i++)
                        dst[i] = rok ? src[i] : make_uint4(0, 0, 0, 0);
                }
            }
            {
                // --- stage B chunk for this head (fp32 -> fp16, 128-bit stores) ---
                const float4* src = (const float4*)(W + (size_t)(c * 128 + lr) * NCOLS + head * 128 + lh * 64);
                uint4* dst = (uint4*)(BH + lr * PA + lh * 64);
                #pragma unroll
                for (int i = 0; i < 8; i++) {
                    float4 a = src[2 * i];
                    float4 b = src[2 * i + 1];
                    dst[i] = make_uint4(pk2(a.x, a.y), pk2(a.z, a.w),
                                        pk2(b.x, b.y), pk2(b.z, b.w));
                }
            }
            __syncthreads();

            // --- fused layer-1 attention dots from the staged fp16 A tile ---
            if (MODE == 1 && head == 0 && c == 0) {
                const uint4* arow = (const uint4*)(AH + lr * PA + lh * 64);
                float ps0 = 0.f, pd0 = 0.f, ps1 = 0.f, pd1 = 0.f;
                #pragma unroll
                for (int i = 0; i < 8; i++) {
                    uint4 pk = arow[i];
                    const uint32_t uu[4] = {pk.x, pk.y, pk.z, pk.w};
                    #pragma unroll
                    for (int q = 0; q < 4; q++) {
                        float2 f = __half22float2(*(const __half2*)&uu[q]);
                        int kk = lh * 64 + i * 8 + q * 2;
                        ps0 += f.x * s_u[0][kk] + f.y * s_u[0][kk + 1];
                        pd0 += f.x * s_u[1][kk] + f.y * s_u[1][kk + 1];
                        ps1 += f.x * s_u[2][kk] + f.y * s_u[2][kk + 1];
                        pd1 += f.x * s_u[3][kk] + f.y * s_u[3][kk + 1];
                    }
                }
                ps0 += __shfl_xor_sync(0xffffffffu, ps0, 1);
                pd0 += __shfl_xor_sync(0xffffffffu, pd0, 1);
                ps1 += __shfl_xor_sync(0xffffffffu, ps1, 1);
                pd1 += __shfl_xor_sync(0xffffffffu, pd1, 1);
                int r = row0 + lr;
                if (lh == 0 && r < NN) {
                    g_a1s[2 * r]     = ps0; g_a1d[2 * r]     = pd0;
                    g_a1s[2 * r + 1] = ps1; g_a1d[2 * r + 1] = pd1;
                }
            }

            // --- MMA: single-term fp16 ---
            #pragma unroll
            for (int kk = 0; kk < 8; kk++) {
                wmma::fragment<wmma::matrix_a, 16, 16, 16, __half, wmma::row_major> af[2];
                wmma::fragment<wmma::matrix_b, 16, 16, 16, __half, wmma::row_major> bf[4];
                #pragma unroll
                for (int i = 0; i < 2; i++)
                    wmma::load_matrix_sync(af[i], AH + (warp_m * 32 + i * 16) * PA + kk * 16, PA);
                #pragma unroll
                for (int j = 0; j < 4; j++)
                    wmma::load_matrix_sync(bf[j], BH + (kk * 16) * PA + warp_n * 64 + j * 16, PA);
                #pragma unroll
                for (int i = 0; i < 2; i++)
                    #pragma unroll
                    for (int j = 0; j < 4; j++)
                        wmma::mma_sync(acc[i][j], af[i], bf[j], acc[i][j]);
            }
        }

        // --- epilogue: convert fragments to fp16, stage in dead B region, copy out ---
        __syncthreads();
        __half* Ch = (__half*)(dyn + OFF_B);
        #pragma unroll
        for (int i = 0; i < 2; i++)
            #pragma unroll
            for (int j = 0; j < 4; j++) {
                wmma::fragment<wmma::accumulator, 16, 16, 16, __half> hf;
                #pragma unroll
                for (int e = 0; e < hf.num_elements; e++)
                    hf.x[e] = __float2half_rn(acc[i][j].x[e]);
                wmma::store_matrix_sync(Ch + (warp_m * 32 + i * 16) * PA + warp_n * 64 + j * 16,
                                        hf, PA, wmma::mem_row_major);
            }
        __syncthreads();

        #pragma unroll
        for (int rr = 0; rr < 16; rr += 2) {
            int row = wid * 16 + rr + (lane >> 4);
            int r = row0 + row;
            uint4 v = *(const uint4*)(Ch + row * PA + (lane & 15) * 8);
            if (r < NN)
                *(uint4*)(Hout + (size_t)r * Hstr + head * 128 + (lane & 15) * 8) = v;
        }
    }
}

// ---------------- single-pass GAT aggregation + fused layer-2 attention dots ----------------
__global__ void k_agg1(const float* __restrict__ b1) {
    __shared__ float s_u2s[256], s_u2d[256];
    int tid = threadIdx.x;
    s_u2s[tid] = g_u2s[tid];
    s_u2d[tid] = g_u2d[tid];
    __syncthreads();

    int w = (blockIdx.x * blockDim.x + tid) >> 5;
    int lane = tid & 31;
    if (w >= NN) return;
    int beg = g_rowstart[w], end = g_rowstart[w + 1];

    // lanes 0-15 -> head 0 channels [8l,8l+8); lanes 16-31 -> head 1
    const int hd = lane >> 4;
    const float ad = g_a1d[2 * w + hd];

    float z = 0.f;
    float acc[8] = {0, 0, 0, 0, 0, 0, 0, 0};
    #pragma unroll 2
    for (int j = beg; j < end; j++) {
        int s = g_srcs[j];
        float e = __expf(lrelu(g_a1s[2 * s + hd] + ad));
        z += e;
        uint4 pk = *(const uint4*)(g_h1h + (size_t)s * C1 + lane * 8);
        const uint32_t u[4] = {pk.x, pk.y, pk.z, pk.w};
        #pragma unroll
        for (int q = 0; q < 4; q++) {
            float2 f = __half22float2(*(const __half2*)&u[q]);
            acc[2 * q]     += e * f.x;
            acc[2 * q + 1] += e * f.y;
        }
    }
    float iz = 1.0f / (z + EPS);
    const float* bb = b1 + lane * 8;
    float ov[8];
    #pragma unroll
    for (int q = 0; q < 8; q++) ov[q] = elu1(acc[q] * iz + bb[q]);
    uint4 o;
    o.x = pk2(ov[0], ov[1]);
    o.y = pk2(ov[2], ov[3]);
    o.z = pk2(ov[4], ov[5]);
    o.w = pk2(ov[6], ov[7]);
    *(uint4*)(g_o1h + (size_t)w * C1 + lane * 8) = o;

    // layer-2 attention dots from the fp16-rounded out1 (matches GEMM2 operands)
    float ds = 0.f, dd = 0.f;
    const uint32_t* op = (const uint32_t*)&o;
    #pragma unroll
    for (int q = 0; q < 4; q++) {
        float2 f = __half22float2(*(const __half2*)&op[q]);
        int cc = lane * 8 + q * 2;
        ds += f.x * s_u2s[cc] + f.y * s_u2s[cc + 1];
        dd += f.x * s_u2d[cc] + f.y * s_u2d[cc + 1];
    }
    ds = warpSum(ds); dd = warpSum(dd);
    if (lane == 0) { g_a2s[w] = ds; g_a2d[w] = dd; }
}

// ---------------- layer-2 single-pass aggregation fused with MLP head ----------------
__global__ void k_agg2mlp(const float* __restrict__ b2,
                          const float* __restrict__ fc1w, const float* __restrict__ fc1b,
                          const float* __restrict__ fc2w, const float* __restrict__ fc2b,
                          float* __restrict__ out) {
    __shared__ float w1s[CH * FCH];
    __shared__ float w2s[FCH], b1s[FCH], b2s[CH];
    int tid = threadIdx.x;
    for (int i = tid; i < CH * FCH; i += blockDim.x) w1s[i] = fc1w[i];
    if (tid < FCH) { w2s[tid] = fc2w[tid]; b1s[tid] = fc1b[tid]; }
    if (tid < CH)  b2s[tid] = b2[tid];
    __syncthreads();

    int w = (blockIdx.x * blockDim.x + tid) >> 5;
    int lane = tid & 31;
    if (w >= NN) return;
    int beg = g_rowstart[w], end = g_rowstart[w + 1];
    float ad = g_a2d[w];

    float z = 0.f;
    float acc[4] = {0, 0, 0, 0};
    #pragma unroll 2
    for (int j = beg; j < end; j++) {
        int s = g_srcs[j];
        float e = __expf(lrelu(g_a2s[s] + ad));
        z += e;
        uint2 pk = *(const uint2*)(g_h2h + (size_t)s * CH + lane * 4);
        float2 f0 = __half22float2(*(const __half2*)&pk.x);
        float2 f1 = __half22float2(*(const __half2*)&pk.y);
        acc[0] += e * f0.x; acc[1] += e * f0.y;
        acc[2] += e * f1.x; acc[3] += e * f1.y;
    }
    float iz = 1.0f / (z + EPS);

    // out2 row stays in registers: lane holds channels [4*lane, 4*lane+4)
    float hvv[4];
    #pragma unroll
    for (int q = 0; q < 4; q++) hvv[q] = elu1(acc[q] * iz + b2s[lane * 4 + q]);

    // MLP: 128 -> 64 (relu) -> 1
    float acc0 = 0.f, acc1 = 0.f;
    #pragma unroll
    for (int k0 = 0; k0 < CH; k0 += 4) {
        int srcl = k0 >> 2;
        #pragma unroll
        for (int kk = 0; kk < 4; kk++) {
            float hk = __shfl_sync(0xffffffffu, hvv[kk], srcl);
            acc0 += hk * w1s[(k0 + kk) * FCH + lane];
            acc1 += hk * w1s[(k0 + kk) * FCH + lane + 32];
        }
    }
    float h0 = fmaxf(acc0 + b1s[lane], 0.f);
    float h1 = fmaxf(acc1 + b1s[lane + 32], 0.f);
    float p = h0 * w2s[lane] + h1 * w2s[lane + 32];
    p = warpSum(p);
    if (lane == 0) out[w] = p + fc2b[0];
}

// ---------------- launch ----------------
extern "C" void kernel_launch(void* const* d_in, const int* in_sizes, int n_in,
                              void* d_out, int out_size) {
    const float* x    = (const float*)d_in[0];
    const int*   eraw = (const int*)d_in[1];
    const float* W1   = (const float*)d_in[2];
    const float* as1  = (const float*)d_in[3];
    const float* ad1  = (const float*)d_in[4];
    const float* b1   = (const float*)d_in[5];
    const float* W2   = (const float*)d_in[6];
    const float* as2  = (const float*)d_in[7];
    const float* ad2  = (const float*)d_in[8];
    const float* b2   = (const float*)d_in[9];
    const float* fc1w = (const float*)d_in[10];
    const float* fc1b = (const float*)d_in[11];
    const float* fc2w = (const float*)d_in[12];
    const float* fc2b = (const float*)d_in[13];
    float* out = (float*)d_out;

    cudaFuncSetAttribute(k_gemm_wmma<1>, cudaFuncAttributeMaxDynamicSharedMemorySize, SMEM_TOT);
    cudaFuncSetAttribute(k_gemm_wmma<2>, cudaFuncAttributeMaxDynamicSharedMemorySize, SMEM_TOT);

    k_init<<<(NN + 255) / 256, 256>>>(eraw);                   // #1
    k_uvec<<<64, 256>>>(W1, as1, ad1, W2, as2, ad2);           // #2
    k_count<<<(ET + 255) / 256, 256>>>(eraw);                  // #3
    k_gemm_wmma<1><<<391, 256, SMEM_TOT>>>(x, W1);             // #4 -> ncu window
    k_scanA<<<49, 1024>>>();                                   // #5
    k_scanC<<<49, 1024>>>();                                   // #6
    k_fill<<<(ET + 255) / 256, 256>>>(eraw);                   // #7
    k_agg1<<<(NN + 7) / 8, 256>>>(b1);                         // #8

    k_gemm_wmma<2><<<391, 256, SMEM_TOT>>>(x, W2);             // #9
    k_agg2mlp<<<(NN + 7) / 8, 256>>>(b2, fc1w, fc1b, fc2w, fc2b, out);  // #10
}

// round 11
// speedup vs baseline: 2.4086x; 1.0474x over previous
#include <cuda_runtime.h>
#include <cuda_fp16.h>
#include <mma.h>
#include <math.h>
#include <cstdint>

using namespace nvcuda;

#define NN 50000
#define NE 800000
#define ET (NE + NN)
#define C1 256
#define CH 128
#define FCH 64
#define NEG_SLOPE 0.2f
#define EPS 1e-16f

// ---------------- device scratch ----------------
__device__ int   g_is64;
__device__ int   g_deg[NN];
__device__ int   g_dinc[NN];
__device__ int   g_bsum[64];
__device__ int   g_rowstart[NN + 1];
__device__ int   g_cursor[NN];
__device__ int   g_srcs[ET];
__device__ __half g_xh[(size_t)NN * CH];    // fp16 x
__device__ __half g_w1h[CH * C1];           // fp16 W1
__device__ __half g_w2h[C1 * CH];           // fp16 W2
__device__ __half g_h1h[(size_t)NN * C1];   // fp16 h1 (gather-only)
__device__ __half g_h2h[(size_t)NN * CH];   // fp16 h2 (gather-only)
__device__ __half g_o1h[(size_t)NN * C1];   // fp16 out1 (feeds GEMM2 only)
__device__ float g_a1s[NN * 2], g_a1d[NN * 2];
__device__ float g_a2s[NN],     g_a2d[NN];
__device__ float g_u1s[256], g_u1d[256];    // W1 @ as1 / ad1 (head-major)
__device__ float g_u2s[256], g_u2d[256];    // W2 @ as2 / ad2

// ---------------- helpers ----------------
__device__ __forceinline__ float warpSum(float v) {
    #pragma unroll
    for (int o = 16; o; o >>= 1) v += __shfl_xor_sync(0xffffffffu, v, o);
    return v;
}
__device__ __forceinline__ float lrelu(float x) { return x > 0.f ? x : NEG_SLOPE * x; }
__device__ __forceinline__ float elu1(float x)  { return x > 0.f ? x : (__expf(x) - 1.0f); }
__device__ __forceinline__ uint32_t pk2(float a, float b) {
    __half2 h = __floats2half2_rn(a, b);
    return *(uint32_t*)&h;
}

// ---------------- init: zero degrees + edge width detect ----------------
__global__ void k_init(const int* __restrict__ raw) {
    int t = blockIdx.x * blockDim.x + threadIdx.x;
    if (t < NN) g_deg[t] = 0;
    if (t == 0) {
        int ok = 1;
        #pragma unroll
        for (int i = 0; i < 64; i++) ok &= (raw[2 * i + 1] == 0);
        g_is64 = ok;
    }
}

// ---------------- operand pre-conversion to fp16 (8 floats per thread) ----------------
__global__ void k_prep(const float* __restrict__ x, const float* __restrict__ W1,
                       const float* __restrict__ W2) {
    const int NX  = NN * CH / 8;   // 800000
    const int NW1 = CH * C1 / 8;   // 4096
    const int NW2 = C1 * CH / 8;   // 4096
    int t = blockIdx.x * blockDim.x + threadIdx.x;
    if (t >= NX + NW1 + NW2) return;
    const float4* src; uint4* dst; int idx;
    if (t < NX)            { src = (const float4*)x;  dst = (uint4*)g_xh;  idx = t; }
    else if (t < NX + NW1) { src = (const float4*)W1; dst = (uint4*)g_w1h; idx = t - NX; }
    else                   { src = (const float4*)W2; dst = (uint4*)g_w2h; idx = t - NX - NW1; }
    float4 a = src[2 * idx], b = src[2 * idx + 1];
    dst[idx] = make_uint4(pk2(a.x, a.y), pk2(a.z, a.w), pk2(b.x, b.y), pk2(b.z, b.w));
}

// ---------------- attention u-vectors: u = W @ att (warp per output) ----------------
__global__ void k_uvec(const float* __restrict__ W1, const float* __restrict__ as1,
                       const float* __restrict__ ad1,
                       const float* __restrict__ W2, const float* __restrict__ as2,
                       const float* __restrict__ ad2) {
    int gw = (blockIdx.x * blockDim.x + threadIdx.x) >> 5;   // 0..511
    int lane = threadIdx.x & 31;
    if (gw < 256) {
        int h = gw >> 7, k = gw & 127;
        float4 w = ((const float4*)(W1 + k * 256 + h * 128))[lane];
        float4 s = ((const float4*)(as1 + h * 128))[lane];
        float4 d = ((const float4*)(ad1 + h * 128))[lane];
        float ps = w.x * s.x + w.y * s.y + w.z * s.z + w.w * s.w;
        float pd = w.x * d.x + w.y * d.y + w.z * d.z + w.w * d.w;
        ps = warpSum(ps); pd = warpSum(pd);
        if (lane == 0) { g_u1s[gw] = ps; g_u1d[gw] = pd; }
    } else {
        int k = gw - 256;
        float4 w = ((const float4*)(W2 + k * 128))[lane];
        float4 s = ((const float4*)as2)[lane];
        float4 d = ((const float4*)ad2)[lane];
        float ps = w.x * s.x + w.y * s.y + w.z * s.z + w.w * s.w;
        float pd = w.x * d.x + w.y * d.y + w.z * d.z + w.w * d.w;
        ps = warpSum(ps); pd = warpSum(pd);
        if (lane == 0) { g_u2s[k] = ps; g_u2d[k] = pd; }
    }
}

// ---------------- CSR build ----------------
__global__ void k_count(const int* __restrict__ raw) {
    int t = blockIdx.x * blockDim.x + threadIdx.x;
    if (t < ET) {
        int d;
        if (t < NE) d = g_is64 ? raw[2 * (NE + t)] : raw[NE + t];
        else        d = t - NE;
        atomicAdd(&g_deg[d], 1);
    }
}
__global__ void k_scanA() {
    __shared__ int sh[1024];
    int t = threadIdx.x;
    int i = blockIdx.x * 1024 + t;
    int v = (i < NN) ? g_deg[i] : 0;
    sh[t] = v;
    __syncthreads();
    for (int off = 1; off < 1024; off <<= 1) {
        int x = (t >= off) ? sh[t - off] : 0;
        __syncthreads();
        sh[t] += x;
        __syncthreads();
    }
    if (i < NN) g_dinc[i] = sh[t];
    if (t == 1023) g_bsum[blockIdx.x] = sh[1023];
}
__global__ void k_scanC() {   // each block redundantly scans the 49 block sums
    __shared__ int s[64];
    int t = threadIdx.x;
    if (t < 64) s[t] = (t < 49) ? g_bsum[t] : 0;
    __syncthreads();
    for (int off = 1; off < 64; off <<= 1) {
        int x = (t >= off && t < 64) ? s[t - off] : 0;
        __syncthreads();
        if (t < 64) s[t] += x;
        __syncthreads();
    }
    int boff = (blockIdx.x == 0) ? 0 : s[blockIdx.x - 1];
    int i = blockIdx.x * 1024 + t;
    if (i < NN) {
        int inc = g_dinc[i] + boff;
        g_rowstart[i + 1] = inc;
        g_cursor[i] = inc - g_deg[i];
    }
    if (i == 0) g_rowstart[0] = 0;
}
__global__ void k_fill(const int* __restrict__ raw) {
    int t = blockIdx.x * blockDim.x + threadIdx.x;
    if (t < ET) {
        int s, d;
        if (t < NE) {
            if (g_is64) { s = raw[2 * t]; d = raw[2 * (NE + t)]; }
            else        { s = raw[t];     d = raw[NE + t]; }
        } else { s = d = t - NE; }
        int p = atomicAdd(&g_cursor[d], 1);
        g_srcs[p] = s;
    }
}

// ---------------- WMMA fp16 GEMM (fp16 operands pre-staged in global) ----------------
// MODE 1: h1 = xh @ W1h   (K=128, N=256: both head tiles, A staged once; a1s/a1d from A tile)
// MODE 2: h2 = o1h @ W2h  (K=256, N=128; no dots)
#define PA 136   // fp16 pitch (conflict-free, 16B-aligned rows)
#define OFF_A 0
#define OFF_B 34816
#define SMEM_TOT 69632    // A (34816) + max(B fp16 34816, C fp16 34816)

template <int MODE>
__global__ __launch_bounds__(256, 2)
void k_gemm_wmma() {
    extern __shared__ char dyn[];
    __shared__ float s_u[4][128];   // MODE1: u1s h0, u1d h0, u1s h1, u1d h1

    constexpr int K      = (MODE == 1) ? 128 : 256;
    constexpr int NCHUNK = K / 128;
    constexpr int NHEADS = (MODE == 1) ? 2 : 1;
    constexpr int NCOLS  = (MODE == 1) ? 256 : 128;   // B width
    constexpr int Hstr   = (MODE == 1) ? C1 : CH;
    const __half* Asrc = (MODE == 1) ? g_xh : g_o1h;
    const __half* Bsrc = (MODE == 1) ? g_w1h : g_w2h;
    __half* Hout    = (MODE == 1) ? g_h1h : g_h2h;

    const int tid = threadIdx.x, wid = tid >> 5, lane = tid & 31;
    const int row0 = blockIdx.x * 128;
    const int warp_m = wid >> 1, warp_n = wid & 1;

    __half* AH = (__half*)(dyn + OFF_A);
    __half* BH = (__half*)(dyn + OFF_B);

    if (MODE == 1 && tid < 128) {
        s_u[0][tid] = g_u1s[tid];
        s_u[1][tid] = g_u1d[tid];
        s_u[2][tid] = g_u1s[128 + tid];
        s_u[3][tid] = g_u1d[128 + tid];
    }

    const int lr = tid >> 1, lh = tid & 1;      // loader: row / 64-col half
    const bool rok = (row0 + lr) < NN;

    for (int head = 0; head < NHEADS; head++) {
        wmma::fragment<wmma::accumulator, 16, 16, 16, float> acc[2][4];
        #pragma unroll
        for (int i = 0; i < 2; i++)
            #pragma unroll
            for (int j = 0; j < 4; j++) wmma::fill_fragment(acc[i][j], 0.f);

        #pragma unroll
        for (int c = 0; c < NCHUNK; c++) {
            if (head || c) __syncthreads();   // protect SMEM being re-staged
            if (head == 0) {
                // --- stage A chunk (fp16 copy, 128-bit) ---
                const uint4* src = (const uint4*)(Asrc + (size_t)(row0 + lr) * K + c * 128 + lh * 64);
                uint4* dst = (uint4*)(AH + lr * PA + lh * 64);
                #pragma unroll
                for (int i = 0; i < 8; i++)
                    dst[i] = rok ? src[i] : make_uint4(0, 0, 0, 0);
            }
            {
                // --- stage B chunk for this head (fp16 copy, 128-bit) ---
                const uint4* src = (const uint4*)(Bsrc + (size_t)(c * 128 + lr) * NCOLS + head * 128 + lh * 64);
                uint4* dst = (uint4*)(BH + lr * PA + lh * 64);
                #pragma unroll
                for (int i = 0; i < 8; i++)
                    dst[i] = src[i];
            }
            __syncthreads();

            // --- fused layer-1 attention dots from the staged fp16 A tile ---
            if (MODE == 1 && head == 0 && c == 0) {
                const uint4* arow = (const uint4*)(AH + lr * PA + lh * 64);
                float ps0 = 0.f, pd0 = 0.f, ps1 = 0.f, pd1 = 0.f;
                #pragma unroll
                for (int i = 0; i < 8; i++) {
                    uint4 pk = arow[i];
                    const uint32_t uu[4] = {pk.x, pk.y, pk.z, pk.w};
                    #pragma unroll
                    for (int q = 0; q < 4; q++) {
                        float2 f = __half22float2(*(const __half2*)&uu[q]);
                        int kk = lh * 64 + i * 8 + q * 2;
                        ps0 += f.x * s_u[0][kk] + f.y * s_u[0][kk + 1];
                        pd0 += f.x * s_u[1][kk] + f.y * s_u[1][kk + 1];
                        ps1 += f.x * s_u[2][kk] + f.y * s_u[2][kk + 1];
                        pd1 += f.x * s_u[3][kk] + f.y * s_u[3][kk + 1];
                    }
                }
                ps0 += __shfl_xor_sync(0xffffffffu, ps0, 1);
                pd0 += __shfl_xor_sync(0xffffffffu, pd0, 1);
                ps1 += __shfl_xor_sync(0xffffffffu, ps1, 1);
                pd1 += __shfl_xor_sync(0xffffffffu, pd1, 1);
                int r = row0 + lr;
                if (lh == 0 && r < NN) {
                    g_a1s[2 * r]     = ps0; g_a1d[2 * r]     = pd0;
                    g_a1s[2 * r + 1] = ps1; g_a1d[2 * r + 1] = pd1;
                }
            }

            // --- MMA: single-term fp16 ---
            #pragma unroll
            for (int kk = 0; kk < 8; kk++) {
                wmma::fragment<wmma::matrix_a, 16, 16, 16, __half, wmma::row_major> af[2];
                wmma::fragment<wmma::matrix_b, 16, 16, 16, __half, wmma::row_major> bf[4];
                #pragma unroll
                for (int i = 0; i < 2; i++)
                    wmma::load_matrix_sync(af[i], AH + (warp_m * 32 + i * 16) * PA + kk * 16, PA);
                #pragma unroll
                for (int j = 0; j < 4; j++)
                    wmma::load_matrix_sync(bf[j], BH + (kk * 16) * PA + warp_n * 64 + j * 16, PA);
                #pragma unroll
                for (int i = 0; i < 2; i++)
                    #pragma unroll
                    for (int j = 0; j < 4; j++)
                        wmma::mma_sync(acc[i][j], af[i], bf[j], acc[i][j]);
            }
        }

        // --- epilogue: convert fragments to fp16, stage in dead B region, copy out ---
        __syncthreads();
        __half* Ch = (__half*)(dyn + OFF_B);
        #pragma unroll
        for (int i = 0; i < 2; i++)
            #pragma unroll
            for (int j = 0; j < 4; j++) {
                wmma::fragment<wmma::accumulator, 16, 16, 16, __half> hf;
                #pragma unroll
                for (int e = 0; e < hf.num_elements; e++)
                    hf.x[e] = __float2half_rn(acc[i][j].x[e]);
                wmma::store_matrix_sync(Ch + (warp_m * 32 + i * 16) * PA + warp_n * 64 + j * 16,
                                        hf, PA, wmma::mem_row_major);
            }
        __syncthreads();

        #pragma unroll
        for (int rr = 0; rr < 16; rr += 2) {
            int row = wid * 16 + rr + (lane >> 4);
            int r = row0 + row;
            uint4 v = *(const uint4*)(Ch + row * PA + (lane & 15) * 8);
            if (r < NN)
                *(uint4*)(Hout + (size_t)r * Hstr + head * 128 + (lane & 15) * 8) = v;
        }
    }
}

// ---------------- single-pass GAT aggregation + fused layer-2 attention dots ----------------
__global__ void k_agg1(const float* __restrict__ b1) {
    __shared__ float s_u2s[256], s_u2d[256];
    int tid = threadIdx.x;
    s_u2s[tid] = g_u2s[tid];
    s_u2d[tid] = g_u2d[tid];
    __syncthreads();

    int w = (blockIdx.x * blockDim.x + tid) >> 5;
    int lane = tid & 31;
    if (w >= NN) return;
    int beg = g_rowstart[w], end = g_rowstart[w + 1];

    // lanes 0-15 -> head 0 channels [8l,8l+8); lanes 16-31 -> head 1
    const int hd = lane >> 4;
    const float ad = g_a1d[2 * w + hd];

    float z = 0.f;
    float acc[8] = {0, 0, 0, 0, 0, 0, 0, 0};
    #pragma unroll 2
    for (int j = beg; j < end; j++) {
        int s = g_srcs[j];
        float e = __expf(lrelu(g_a1s[2 * s + hd] + ad));
        z += e;
        uint4 pk = *(const uint4*)(g_h1h + (size_t)s * C1 + lane * 8);
        const uint32_t u[4] = {pk.x, pk.y, pk.z, pk.w};
        #pragma unroll
        for (int q = 0; q < 4; q++) {
            float2 f = __half22float2(*(const __half2*)&u[q]);
            acc[2 * q]     += e * f.x;
            acc[2 * q + 1] += e * f.y;
        }
    }
    float iz = 1.0f / (z + EPS);
    const float* bb = b1 + lane * 8;
    float ov[8];
    #pragma unroll
    for (int q = 0; q < 8; q++) ov[q] = elu1(acc[q] * iz + bb[q]);
    uint4 o;
    o.x = pk2(ov[0], ov[1]);
    o.y = pk2(ov[2], ov[3]);
    o.z = pk2(ov[4], ov[5]);
    o.w = pk2(ov[6], ov[7]);
    *(uint4*)(g_o1h + (size_t)w * C1 + lane * 8) = o;

    // layer-2 attention dots from the fp16-rounded out1 (matches GEMM2 operands)
    float ds = 0.f, dd = 0.f;
    const uint32_t* op = (const uint32_t*)&o;
    #pragma unroll
    for (int q = 0; q < 4; q++) {
        float2 f = __half22float2(*(const __half2*)&op[q]);
        int cc = lane * 8 + q * 2;
        ds += f.x * s_u2s[cc] + f.y * s_u2s[cc + 1];
        dd += f.x * s_u2d[cc] + f.y * s_u2d[cc + 1];
    }
    ds = warpSum(ds); dd = warpSum(dd);
    if (lane == 0) { g_a2s[w] = ds; g_a2d[w] = dd; }
}

// ---------------- layer-2 single-pass aggregation fused with MLP head ----------------
__global__ void k_agg2mlp(const float* __restrict__ b2,
                          const float* __restrict__ fc1w, const float* __restrict__ fc1b,
                          const float* __restrict__ fc2w, const float* __restrict__ fc2b,
                          float* __restrict__ out) {
    __shared__ float w1s[CH * FCH];
    __shared__ float w2s[FCH], b1s[FCH], b2s[CH];
    int tid = threadIdx.x;
    for (int i = tid; i < CH * FCH; i += blockDim.x) w1s[i] = fc1w[i];
    if (tid < FCH) { w2s[tid] = fc2w[tid]; b1s[tid] = fc1b[tid]; }
    if (tid < CH)  b2s[tid] = b2[tid];
    __syncthreads();

    int w = (blockIdx.x * blockDim.x + tid) >> 5;
    int lane = tid & 31;
    if (w >= NN) return;
    int beg = g_rowstart[w], end = g_rowstart[w + 1];
    float ad = g_a2d[w];

    float z = 0.f;
    float acc[4] = {0, 0, 0, 0};
    #pragma unroll 2
    for (int j = beg; j < end; j++) {
        int s = g_srcs[j];
        float e = __expf(lrelu(g_a2s[s] + ad));
        z += e;
        uint2 pk = *(const uint2*)(g_h2h + (size_t)s * CH + lane * 4);
        float2 f0 = __half22float2(*(const __half2*)&pk.x);
        float2 f1 = __half22float2(*(const __half2*)&pk.y);
        acc[0] += e * f0.x; acc[1] += e * f0.y;
        acc[2] += e * f1.x; acc[3] += e * f1.y;
    }
    float iz = 1.0f / (z + EPS);

    // out2 row stays in registers: lane holds channels [4*lane, 4*lane+4)
    float hvv[4];
    #pragma unroll
    for (int q = 0; q < 4; q++) hvv[q] = elu1(acc[q] * iz + b2s[lane * 4 + q]);

    // MLP: 128 -> 64 (relu) -> 1
    float acc0 = 0.f, acc1 = 0.f;
    #pragma unroll
    for (int k0 = 0; k0 < CH; k0 += 4) {
        int srcl = k0 >> 2;
        #pragma unroll
        for (int kk = 0; kk < 4; kk++) {
            float hk = __shfl_sync(0xffffffffu, hvv[kk], srcl);
            acc0 += hk * w1s[(k0 + kk) * FCH + lane];
            acc1 += hk * w1s[(k0 + kk) * FCH + lane + 32];
        }
    }
    float h0 = fmaxf(acc0 + b1s[lane], 0.f);
    float h1 = fmaxf(acc1 + b1s[lane + 32], 0.f);
    float p = h0 * w2s[lane] + h1 * w2s[lane + 32];
    p = warpSum(p);
    if (lane == 0) out[w] = p + fc2b[0];
}

// ---------------- launch ----------------
extern "C" void kernel_launch(void* const* d_in, const int* in_sizes, int n_in,
                              void* d_out, int out_size) {
    const float* x    = (const float*)d_in[0];
    const int*   eraw = (const int*)d_in[1];
    const float* W1   = (const float*)d_in[2];
    const float* as1  = (const float*)d_in[3];
    const float* ad1  = (const float*)d_in[4];
    const float* b1   = (const float*)d_in[5];
    const float* W2   = (const float*)d_in[6];
    const float* as2  = (const float*)d_in[7];
    const float* ad2  = (const float*)d_in[8];
    const float* b2   = (const float*)d_in[9];
    const float* fc1w = (const float*)d_in[10];
    const float* fc1b = (const float*)d_in[11];
    const float* fc2w = (const float*)d_in[12];
    const float* fc2b = (const float*)d_in[13];
    float* out = (float*)d_out;

    cudaFuncSetAttribute(k_gemm_wmma<1>, cudaFuncAttributeMaxDynamicSharedMemorySize, SMEM_TOT);
    cudaFuncSetAttribute(k_gemm_wmma<2>, cudaFuncAttributeMaxDynamicSharedMemorySize, SMEM_TOT);

    const int NPREP = NN * CH / 8 + CH * C1 / 8 + C1 * CH / 8;

    k_init<<<(NN + 255) / 256, 256>>>(eraw);                   // #1
    k_prep<<<(NPREP + 255) / 256, 256>>>(x, W1, W2);           // #2
    k_uvec<<<64, 256>>>(W1, as1, ad1, W2, as2, ad2);           // #3
    k_gemm_wmma<1><<<391, 256, SMEM_TOT>>>();                  // #4 -> ncu window
    k_count<<<(ET + 255) / 256, 256>>>(eraw);                  // #5
    k_scanA<<<49, 1024>>>();                                   // #6
    k_scanC<<<49, 1024>>>();                                   // #7
    k_fill<<<(ET + 255) / 256, 256>>>(eraw);                   // #8
    k_agg1<<<(NN + 7) / 8, 256>>>(b1);                         // #9

    k_gemm_wmma<2><<<391, 256, SMEM_TOT>>>();                  // #10
    k_agg2mlp<<<(NN + 7) / 8, 256>>>(b2, fc1w, fc1b, fc2w, fc2b, out);  // #11
}

// round 12
// speedup vs baseline: 2.4089x; 1.0001x over previous
#include <cuda_runtime.h>
#include <cuda_fp16.h>
#include <mma.h>
#include <math.h>
#include <cstdint>

using namespace nvcuda;

#define NN 50000
#define NE 800000
#define ET (NE + NN)
#define C1 256
#define CH 128
#define FCH 64
#define NEG_SLOPE 0.2f
#define EPS 1e-16f

// ---------------- device scratch ----------------
__device__ int   g_is64;
__device__ int   g_deg[NN];
__device__ int   g_dinc[NN];
__device__ int   g_bsum[64];
__device__ int   g_rowstart[NN + 1];
__device__ int   g_cursor[NN];
__device__ int   g_srcs[ET];
__device__ int2  g_edge2[NE];               // packed (src,dst), written by k_count
__device__ __half g_xh[(size_t)NN * CH];    // fp16 x
__device__ __half g_w1h[CH * C1];           // fp16 W1
__device__ __half g_w2h[C1 * CH];           // fp16 W2
__device__ __half g_h1h[(size_t)NN * C1];   // fp16 h1 (gather-only)
__device__ __half g_h2h[(size_t)NN * CH];   // fp16 h2 (gather-only)
__device__ __half g_o1h[(size_t)NN * C1];   // fp16 out1 (feeds GEMM2 only)
__device__ float g_a1s[NN * 2], g_a1d[NN * 2];
__device__ float g_a2s[NN],     g_a2d[NN];
__device__ float g_u1s[256], g_u1d[256];    // W1 @ as1 / ad1 (head-major)
__device__ float g_u2s[256], g_u2d[256];    // W2 @ as2 / ad2

// ---------------- helpers ----------------
__device__ __forceinline__ float warpSum(float v) {
    #pragma unroll
    for (int o = 16; o; o >>= 1) v += __shfl_xor_sync(0xffffffffu, v, o);
    return v;
}
__device__ __forceinline__ int warpSumI(int v) {
    #pragma unroll
    for (int o = 16; o; o >>= 1) v += __shfl_xor_sync(0xffffffffu, v, o);
    return v;
}
__device__ __forceinline__ float lrelu(float x) { return x > 0.f ? x : NEG_SLOPE * x; }
__device__ __forceinline__ float elu1(float x)  { return x > 0.f ? x : (__expf(x) - 1.0f); }
__device__ __forceinline__ uint32_t pk2(float a, float b) {
    __half2 h = __floats2half2_rn(a, b);
    return *(uint32_t*)&h;
}

// ---------------- init: zero degrees + edge width detect ----------------
__global__ void k_init(const int* __restrict__ raw) {
    int t = blockIdx.x * blockDim.x + threadIdx.x;
    if (t < NN) g_deg[t] = 0;
    if (t == 0) {
        int ok = 1;
        #pragma unroll
        for (int i = 0; i < 64; i++) ok &= (raw[2 * i + 1] == 0);
        g_is64 = ok;
    }
}

// ---------------- operand pre-conversion to fp16 (8 floats per thread) ----------------
__global__ void k_prep(const float* __restrict__ x, const float* __restrict__ W1,
                       const float* __restrict__ W2) {
    const int NX  = NN * CH / 8;
    const int NW1 = CH * C1 / 8;
    const int NW2 = C1 * CH / 8;
    int t = blockIdx.x * blockDim.x + threadIdx.x;
    if (t >= NX + NW1 + NW2) return;
    const float4* src; uint4* dst; int idx;
    if (t < NX)            { src = (const float4*)x;  dst = (uint4*)g_xh;  idx = t; }
    else if (t < NX + NW1) { src = (const float4*)W1; dst = (uint4*)g_w1h; idx = t - NX; }
    else                   { src = (const float4*)W2; dst = (uint4*)g_w2h; idx = t - NX - NW1; }
    float4 a = src[2 * idx], b = src[2 * idx + 1];
    dst[idx] = make_uint4(pk2(a.x, a.y), pk2(a.z, a.w), pk2(b.x, b.y), pk2(b.z, b.w));
}

// ---------------- attention u-vectors: u = W @ att (warp per output) ----------------
__global__ void k_uvec(const float* __restrict__ W1, const float* __restrict__ as1,
                       const float* __restrict__ ad1,
                       const float* __restrict__ W2, const float* __restrict__ as2,
                       const float* __restrict__ ad2) {
    int gw = (blockIdx.x * blockDim.x + threadIdx.x) >> 5;   // 0..511
    int lane = threadIdx.x & 31;
    if (gw < 256) {
        int h = gw >> 7, k = gw & 127;
        float4 w = ((const float4*)(W1 + k * 256 + h * 128))[lane];
        float4 s = ((const float4*)(as1 + h * 128))[lane];
        float4 d = ((const float4*)(ad1 + h * 128))[lane];
        float ps = w.x * s.x + w.y * s.y + w.z * s.z + w.w * s.w;
        float pd = w.x * d.x + w.y * d.y + w.z * d.z + w.w * d.w;
        ps = warpSum(ps); pd = warpSum(pd);
        if (lane == 0) { g_u1s[gw] = ps; g_u1d[gw] = pd; }
    } else {
        int k = gw - 256;
        float4 w = ((const float4*)(W2 + k * 128))[lane];
        float4 s = ((const float4*)as2)[lane];
        float4 d = ((const float4*)ad2)[lane];
        float ps = w.x * s.x + w.y * s.y + w.z * s.z + w.w * s.w;
        float pd = w.x * d.x + w.y * d.y + w.z * d.z + w.w * d.w;
        ps = warpSum(ps); pd = warpSum(pd);
        if (lane == 0) { g_u2s[k] = ps; g_u2d[k] = pd; }
    }
}

// ---------------- CSR build ----------------
__global__ void k_count(const int* __restrict__ raw) {
    int t = blockIdx.x * blockDim.x + threadIdx.x;
    if (t < NE) {
        int s, d;
        if (g_is64) { s = raw[2 * t]; d = raw[2 * (NE + t)]; }
        else        { s = raw[t];     d = raw[NE + t]; }
        g_edge2[t] = make_int2(s, d);
        atomicAdd(&g_deg[d], 1);
    } else if (t < ET) {
        atomicAdd(&g_deg[t - NE], 1);
    }
}
__global__ void k_scanA() {   // shuffle scan: 2 syncs total
    __shared__ int wtot[32];
    int t = threadIdx.x, lane = t & 31, wd = t >> 5;
    int i = blockIdx.x * 1024 + t;
    int v = (i < NN) ? g_deg[i] : 0;
    int ws = v;
    #pragma unroll
    for (int off = 1; off < 32; off <<= 1) {
        int y = __shfl_up_sync(0xffffffffu, ws, off);
        if (lane >= off) ws += y;
    }
    if (lane == 31) wtot[wd] = ws;
    __syncthreads();
    if (wd == 0) {
        int tv = wtot[lane];
        #pragma unroll
        for (int off = 1; off < 32; off <<= 1) {
            int y = __shfl_up_sync(0xffffffffu, tv, off);
            if (lane >= off) tv += y;
        }
        wtot[lane] = tv;
        if (lane == 31) g_bsum[blockIdx.x] = tv;
    }
    __syncthreads();
    int woff = wd ? wtot[wd - 1] : 0;
    if (i < NN) g_dinc[i] = woff + ws;
}
__global__ void k_scanC() {   // per-block offset = reduction over preceding block sums
    __shared__ int s_boff;
    int t = threadIdx.x;
    if (t < 32) {
        int b = blockIdx.x;
        int v = (t < b) ? g_bsum[t] : 0;
        if (t + 32 < b) v += g_bsum[t + 32];
        v = warpSumI(v);
        if (t == 0) s_boff = v;
    }
    __syncthreads();
    int boff = s_boff;
    int i = blockIdx.x * 1024 + t;
    if (i < NN) {
        int inc = g_dinc[i] + boff;
        g_rowstart[i + 1] = inc;
        g_cursor[i] = inc - g_deg[i];
    }
    if (i == 0) g_rowstart[0] = 0;
}
__global__ void k_fill() {
    int t = blockIdx.x * blockDim.x + threadIdx.x;
    if (t < NE) {
        int2 e = g_edge2[t];
        int p = atomicAdd(&g_cursor[e.y], 1);
        g_srcs[p] = e.x;
    } else if (t < ET) {
        int n = t - NE;
        int p = atomicAdd(&g_cursor[n], 1);
        g_srcs[p] = n;
    }
}

// ---------------- WMMA fp16 GEMM (fp16 operands pre-staged in global) ----------------
#define PA 136
#define OFF_A 0
#define OFF_B 34816
#define SMEM_TOT 69632

template <int MODE>
__global__ __launch_bounds__(256, 2)
void k_gemm_wmma() {
    extern __shared__ char dyn[];
    __shared__ float s_u[4][128];

    constexpr int K      = (MODE == 1) ? 128 : 256;
    constexpr int NCHUNK = K / 128;
    constexpr int NHEADS = (MODE == 1) ? 2 : 1;
    constexpr int NCOLS  = (MODE == 1) ? 256 : 128;
    constexpr int Hstr   = (MODE == 1) ? C1 : CH;
    const __half* Asrc = (MODE == 1) ? g_xh : g_o1h;
    const __half* Bsrc = (MODE == 1) ? g_w1h : g_w2h;
    __half* Hout    = (MODE == 1) ? g_h1h : g_h2h;

    const int tid = threadIdx.x, wid = tid >> 5, lane = tid & 31;
    const int row0 = blockIdx.x * 128;
    const int warp_m = wid >> 1, warp_n = wid & 1;

    __half* AH = (__half*)(dyn + OFF_A);
    __half* BH = (__half*)(dyn + OFF_B);

    if (MODE == 1 && tid < 128) {
        s_u[0][tid] = g_u1s[tid];
        s_u[1][tid] = g_u1d[tid];
        s_u[2][tid] = g_u1s[128 + tid];
        s_u[3][tid] = g_u1d[128 + tid];
    }

    const int lr = tid >> 1, lh = tid & 1;
    const bool rok = (row0 + lr) < NN;

    for (int head = 0; head < NHEADS; head++) {
        wmma::fragment<wmma::accumulator, 16, 16, 16, float> acc[2][4];
        #pragma unroll
        for (int i = 0; i < 2; i++)
            #pragma unroll
            for (int j = 0; j < 4; j++) wmma::fill_fragment(acc[i][j], 0.f);

        #pragma unroll
        for (int c = 0; c < NCHUNK; c++) {
            if (head || c) __syncthreads();
            if (head == 0) {
                const uint4* src = (const uint4*)(Asrc + (size_t)(row0 + lr) * K + c * 128 + lh * 64);
                uint4* dst = (uint4*)(AH + lr * PA + lh * 64);
                #pragma unroll
                for (int i = 0; i < 8; i++)
                    dst[i] = rok ? src[i] : make_uint4(0, 0, 0, 0);
            }
            {
                const uint4* src = (const uint4*)(Bsrc + (size_t)(c * 128 + lr) * NCOLS + head * 128 + lh * 64);
                uint4* dst = (uint4*)(BH + lr * PA + lh * 64);
                #pragma unroll
                for (int i = 0; i < 8; i++)
                    dst[i] = src[i];
            }
            __syncthreads();

            // fused layer-1 attention dots from the staged fp16 A tile
            if (MODE == 1 && head == 0 && c == 0) {
                const uint4* arow = (const uint4*)(AH + lr * PA + lh * 64);
                float ps0 = 0.f, pd0 = 0.f, ps1 = 0.f, pd1 = 0.f;
                #pragma unroll
                for (int i = 0; i < 8; i++) {
                    uint4 pk = arow[i];
                    const uint32_t uu[4] = {pk.x, pk.y, pk.z, pk.w};
                    #pragma unroll
                    for (int q = 0; q < 4; q++) {
                        float2 f = __half22float2(*(const __half2*)&uu[q]);
                        int kk = lh * 64 + i * 8 + q * 2;
                        ps0 += f.x * s_u[0][kk] + f.y * s_u[0][kk + 1];
                        pd0 += f.x * s_u[1][kk] + f.y * s_u[1][kk + 1];
                        ps1 += f.x * s_u[2][kk] + f.y * s_u[2][kk + 1];
                        pd1 += f.x * s_u[3][kk] + f.y * s_u[3][kk + 1];
                    }
                }
                ps0 += __shfl_xor_sync(0xffffffffu, ps0, 1);
                pd0 += __shfl_xor_sync(0xffffffffu, pd0, 1);
                ps1 += __shfl_xor_sync(0xffffffffu, ps1, 1);
                pd1 += __shfl_xor_sync(0xffffffffu, pd1, 1);
                int r = row0 + lr;
                if (lh == 0 && r < NN) {
                    g_a1s[2 * r]     = ps0; g_a1d[2 * r]     = pd0;
                    g_a1s[2 * r + 1] = ps1; g_a1d[2 * r + 1] = pd1;
                }
            }

            #pragma unroll
            for (int kk = 0; kk < 8; kk++) {
                wmma::fragment<wmma::matrix_a, 16, 16, 16, __half, wmma::row_major> af[2];
                wmma::fragment<wmma::matrix_b, 16, 16, 16, __half, wmma::row_major> bf[4];
                #pragma unroll
                for (int i = 0; i < 2; i++)
                    wmma::load_matrix_sync(af[i], AH + (warp_m * 32 + i * 16) * PA + kk * 16, PA);
                #pragma unroll
                for (int j = 0; j < 4; j++)
                    wmma::load_matrix_sync(bf[j], BH + (kk * 16) * PA + warp_n * 64 + j * 16, PA);
                #pragma unroll
                for (int i = 0; i < 2; i++)
                    #pragma unroll
                    for (int j = 0; j < 4; j++)
                        wmma::mma_sync(acc[i][j], af[i], bf[j], acc[i][j]);
            }
        }

        __syncthreads();
        __half* Ch = (__half*)(dyn + OFF_B);
        #pragma unroll
        for (int i = 0; i < 2; i++)
            #pragma unroll
            for (int j = 0; j < 4; j++) {
                wmma::fragment<wmma::accumulator, 16, 16, 16, __half> hf;
                #pragma unroll
                for (int e = 0; e < hf.num_elements; e++)
                    hf.x[e] = __float2half_rn(acc[i][j].x[e]);
                wmma::store_matrix_sync(Ch + (warp_m * 32 + i * 16) * PA + warp_n * 64 + j * 16,
                                        hf, PA, wmma::mem_row_major);
            }
        __syncthreads();

        #pragma unroll
        for (int rr = 0; rr < 16; rr += 2) {
            int row = wid * 16 + rr + (lane >> 4);
            int r = row0 + row;
            uint4 v = *(const uint4*)(Ch + row * PA + (lane & 15) * 8);
            if (r < NN)
                *(uint4*)(Hout + (size_t)r * Hstr + head * 128 + (lane & 15) * 8) = v;
        }
    }
}

// ---------------- single-pass aggregation, 4-wide unrolled, + layer-2 dots ----------------
__global__ void k_agg1(const float* __restrict__ b1) {
    __shared__ float s_u2s[256], s_u2d[256];
    int tid = threadIdx.x;
    s_u2s[tid] = g_u2s[tid];
    s_u2d[tid] = g_u2d[tid];
    __syncthreads();

    int w = (blockIdx.x * blockDim.x + tid) >> 5;
    int lane = tid & 31;
    if (w >= NN) return;
    int beg = g_rowstart[w], end = g_rowstart[w + 1];

    const int hd = lane >> 4;
    const float ad = g_a1d[2 * w + hd];

    float z = 0.f;
    float acc[8] = {0, 0, 0, 0, 0, 0, 0, 0};
    int j = beg;
    for (; j + 4 <= end; j += 4) {
        int s0 = g_srcs[j],     s1 = g_srcs[j + 1];
        int s2 = g_srcs[j + 2], s3 = g_srcs[j + 3];
        float a0 = g_a1s[2 * s0 + hd], a1 = g_a1s[2 * s1 + hd];
        float a2 = g_a1s[2 * s2 + hd], a3 = g_a1s[2 * s3 + hd];
        uint4 p0 = *(const uint4*)(g_h1h + (size_t)s0 * C1 + lane * 8);
        uint4 p1 = *(const uint4*)(g_h1h + (size_t)s1 * C1 + lane * 8);
        uint4 p2 = *(const uint4*)(g_h1h + (size_t)s2 * C1 + lane * 8);
        uint4 p3 = *(const uint4*)(g_h1h + (size_t)s3 * C1 + lane * 8);
        float e0 = __expf(lrelu(a0 + ad)), e1 = __expf(lrelu(a1 + ad));
        float e2 = __expf(lrelu(a2 + ad)), e3 = __expf(lrelu(a3 + ad));
        z += (e0 + e1) + (e2 + e3);
        const uint32_t* u0 = (const uint32_t*)&p0;
        const uint32_t* u1 = (const uint32_t*)&p1;
        const uint32_t* u2 = (const uint32_t*)&p2;
        const uint32_t* u3 = (const uint32_t*)&p3;
        #pragma unroll
        for (int q = 0; q < 4; q++) {
            float2 f0 = __half22float2(*(const __half2*)&u0[q]);
            float2 f1 = __half22float2(*(const __half2*)&u1[q]);
            float2 f2 = __half22float2(*(const __half2*)&u2[q]);
            float2 f3 = __half22float2(*(const __half2*)&u3[q]);
            acc[2 * q]     += e0 * f0.x + e1 * f1.x + e2 * f2.x + e3 * f3.x;
            acc[2 * q + 1] += e0 * f0.y + e1 * f1.y + e2 * f2.y + e3 * f3.y;
        }
    }
    for (; j < end; j++) {
        int s = g_srcs[j];
        float e = __expf(lrelu(g_a1s[2 * s + hd] + ad));
        z += e;
        uint4 pk = *(const uint4*)(g_h1h + (size_t)s * C1 + lane * 8);
        const uint32_t* u = (const uint32_t*)&pk;
        #pragma unroll
        for (int q = 0; q < 4; q++) {
            float2 f = __half22float2(*(const __half2*)&u[q]);
            acc[2 * q]     += e * f.x;
            acc[2 * q + 1] += e * f.y;
        }
    }
    float iz = 1.0f / (z + EPS);
    const float* bb = b1 + lane * 8;
    float ov[8];
    #pragma unroll
    for (int q = 0; q < 8; q++) ov[q] = elu1(acc[q] * iz + bb[q]);
    uint4 o;
    o.x = pk2(ov[0], ov[1]);
    o.y = pk2(ov[2], ov[3]);
    o.z = pk2(ov[4], ov[5]);
    o.w = pk2(ov[6], ov[7]);
    *(uint4*)(g_o1h + (size_t)w * C1 + lane * 8) = o;

    // layer-2 attention dots from the fp16-rounded out1
    float ds = 0.f, dd = 0.f;
    const uint32_t* op = (const uint32_t*)&o;
    #pragma unroll
    for (int q = 0; q < 4; q++) {
        float2 f = __half22float2(*(const __half2*)&op[q]);
        int cc = lane * 8 + q * 2;
        ds += f.x * s_u2s[cc] + f.y * s_u2s[cc + 1];
        dd += f.x * s_u2d[cc] + f.y * s_u2d[cc + 1];
    }
    ds = warpSum(ds); dd = warpSum(dd);
    if (lane == 0) { g_a2s[w] = ds; g_a2d[w] = dd; }
}

// ---------------- layer-2 aggregation (4-wide) fused with MLP head ----------------
__global__ void k_agg2mlp(const float* __restrict__ b2,
                          const float* __restrict__ fc1w, const float* __restrict__ fc1b,
                          const float* __restrict__ fc2w, const float* __restrict__ fc2b,
                          float* __restrict__ out) {
    __shared__ float w1s[CH * FCH];
    __shared__ float w2s[FCH], b1s[FCH], b2s[CH];
    int tid = threadIdx.x;
    for (int i = tid; i < CH * FCH; i += blockDim.x) w1s[i] = fc1w[i];
    if (tid < FCH) { w2s[tid] = fc2w[tid]; b1s[tid] = fc1b[tid]; }
    if (tid < CH)  b2s[tid] = b2[tid];
    __syncthreads();

    int w = (blockIdx.x * blockDim.x + tid) >> 5;
    int lane = tid & 31;
    if (w >= NN) return;
    int beg = g_rowstart[w], end = g_rowstart[w + 1];
    float ad = g_a2d[w];

    float z = 0.f;
    float acc[4] = {0, 0, 0, 0};
    int j = beg;
    for (; j + 4 <= end; j += 4) {
        int s0 = g_srcs[j],     s1 = g_srcs[j + 1];
        int s2 = g_srcs[j + 2], s3 = g_srcs[j + 3];
        float a0 = g_a2s[s0], a1 = g_a2s[s1], a2 = g_a2s[s2], a3 = g_a2s[s3];
        uint2 p0 = *(const uint2*)(g_h2h + (size_t)s0 * CH + lane * 4);
        uint2 p1 = *(const uint2*)(g_h2h + (size_t)s1 * CH + lane * 4);
        uint2 p2 = *(const uint2*)(g_h2h + (size_t)s2 * CH + lane * 4);
        uint2 p3 = *(const uint2*)(g_h2h + (size_t)s3 * CH + lane * 4);
        float e0 = __expf(lrelu(a0 + ad)), e1 = __expf(lrelu(a1 + ad));
        float e2 = __expf(lrelu(a2 + ad)), e3 = __expf(lrelu(a3 + ad));
        z += (e0 + e1) + (e2 + e3);
        float2 f;
        f = __half22float2(*(const __half2*)&p0.x); acc[0] += e0 * f.x; acc[1] += e0 * f.y;
        f = __half22float2(*(const __half2*)&p0.y); acc[2] += e0 * f.x; acc[3] += e0 * f.y;
        f = __half22float2(*(const __half2*)&p1.x); acc[0] += e1 * f.x; acc[1] += e1 * f.y;
        f = __half22float2(*(const __half2*)&p1.y); acc[2] += e1 * f.x; acc[3] += e1 * f.y;
        f = __half22float2(*(const __half2*)&p2.x); acc[0] += e2 * f.x; acc[1] += e2 * f.y;
        f = __half22float2(*(const __half2*)&p2.y); acc[2] += e2 * f.x; acc[3] += e2 * f.y;
        f = __half22float2(*(const __half2*)&p3.x); acc[0] += e3 * f.x; acc[1] += e3 * f.y;
        f = __half22float2(*(const __half2*)&p3.y); acc[2] += e3 * f.x; acc[3] += e3 * f.y;
    }
    for (; j < end; j++) {
        int s = g_srcs[j];
        float e = __expf(lrelu(g_a2s[s] + ad));
        z += e;
        uint2 pk = *(const uint2*)(g_h2h + (size_t)s * CH + lane * 4);
        float2 f0 = __half22float2(*(const __half2*)&pk.x);
        float2 f1 = __half22float2(*(const __half2*)&pk.y);
        acc[0] += e * f0.x; acc[1] += e * f0.y;
        acc[2] += e * f1.x; acc[3] += e * f1.y;
    }
    float iz = 1.0f / (z + EPS);

    float hvv[4];
    #pragma unroll
    for (int q = 0; q < 4; q++) hvv[q] = elu1(acc[q] * iz + b2s[lane * 4 + q]);

    float acc0 = 0.f, acc1 = 0.f;
    #pragma unroll
    for (int k0 = 0; k0 < CH; k0 += 4) {
        int srcl = k0 >> 2;
        #pragma unroll
        for (int kk = 0; kk < 4; kk++) {
            float hk = __shfl_sync(0xffffffffu, hvv[kk], srcl);
            acc0 += hk * w1s[(k0 + kk) * FCH + lane];
            acc1 += hk * w1s[(k0 + kk) * FCH + lane + 32];
        }
    }
    float h0 = fmaxf(acc0 + b1s[lane], 0.f);
    float h1 = fmaxf(acc1 + b1s[lane + 32], 0.f);
    float p = h0 * w2s[lane] + h1 * w2s[lane + 32];
    p = warpSum(p);
    if (lane == 0) out[w] = p + fc2b[0];
}

// ---------------- launch ----------------
extern "C" void kernel_launch(void* const* d_in, const int* in_sizes, int n_in,
                              void* d_out, int out_size) {
    const float* x    = (const float*)d_in[0];
    const int*   eraw = (const int*)d_in[1];
    const float* W1   = (const float*)d_in[2];
    const float* as1  = (const float*)d_in[3];
    const float* ad1  = (const float*)d_in[4];
    const float* b1   = (const float*)d_in[5];
    const float* W2   = (const float*)d_in[6];
    const float* as2  = (const float*)d_in[7];
    const float* ad2  = (const float*)d_in[8];
    const float* b2   = (const float*)d_in[9];
    const float* fc1w = (const float*)d_in[10];
    const float* fc1b = (const float*)d_in[11];
    const float* fc2w = (const float*)d_in[12];
    const float* fc2b = (const float*)d_in[13];
    float* out = (float*)d_out;

    cudaFuncSetAttribute(k_gemm_wmma<1>, cudaFuncAttributeMaxDynamicSharedMemorySize, SMEM_TOT);
    cudaFuncSetAttribute(k_gemm_wmma<2>, cudaFuncAttributeMaxDynamicSharedMemorySize, SMEM_TOT);

    const int NPREP = NN * CH / 8 + CH * C1 / 8 + C1 * CH / 8;

    k_init<<<(NN + 255) / 256, 256>>>(eraw);                   // #1
    k_prep<<<(NPREP + 255) / 256, 256>>>(x, W1, W2);           // #2
    k_uvec<<<64, 256>>>(W1, as1, ad1, W2, as2, ad2);           // #3
    k_gemm_wmma<1><<<391, 256, SMEM_TOT>>>();                  // #4 -> ncu window
    k_count<<<(ET + 255) / 256, 256>>>(eraw);                  // #5
    k_scanA<<<49, 1024>>>();                                   // #6
    k_scanC<<<49, 1024>>>();                                   // #7
    k_fill<<<(ET + 255) / 256, 256>>>();                       // #8
    k_agg1<<<(NN + 7) / 8, 256>>>(b1);                         // #9

    k_gemm_wmma<2><<<391, 256, SMEM_TOT>>>();                  // #10
    k_agg2mlp<<<(NN + 7) / 8, 256>>>(b2, fc1w, fc1b, fc2w, fc2b, out);  // #11
}

// round 13
// speedup vs baseline: 2.5471x; 1.0573x over previous
#include <cuda_runtime.h>
#include <cuda_fp16.h>
#include <mma.h>
#include <math.h>
#include <cstdint>

using namespace nvcuda;

#define NN 50000
#define NE 800000
#define ET (NE + NN)
#define C1 256
#define CH 128
#define FCH 64
#define NEG_SLOPE 0.2f
#define EPS 1e-16f

// ---------------- device scratch ----------------
__device__ int   g_is64;
__device__ int   g_deg[NN];
__device__ int   g_dinc[NN];
__device__ int   g_bsum[64];
__device__ int   g_rowstart[NN + 1];
__device__ int   g_cursor[NN];
__device__ int   g_srcs[ET];
__device__ int2  g_edge2[NE];               // packed (src,dst), written by k_count
__device__ __half g_xh[(size_t)NN * CH];    // fp16 x
__device__ __half g_w1h[CH * C1];           // fp16 W1
__device__ __half g_w2h[C1 * CH];           // fp16 W2
__device__ __half g_h1h[(size_t)NN * C1];   // fp16 h1 (gather-only)
__device__ __half g_h2h[(size_t)NN * CH];   // fp16 h2 (gather-only)
__device__ __half g_o1h[(size_t)NN * C1];   // fp16 out1 (feeds GEMM2 only)
__device__ float g_a1s[NN * 2], g_a1d[NN * 2];
__device__ float g_a2s[NN],     g_a2d[NN];
__device__ float g_u1s[256], g_u1d[256];    // W1 @ as1 / ad1 (head-major)
__device__ float g_u2s[256], g_u2d[256];    // W2 @ as2 / ad2

// ---------------- helpers ----------------
__device__ __forceinline__ float warpSum(float v) {
    #pragma unroll
    for (int o = 16; o; o >>= 1) v += __shfl_xor_sync(0xffffffffu, v, o);
    return v;
}
__device__ __forceinline__ int warpSumI(int v) {
    #pragma unroll
    for (int o = 16; o; o >>= 1) v += __shfl_xor_sync(0xffffffffu, v, o);
    return v;
}
__device__ __forceinline__ float lrelu(float x) { return x > 0.f ? x : NEG_SLOPE * x; }
__device__ __forceinline__ float elu1(float x)  { return x > 0.f ? x : (__expf(x) - 1.0f); }
__device__ __forceinline__ uint32_t pk2(float a, float b) {
    __half2 h = __floats2half2_rn(a, b);
    return *(uint32_t*)&h;
}

// ---------------- init: zero degrees + edge width detect ----------------
__global__ void k_init(const int* __restrict__ raw) {
    int t = blockIdx.x * blockDim.x + threadIdx.x;
    if (t < NN) g_deg[t] = 0;
    if (t == 0) {
        int ok = 1;
        #pragma unroll
        for (int i = 0; i < 64; i++) ok &= (raw[2 * i + 1] == 0);
        g_is64 = ok;
    }
}

// ---------------- operand pre-conversion to fp16 (8 floats per thread) ----------------
__global__ void k_prep(const float* __restrict__ x, const float* __restrict__ W1,
                       const float* __restrict__ W2) {
    const int NX  = NN * CH / 8;
    const int NW1 = CH * C1 / 8;
    const int NW2 = C1 * CH / 8;
    int t = blockIdx.x * blockDim.x + threadIdx.x;
    if (t >= NX + NW1 + NW2) return;
    const float4* src; uint4* dst; int idx;
    if (t < NX)            { src = (const float4*)x;  dst = (uint4*)g_xh;  idx = t; }
    else if (t < NX + NW1) { src = (const float4*)W1; dst = (uint4*)g_w1h; idx = t - NX; }
    else                   { src = (const float4*)W2; dst = (uint4*)g_w2h; idx = t - NX - NW1; }
    float4 a = src[2 * idx], b = src[2 * idx + 1];
    dst[idx] = make_uint4(pk2(a.x, a.y), pk2(a.z, a.w), pk2(b.x, b.y), pk2(b.z, b.w));
}

// ---------------- attention u-vectors: u = W @ att (warp per output) ----------------
__global__ void k_uvec(const float* __restrict__ W1, const float* __restrict__ as1,
                       const float* __restrict__ ad1,
                       const float* __restrict__ W2, const float* __restrict__ as2,
                       const float* __restrict__ ad2) {
    int gw = (blockIdx.x * blockDim.x + threadIdx.x) >> 5;   // 0..511
    int lane = threadIdx.x & 31;
    if (gw < 256) {
        int h = gw >> 7, k = gw & 127;
        float4 w = ((const float4*)(W1 + k * 256 + h * 128))[lane];
        float4 s = ((const float4*)(as1 + h * 128))[lane];
        float4 d = ((const float4*)(ad1 + h * 128))[lane];
        float ps = w.x * s.x + w.y * s.y + w.z * s.z + w.w * s.w;
        float pd = w.x * d.x + w.y * d.y + w.z * d.z + w.w * d.w;
        ps = warpSum(ps); pd = warpSum(pd);
        if (lane == 0) { g_u1s[gw] = ps; g_u1d[gw] = pd; }
    } else {
        int k = gw - 256;
        float4 w = ((const float4*)(W2 + k * 128))[lane];
        float4 s = ((const float4*)as2)[lane];
        float4 d = ((const float4*)ad2)[lane];
        float ps = w.x * s.x + w.y * s.y + w.z * s.z + w.w * s.w;
        float pd = w.x * d.x + w.y * d.y + w.z * d.z + w.w * d.w;
        ps = warpSum(ps); pd = warpSum(pd);
        if (lane == 0) { g_u2s[k] = ps; g_u2d[k] = pd; }
    }
}

// ---------------- CSR build ----------------
__global__ void k_count(const int* __restrict__ raw) {
    int t = blockIdx.x * blockDim.x + threadIdx.x;
    if (t < NE) {
        int s, d;
        if (g_is64) { s = raw[2 * t]; d = raw[2 * (NE + t)]; }
        else        { s = raw[t];     d = raw[NE + t]; }
        g_edge2[t] = make_int2(s, d);
        atomicAdd(&g_deg[d], 1);
    } else if (t < ET) {
        atomicAdd(&g_deg[t - NE], 1);
    }
}
__global__ void k_scanA() {   // shuffle scan: 2 syncs total
    __shared__ int wtot[32];
    int t = threadIdx.x, lane = t & 31, wd = t >> 5;
    int i = blockIdx.x * 1024 + t;
    int v = (i < NN) ? g_deg[i] : 0;
    int ws = v;
    #pragma unroll
    for (int off = 1; off < 32; off <<= 1) {
        int y = __shfl_up_sync(0xffffffffu, ws, off);
        if (lane >= off) ws += y;
    }
    if (lane == 31) wtot[wd] = ws;
    __syncthreads();
    if (wd == 0) {
        int tv = wtot[lane];
        #pragma unroll
        for (int off = 1; off < 32; off <<= 1) {
            int y = __shfl_up_sync(0xffffffffu, tv, off);
            if (lane >= off) tv += y;
        }
        wtot[lane] = tv;
        if (lane == 31) g_bsum[blockIdx.x] = tv;
    }
    __syncthreads();
    int woff = wd ? wtot[wd - 1] : 0;
    if (i < NN) g_dinc[i] = woff + ws;
}
__global__ void k_scanC() {   // per-block offset = reduction over preceding block sums
    __shared__ int s_boff;
    int t = threadIdx.x;
    if (t < 32) {
        int b = blockIdx.x;
        int v = (t < b) ? g_bsum[t] : 0;
        if (t + 32 < b) v += g_bsum[t + 32];
        v = warpSumI(v);
        if (t == 0) s_boff = v;
    }
    __syncthreads();
    int boff = s_boff;
    int i = blockIdx.x * 1024 + t;
    if (i < NN) {
        int inc = g_dinc[i] + boff;
        g_rowstart[i + 1] = inc;
        g_cursor[i] = inc - g_deg[i];
    }
    if (i == 0) g_rowstart[0] = 0;
}
__global__ void k_fill() {
    int t = blockIdx.x * blockDim.x + threadIdx.x;
    if (t < NE) {
        int2 e = g_edge2[t];
        int p = atomicAdd(&g_cursor[e.y], 1);
        g_srcs[p] = e.x;
    } else if (t < ET) {
        int n = t - NE;
        int p = atomicAdd(&g_cursor[n], 1);
        g_srcs[p] = n;
    }
}

// ---------------- WMMA fp16 GEMM (fp16 operands pre-staged in global) ----------------
#define PA 136
#define OFF_A 0
#define OFF_B 34816
#define SMEM_TOT 69632

template <int MODE>
__global__ __launch_bounds__(256, 2)
void k_gemm_wmma() {
    extern __shared__ char dyn[];
    __shared__ float s_u[4][128];

    constexpr int K      = (MODE == 1) ? 128 : 256;
    constexpr int NCHUNK = K / 128;
    constexpr int NHEADS = (MODE == 1) ? 2 : 1;
    constexpr int NCOLS  = (MODE == 1) ? 256 : 128;
    constexpr int Hstr   = (MODE == 1) ? C1 : CH;
    const __half* Asrc = (MODE == 1) ? g_xh : g_o1h;
    const __half* Bsrc = (MODE == 1) ? g_w1h : g_w2h;
    __half* Hout    = (MODE == 1) ? g_h1h : g_h2h;

    const int tid = threadIdx.x, wid = tid >> 5, lane = tid & 31;
    const int row0 = blockIdx.x * 128;
    const int warp_m = wid >> 1, warp_n = wid & 1;

    __half* AH = (__half*)(dyn + OFF_A);
    __half* BH = (__half*)(dyn + OFF_B);

    if (MODE == 1 && tid < 128) {
        s_u[0][tid] = g_u1s[tid];
        s_u[1][tid] = g_u1d[tid];
        s_u[2][tid] = g_u1s[128 + tid];
        s_u[3][tid] = g_u1d[128 + tid];
    }

    const int lr = tid >> 1, lh = tid & 1;
    const bool rok = (row0 + lr) < NN;

    for (int head = 0; head < NHEADS; head++) {
        wmma::fragment<wmma::accumulator, 16, 16, 16, float> acc[2][4];
        #pragma unroll
        for (int i = 0; i < 2; i++)
            #pragma unroll
            for (int j = 0; j < 4; j++) wmma::fill_fragment(acc[i][j], 0.f);

        #pragma unroll
        for (int c = 0; c < NCHUNK; c++) {
            if (head || c) __syncthreads();
            if (head == 0) {
                const uint4* src = (const uint4*)(Asrc + (size_t)(row0 + lr) * K + c * 128 + lh * 64);
                uint4* dst = (uint4*)(AH + lr * PA + lh * 64);
                #pragma unroll
                for (int i = 0; i < 8; i++)
                    dst[i] = rok ? src[i] : make_uint4(0, 0, 0, 0);
            }
            {
                const uint4* src = (const uint4*)(Bsrc + (size_t)(c * 128 + lr) * NCOLS + head * 128 + lh * 64);
                uint4* dst = (uint4*)(BH + lr * PA + lh * 64);
                #pragma unroll
                for (int i = 0; i < 8; i++)
                    dst[i] = src[i];
            }
            __syncthreads();

            // fused layer-1 attention dots from the staged fp16 A tile
            if (MODE == 1 && head == 0 && c == 0) {
                const uint4* arow = (const uint4*)(AH + lr * PA + lh * 64);
                float ps0 = 0.f, pd0 = 0.f, ps1 = 0.f, pd1 = 0.f;
                #pragma unroll
                for (int i = 0; i < 8; i++) {
                    uint4 pk = arow[i];
                    const uint32_t uu[4] = {pk.x, pk.y, pk.z, pk.w};
                    #pragma unroll
                    for (int q = 0; q < 4; q++) {
                        float2 f = __half22float2(*(const __half2*)&uu[q]);
                        int kk = lh * 64 + i * 8 + q * 2;
                        ps0 += f.x * s_u[0][kk] + f.y * s_u[0][kk + 1];
                        pd0 += f.x * s_u[1][kk] + f.y * s_u[1][kk + 1];
                        ps1 += f.x * s_u[2][kk] + f.y * s_u[2][kk + 1];
                        pd1 += f.x * s_u[3][kk] + f.y * s_u[3][kk + 1];
                    }
                }
                ps0 += __shfl_xor_sync(0xffffffffu, ps0, 1);
                pd0 += __shfl_xor_sync(0xffffffffu, pd0, 1);
                ps1 += __shfl_xor_sync(0xffffffffu, ps1, 1);
                pd1 += __shfl_xor_sync(0xffffffffu, pd1, 1);
                int r = row0 + lr;
                if (lh == 0 && r < NN) {
                    g_a1s[2 * r]     = ps0; g_a1d[2 * r]     = pd0;
                    g_a1s[2 * r + 1] = ps1; g_a1d[2 * r + 1] = pd1;
                }
            }

            #pragma unroll
            for (int kk = 0; kk < 8; kk++) {
                wmma::fragment<wmma::matrix_a, 16, 16, 16, __half, wmma::row_major> af[2];
                wmma::fragment<wmma::matrix_b, 16, 16, 16, __half, wmma::row_major> bf[4];
                #pragma unroll
                for (int i = 0; i < 2; i++)
                    wmma::load_matrix_sync(af[i], AH + (warp_m * 32 + i * 16) * PA + kk * 16, PA);
                #pragma unroll
                for (int j = 0; j < 4; j++)
                    wmma::load_matrix_sync(bf[j], BH + (kk * 16) * PA + warp_n * 64 + j * 16, PA);
                #pragma unroll
                for (int i = 0; i < 2; i++)
                    #pragma unroll
                    for (int j = 0; j < 4; j++)
                        wmma::mma_sync(acc[i][j], af[i], bf[j], acc[i][j]);
            }
        }

        __syncthreads();
        __half* Ch = (__half*)(dyn + OFF_B);
        #pragma unroll
        for (int i = 0; i < 2; i++)
            #pragma unroll
            for (int j = 0; j < 4; j++) {
                wmma::fragment<wmma::accumulator, 16, 16, 16, __half> hf;
                #pragma unroll
                for (int e = 0; e < hf.num_elements; e++)
                    hf.x[e] = __float2half_rn(acc[i][j].x[e]);
                wmma::store_matrix_sync(Ch + (warp_m * 32 + i * 16) * PA + warp_n * 64 + j * 16,
                                        hf, PA, wmma::mem_row_major);
            }
        __syncthreads();

        #pragma unroll
        for (int rr = 0; rr < 16; rr += 2) {
            int row = wid * 16 + rr + (lane >> 4);
            int r = row0 + row;
            uint4 v = *(const uint4*)(Ch + row * PA + (lane & 15) * 8);
            if (r < NN)
                *(uint4*)(Hout + (size_t)r * Hstr + head * 128 + (lane & 15) * 8) = v;
        }
    }
}

// ---------------- single-pass aggregation, 4-wide unrolled, + layer-2 dots ----------------
__global__ void k_agg1(const float* __restrict__ b1) {
    __shared__ float s_u2s[256], s_u2d[256];
    int tid = threadIdx.x;
    s_u2s[tid] = g_u2s[tid];
    s_u2d[tid] = g_u2d[tid];
    __syncthreads();

    int w = (blockIdx.x * blockDim.x + tid) >> 5;
    int lane = tid & 31;
    if (w >= NN) return;
    int beg = g_rowstart[w], end = g_rowstart[w + 1];

    const int hd = lane >> 4;
    const float ad = g_a1d[2 * w + hd];

    float z = 0.f;
    float acc[8] = {0, 0, 0, 0, 0, 0, 0, 0};
    int j = beg;
    for (; j + 4 <= end; j += 4) {
        int s0 = g_srcs[j],     s1 = g_srcs[j + 1];
        int s2 = g_srcs[j + 2], s3 = g_srcs[j + 3];
        float a0 = g_a1s[2 * s0 + hd], a1 = g_a1s[2 * s1 + hd];
        float a2 = g_a1s[2 * s2 + hd], a3 = g_a1s[2 * s3 + hd];
        uint4 p0 = *(const uint4*)(g_h1h + (size_t)s0 * C1 + lane * 8);
        uint4 p1 = *(const uint4*)(g_h1h + (size_t)s1 * C1 + lane * 8);
        uint4 p2 = *(const uint4*)(g_h1h + (size_t)s2 * C1 + lane * 8);
        uint4 p3 = *(const uint4*)(g_h1h + (size_t)s3 * C1 + lane * 8);
        float e0 = __expf(lrelu(a0 + ad)), e1 = __expf(lrelu(a1 + ad));
        float e2 = __expf(lrelu(a2 + ad)), e3 = __expf(lrelu(a3 + ad));
        z += (e0 + e1) + (e2 + e3);
        const uint32_t* u0 = (const uint32_t*)&p0;
        const uint32_t* u1 = (const uint32_t*)&p1;
        const uint32_t* u2 = (const uint32_t*)&p2;
        const uint32_t* u3 = (const uint32_t*)&p3;
        #pragma unroll
        for (int q = 0; q < 4; q++) {
            float2 f0 = __half22float2(*(const __half2*)&u0[q]);
            float2 f1 = __half22float2(*(const __half2*)&u1[q]);
            float2 f2 = __half22float2(*(const __half2*)&u2[q]);
            float2 f3 = __half22float2(*(const __half2*)&u3[q]);
            acc[2 * q]     += e0 * f0.x + e1 * f1.x + e2 * f2.x + e3 * f3.x;
            acc[2 * q + 1] += e0 * f0.y + e1 * f1.y + e2 * f2.y + e3 * f3.y;
        }
    }
    for (; j < end; j++) {
        int s = g_srcs[j];
        float e = __expf(lrelu(g_a1s[2 * s + hd] + ad));
        z += e;
        uint4 pk = *(const uint4*)(g_h1h + (size_t)s * C1 + lane * 8);
        const uint32_t* u = (const uint32_t*)&pk;
        #pragma unroll
        for (int q = 0; q < 4; q++) {
            float2 f = __half22float2(*(const __half2*)&u[q]);
            acc[2 * q]     += e * f.x;
            acc[2 * q + 1] += e * f.y;
        }
    }
    float iz = 1.0f / (z + EPS);
    const float* bb = b1 + lane * 8;
    float ov[8];
    #pragma unroll
    for (int q = 0; q < 8; q++) ov[q] = elu1(acc[q] * iz + bb[q]);
    uint4 o;
    o.x = pk2(ov[0], ov[1]);
    o.y = pk2(ov[2], ov[3]);
    o.z = pk2(ov[4], ov[5]);
    o.w = pk2(ov[6], ov[7]);
    *(uint4*)(g_o1h + (size_t)w * C1 + lane * 8) = o;

    // layer-2 attention dots from the fp16-rounded out1
    float ds = 0.f, dd = 0.f;
    const uint32_t* op = (const uint32_t*)&o;
    #pragma unroll
    for (int q = 0; q < 4; q++) {
        float2 f = __half22float2(*(const __half2*)&op[q]);
        int cc = lane * 8 + q * 2;
        ds += f.x * s_u2s[cc] + f.y * s_u2s[cc + 1];
        dd += f.x * s_u2d[cc] + f.y * s_u2d[cc + 1];
    }
    ds = warpSum(ds); dd = warpSum(dd);
    if (lane == 0) { g_a2s[w] = ds; g_a2d[w] = dd; }
}

// ---------------- layer-2 aggregation (4-wide) fused with MLP head ----------------
__global__ void k_agg2mlp(const float* __restrict__ b2,
                          const float* __restrict__ fc1w, const float* __restrict__ fc1b,
                          const float* __restrict__ fc2w, const float* __restrict__ fc2b,
                          float* __restrict__ out) {
    __shared__ float w1s[CH * FCH];
    __shared__ float w2s[FCH], b1s[FCH], b2s[CH];
    int tid = threadIdx.x;
    for (int i = tid; i < CH * FCH; i += blockDim.x) w1s[i] = fc1w[i];
    if (tid < FCH) { w2s[tid] = fc2w[tid]; b1s[tid] = fc1b[tid]; }
    if (tid < CH)  b2s[tid] = b2[tid];
    __syncthreads();

    int w = (blockIdx.x * blockDim.x + tid) >> 5;
    int lane = tid & 31;
    if (w >= NN) return;
    int beg = g_rowstart[w], end = g_rowstart[w + 1];
    float ad = g_a2d[w];

    float z = 0.f;
    float acc[4] = {0, 0, 0, 0};
    int j = beg;
    for (; j + 4 <= end; j += 4) {
        int s0 = g_srcs[j],     s1 = g_srcs[j + 1];
        int s2 = g_srcs[j + 2], s3 = g_srcs[j + 3];
        float a0 = g_a2s[s0], a1 = g_a2s[s1], a2 = g_a2s[s2], a3 = g_a2s[s3];
        uint2 p0 = *(const uint2*)(g_h2h + (size_t)s0 * CH + lane * 4);
        uint2 p1 = *(const uint2*)(g_h2h + (size_t)s1 * CH + lane * 4);
        uint2 p2 = *(const uint2*)(g_h2h + (size_t)s2 * CH + lane * 4);
        uint2 p3 = *(const uint2*)(g_h2h + (size_t)s3 * CH + lane * 4);
        float e0 = __expf(lrelu(a0 + ad)), e1 = __expf(lrelu(a1 + ad));
        float e2 = __expf(lrelu(a2 + ad)), e3 = __expf(lrelu(a3 + ad));
        z += (e0 + e1) + (e2 + e3);
        float2 f;
        f = __half22float2(*(const __half2*)&p0.x); acc[0] += e0 * f.x; acc[1] += e0 * f.y;
        f = __half22float2(*(const __half2*)&p0.y); acc[2] += e0 * f.x; acc[3] += e0 * f.y;
        f = __half22float2(*(const __half2*)&p1.x); acc[0] += e1 * f.x; acc[1] += e1 * f.y;
        f = __half22float2(*(const __half2*)&p1.y); acc[2] += e1 * f.x; acc[3] += e1 * f.y;
        f = __half22float2(*(const __half2*)&p2.x); acc[0] += e2 * f.x; acc[1] += e2 * f.y;
        f = __half22float2(*(const __half2*)&p2.y); acc[2] += e2 * f.x; acc[3] += e2 * f.y;
        f = __half22float2(*(const __half2*)&p3.x); acc[0] += e3 * f.x; acc[1] += e3 * f.y;
        f = __half22float2(*(const __half2*)&p3.y); acc[2] += e3 * f.x; acc[3] += e3 * f.y;
    }
    for (; j < end; j++) {
        int s = g_srcs[j];
        float e = __expf(lrelu(g_a2s[s] + ad));
        z += e;
        uint2 pk = *(const uint2*)(g_h2h + (size_t)s * CH + lane * 4);
        float2 f0 = __half22float2(*(const __half2*)&pk.x);
        float2 f1 = __half22float2(*(const __half2*)&pk.y);
        acc[0] += e * f0.x; acc[1] += e * f0.y;
        acc[2] += e * f1.x; acc[3] += e * f1.y;
    }
    float iz = 1.0f / (z + EPS);

    float hvv[4];
    #pragma unroll
    for (int q = 0; q < 4; q++) hvv[q] = elu1(acc[q] * iz + b2s[lane * 4 + q]);

    float acc0 = 0.f, acc1 = 0.f;
    #pragma unroll
    for (int k0 = 0; k0 < CH; k0 += 4) {
        int srcl = k0 >> 2;
        #pragma unroll
        for (int kk = 0; kk < 4; kk++) {
            float hk = __shfl_sync(0xffffffffu, hvv[kk], srcl);
            acc0 += hk * w1s[(k0 + kk) * FCH + lane];
            acc1 += hk * w1s[(k0 + kk) * FCH + lane + 32];
        }
    }
    float h0 = fmaxf(acc0 + b1s[lane], 0.f);
    float h1 = fmaxf(acc1 + b1s[lane + 32], 0.f);
    float p = h0 * w2s[lane] + h1 * w2s[lane + 32];
    p = warpSum(p);
    if (lane == 0) out[w] = p + fc2b[0];
}

// ---------------- launch (two-stream fork/join, graph-capturable) ----------------
extern "C" void kernel_launch(void* const* d_in, const int* in_sizes, int n_in,
                              void* d_out, int out_size) {
    const float* x    = (const float*)d_in[0];
    const int*   eraw = (const int*)d_in[1];
    const float* W1   = (const float*)d_in[2];
    const float* as1  = (const float*)d_in[3];
    const float* ad1  = (const float*)d_in[4];
    const float* b1   = (const float*)d_in[5];
    const float* W2   = (const float*)d_in[6];
    const float* as2  = (const float*)d_in[7];
    const float* ad2  = (const float*)d_in[8];
    const float* b2   = (const float*)d_in[9];
    const float* fc1w = (const float*)d_in[10];
    const float* fc1b = (const float*)d_in[11];
    const float* fc2w = (const float*)d_in[12];
    const float* fc2b = (const float*)d_in[13];
    float* out = (float*)d_out;

    static cudaStream_t s2 = nullptr;
    static cudaEvent_t evFork = nullptr, evJoin = nullptr;
    if (s2 == nullptr) {
        cudaStreamCreateWithFlags(&s2, cudaStreamNonBlocking);
        cudaEventCreateWithFlags(&evFork, cudaEventDisableTiming);
        cudaEventCreateWithFlags(&evJoin, cudaEventDisableTiming);
        cudaFuncSetAttribute(k_gemm_wmma<1>, cudaFuncAttributeMaxDynamicSharedMemorySize, SMEM_TOT);
        cudaFuncSetAttribute(k_gemm_wmma<2>, cudaFuncAttributeMaxDynamicSharedMemorySize, SMEM_TOT);
    }

    const int NPREP = NN * CH / 8 + CH * C1 / 8 + C1 * CH / 8;

    // stream 0: init -> prep -> uvec -> GEMM1
    k_init<<<(NN + 255) / 256, 256>>>(eraw);                       // #1
    cudaEventRecord(evFork, 0);
    k_prep<<<(NPREP + 255) / 256, 256>>>(x, W1, W2);               // #2
    k_uvec<<<64, 256>>>(W1, as1, ad1, W2, as2, ad2);               // #3
    k_gemm_wmma<1><<<391, 256, SMEM_TOT>>>();                      // #4 -> ncu window

    // stream 2 (forked after init): CSR build, concurrent with GEMM1 path
    cudaStreamWaitEvent(s2, evFork, 0);
    k_count<<<(ET + 255) / 256, 256, 0, s2>>>(eraw);               // #5
    k_scanA<<<49, 1024, 0, s2>>>();                                // #6
    k_scanC<<<49, 1024, 0, s2>>>();                                // #7
    k_fill<<<(ET + 255) / 256, 256, 0, s2>>>();                    // #8
    cudaEventRecord(evJoin, s2);

    // join: agg1 needs GEMM1 (program order) + fill (event)
    cudaStreamWaitEvent(0, evJoin, 0);
    k_agg1<<<(NN + 7) / 8, 256>>>(b1);                             // #9
    k_gemm_wmma<2><<<391, 256, SMEM_TOT>>>();                      // #10
    k_agg2mlp<<<(NN + 7) / 8, 256>>>(b2, fc1w, fc1b, fc2w, fc2b, out);  // #11
}